// round 7
// baseline (speedup 1.0000x reference)
#include <cuda_runtime.h>
#include <cuda_bf16.h>
#include <math.h>
#include <stdint.h>

#define D_MODEL   1024
#define NUM_HEADS 16
#define HEAD_DIM  64
#define NTOK      4096
// (1/sqrt(64)) * log2(e)
#define C_SCALE   0.18033688011112042f

// ---------------- static scratch (allocation-free rule) ----------------
__device__ float g_v[NTOK * D_MODEL];
__device__ float g_o[NTOK * D_MODEL];

__device__ __nv_bfloat16 g_xh[NTOK * D_MODEL];
__device__ __nv_bfloat16 g_xl[NTOK * D_MODEL];
__device__ __nv_bfloat16 g_qh[NTOK * D_MODEL];
__device__ __nv_bfloat16 g_ql[NTOK * D_MODEL];
__device__ __nv_bfloat16 g_kh[NTOK * D_MODEL];
__device__ __nv_bfloat16 g_kl[NTOK * D_MODEL];
__device__ __nv_bfloat16 g_vh[NTOK * D_MODEL];
__device__ __nv_bfloat16 g_vl[NTOK * D_MODEL];
__device__ __nv_bfloat16 g_oh[NTOK * D_MODEL];
__device__ __nv_bfloat16 g_ol[NTOK * D_MODEL];
__device__ __nv_bfloat16 g_wqh[D_MODEL * D_MODEL];
__device__ __nv_bfloat16 g_wql[D_MODEL * D_MODEL];
__device__ __nv_bfloat16 g_wkh[D_MODEL * D_MODEL];
__device__ __nv_bfloat16 g_wkl[D_MODEL * D_MODEL];
__device__ __nv_bfloat16 g_wvh[D_MODEL * D_MODEL];
__device__ __nv_bfloat16 g_wvl[D_MODEL * D_MODEL];
__device__ __nv_bfloat16 g_woh[D_MODEL * D_MODEL];
__device__ __nv_bfloat16 g_wol[D_MODEL * D_MODEL];

// ---------------- helpers ----------------
__device__ __forceinline__ uint32_t smem_u32(const void* p) {
    uint32_t a;
    asm("{ .reg .u64 t; cvta.to.shared.u64 t, %1; cvt.u32.u64 %0, t; }"
        : "=r"(a) : "l"(p));
    return a;
}

__device__ __forceinline__ void ldsm_x4(uint32_t* r, uint32_t addr) {
    asm volatile("ldmatrix.sync.aligned.m8n8.x4.shared.b16 {%0,%1,%2,%3}, [%4];"
                 : "=r"(r[0]), "=r"(r[1]), "=r"(r[2]), "=r"(r[3]) : "r"(addr));
}
__device__ __forceinline__ void ldsm_x4t(uint32_t* r, uint32_t addr) {
    asm volatile("ldmatrix.sync.aligned.m8n8.x4.trans.shared.b16 {%0,%1,%2,%3}, [%4];"
                 : "=r"(r[0]), "=r"(r[1]), "=r"(r[2]), "=r"(r[3]) : "r"(addr));
}
__device__ __forceinline__ void mma_bf16(float* d, const uint32_t* a, const uint32_t* b) {
    asm volatile(
        "mma.sync.aligned.m16n8k16.row.col.f32.bf16.bf16.f32 "
        "{%0,%1,%2,%3}, {%4,%5,%6,%7}, {%8,%9}, {%0,%1,%2,%3};"
        : "+f"(d[0]), "+f"(d[1]), "+f"(d[2]), "+f"(d[3])
        : "r"(a[0]), "r"(a[1]), "r"(a[2]), "r"(a[3]), "r"(b[0]), "r"(b[1]));
}

#define CP_ASYNC16(dst, src) \
    asm volatile("cp.async.cg.shared.global [%0], [%1], 16;" :: "r"(dst), "l"(src))
#define CP_COMMIT asm volatile("cp.async.commit_group;" ::: "memory")
template <int N>
__device__ __forceinline__ void cp_wait() {
    asm volatile("cp.async.wait_group %0;" :: "n"(N) : "memory");
}

__device__ __forceinline__ uint32_t pack_bf16x2(float lo, float hi) {
    __nv_bfloat162 t = __floats2bfloat162_rn(lo, hi);
    return *(uint32_t*)&t;
}
__device__ __forceinline__ float bf16lo(uint32_t p) { return __uint_as_float(p << 16); }
__device__ __forceinline__ float bf16hi(uint32_t p) { return __uint_as_float(p & 0xffff0000u); }

// fast 2^t on FMA pipe (t <= 0 expected), rel err < 2e-5
__device__ __forceinline__ float exp2_fast(float t) {
    t = fmaxf(t, -126.0f);
    float fn = floorf(t);
    float f = t - fn;
    float p = fmaf(f, 0.000154035f, 0.0013333558f);
    p = fmaf(f, p, 0.0096181291f);
    p = fmaf(f, p, 0.0555041087f);
    p = fmaf(f, p, 0.2402265070f);
    p = fmaf(f, p, 0.6931471806f);
    p = fmaf(f, p, 1.0f);
    int n = (int)fn;
    return p * __int_as_float((n + 127) << 23);
}

// ---------------------------------------------------------------------------
// fp32 -> (bf16 hi, bf16 lo) split
// ---------------------------------------------------------------------------
__device__ __forceinline__ void split_body(const float* __restrict__ x,
                                           __nv_bfloat16* __restrict__ h,
                                           __nv_bfloat16* __restrict__ l, int i) {
    float4 v = *(const float4*)(x + i);
    __nv_bfloat16 h0 = __float2bfloat16(v.x);
    __nv_bfloat16 h1 = __float2bfloat16(v.y);
    __nv_bfloat16 h2 = __float2bfloat16(v.z);
    __nv_bfloat16 h3 = __float2bfloat16(v.w);
    __nv_bfloat16 l0 = __float2bfloat16(v.x - __bfloat162float(h0));
    __nv_bfloat16 l1 = __float2bfloat16(v.y - __bfloat162float(h1));
    __nv_bfloat16 l2 = __float2bfloat16(v.z - __bfloat162float(h2));
    __nv_bfloat16 l3 = __float2bfloat16(v.w - __bfloat162float(h3));
    __nv_bfloat162* hp = (__nv_bfloat162*)(h + i);
    __nv_bfloat162* lp = (__nv_bfloat162*)(l + i);
    hp[0] = __nv_bfloat162(h0, h1); hp[1] = __nv_bfloat162(h2, h3);
    lp[0] = __nv_bfloat162(l0, l1); lp[1] = __nv_bfloat162(l2, l3);
}

__global__ void split_bf16(const float* __restrict__ x, __nv_bfloat16* __restrict__ h,
                           __nv_bfloat16* __restrict__ l, int n) {
    int i = (blockIdx.x * blockDim.x + threadIdx.x) * 4;
    if (i < n) split_body(x, h, l, i);
}

__global__ void split_bf16_w4(const float* w0, const float* w1, const float* w2,
                              const float* w3, __nv_bfloat16* h0, __nv_bfloat16* l0,
                              __nv_bfloat16* h1, __nv_bfloat16* l1,
                              __nv_bfloat16* h2, __nv_bfloat16* l2,
                              __nv_bfloat16* h3, __nv_bfloat16* l3, int n) {
    const float* w[4] = {w0, w1, w2, w3};
    __nv_bfloat16* h[4] = {h0, h1, h2, h3};
    __nv_bfloat16* l[4] = {l0, l1, l2, l3};
    int m = blockIdx.y;
    int i = (blockIdx.x * blockDim.x + threadIdx.x) * 4;
    if (i < n) split_body(w[m], h[m], l[m], i);
}

// ---------------------------------------------------------------------------
// HMMA split-bf16 GEMM. BK=16, 4-stage cp.async pipeline (prefetch depth 3).
// Row stride 24 halves (48B): 16B-aligned for ldmatrix, bank-conflict-free.
// ---------------------------------------------------------------------------
#define ROWH    24                 // halves per smem row (16 data + 8 pad)
#define GTILE16 (128 * ROWH * 2)   // 6144 B per tile
#define GSTAGE16 (4 * GTILE16)     // 24576 B per stage (Ah, Al, Bh, Bl)
#define GEMM_SMEM (4 * GSTAGE16)   // 98304 B, 4 stages

__global__ __launch_bounds__(256, 2)
void gemm_mma(const __nv_bfloat16* __restrict__ Ah, const __nv_bfloat16* __restrict__ Al,
              const __nv_bfloat16* __restrict__ Bh, const __nv_bfloat16* __restrict__ Bl,
              float* __restrict__ C, __nv_bfloat16* __restrict__ Ch,
              __nv_bfloat16* __restrict__ Cl, int M, int N, int K) {
    extern __shared__ char smem[];
    const uint32_t sb = smem_u32(smem);
    const int tid = threadIdx.x;
    const int lane = tid & 31;
    const int wid = tid >> 5;
    const int wm = wid & 3;
    const int wn = wid >> 2;
    const int m0 = blockIdx.y * 128;
    const int n0 = blockIdx.x * 128;

    const __nv_bfloat16* srcs[4] = {Ah + (size_t)m0 * K, Al + (size_t)m0 * K,
                                    Bh + (size_t)n0 * K, Bl + (size_t)n0 * K};

    float acc[2][8][4];
#pragma unroll
    for (int a = 0; a < 2; a++)
#pragma unroll
        for (int b = 0; b < 8; b++)
#pragma unroll
            for (int c = 0; c < 4; c++) acc[a][b][c] = 0.f;

    // one 16-wide k-chunk per stage: each thread copies one 16B segment per tile
    const int lrow = tid >> 1;          // 0..127
    const int lcs  = tid & 1;           // 0..1
    auto load_stage = [&](int s, int kc) {
        uint32_t base = sb + s * GSTAGE16 + (lrow * ROWH + lcs * 8) * 2;
        size_t goff = (size_t)lrow * K + kc * 16 + lcs * 8;
#pragma unroll
        for (int t = 0; t < 4; t++)
            CP_ASYNC16(base + t * GTILE16, srcs[t] + goff);
    };

    const int NCH = K / 16;   // 64
    load_stage(0, 0); CP_COMMIT;
    load_stage(1, 1); CP_COMMIT;
    load_stage(2, 2); CP_COMMIT;

    for (int kc = 0; kc < NCH; kc++) {
        int rem = NCH - 1 - kc;
        if (rem >= 3) {
            load_stage((kc + 3) & 3, kc + 3);
            CP_COMMIT;
            cp_wait<3>();
        } else if (rem == 2) {
            cp_wait<2>();
        } else if (rem == 1) {
            cp_wait<1>();
        } else {
            cp_wait<0>();
        }
        __syncthreads();

        const uint32_t st = sb + (kc & 3) * GSTAGE16;
        uint32_t a_h[2][4], a_l[2][4];
#pragma unroll
        for (int mt = 0; mt < 2; mt++) {
            uint32_t ar = st + ((wm * 32 + mt * 16 + (lane & 15)) * ROWH
                                + (lane >> 4) * 8) * 2;
            ldsm_x4(a_h[mt], ar);
            ldsm_x4(a_l[mt], ar + GTILE16);
        }
#pragma unroll
        for (int np = 0; np < 4; np++) {
            uint32_t br = st + 2 * GTILE16
                        + ((wn * 64 + np * 16 + ((lane >> 4) << 3) + (lane & 7)) * ROWH
                           + ((lane >> 3) & 1) * 8) * 2;
            uint32_t bh[4], bl[4];
            ldsm_x4(bh, br);
            ldsm_x4(bl, br + GTILE16);
#pragma unroll
            for (int mt = 0; mt < 2; mt++) {
                mma_bf16(acc[mt][2 * np],     a_h[mt], bh);
                mma_bf16(acc[mt][2 * np],     a_h[mt], bl);
                mma_bf16(acc[mt][2 * np],     a_l[mt], bh);
                mma_bf16(acc[mt][2 * np + 1], a_h[mt], bh + 2);
                mma_bf16(acc[mt][2 * np + 1], a_h[mt], bl + 2);
                mma_bf16(acc[mt][2 * np + 1], a_l[mt], bh + 2);
            }
        }
        __syncthreads();
    }

#pragma unroll
    for (int mt = 0; mt < 2; mt++) {
#pragma unroll
        for (int nt = 0; nt < 8; nt++) {
            int r0 = m0 + wm * 32 + mt * 16 + (lane >> 2);
            int col = n0 + wn * 64 + nt * 8 + (lane & 3) * 2;
            float d0 = acc[mt][nt][0], d1 = acc[mt][nt][1];
            float d2 = acc[mt][nt][2], d3 = acc[mt][nt][3];
            if (C) {
                float2 v0 = {d0, d1}, v1 = {d2, d3};
                *(float2*)&C[(size_t)r0 * N + col] = v0;
                *(float2*)&C[(size_t)(r0 + 8) * N + col] = v1;
            }
            if (Ch) {
                uint32_t ph0 = pack_bf16x2(d0, d1);
                uint32_t pl0 = pack_bf16x2(d0 - bf16lo(ph0), d1 - bf16hi(ph0));
                uint32_t ph1 = pack_bf16x2(d2, d3);
                uint32_t pl1 = pack_bf16x2(d2 - bf16lo(ph1), d3 - bf16hi(ph1));
                *(uint32_t*)&Ch[(size_t)r0 * N + col] = ph0;
                *(uint32_t*)&Cl[(size_t)r0 * N + col] = pl0;
                *(uint32_t*)&Ch[(size_t)(r0 + 8) * N + col] = ph1;
                *(uint32_t*)&Cl[(size_t)(r0 + 8) * N + col] = pl1;
            }
        }
    }
}

// ---------------------------------------------------------------------------
// HMMA flash attention — R5-exact version (64-q blocks, 128 thr, static smem)
// ---------------------------------------------------------------------------
__global__ __launch_bounds__(128)
void attn_mma(const __nv_bfloat16* __restrict__ Qh_, const __nv_bfloat16* __restrict__ Ql_,
              const __nv_bfloat16* __restrict__ Kh_, const __nv_bfloat16* __restrict__ Kl_,
              const __nv_bfloat16* __restrict__ Vh_, const __nv_bfloat16* __restrict__ Vl_,
              float* __restrict__ O, int S) {
    __shared__ __align__(16) uint16_t sKh[64 * 72];
    __shared__ __align__(16) uint16_t sKl[64 * 72];
    __shared__ __align__(16) uint16_t sVh[64 * 72];
    __shared__ __align__(16) uint16_t sVl[64 * 72];

    const int tid = threadIdx.x;
    const int lane = tid & 31;
    const int wid = tid >> 5;
    const int h = blockIdx.y;
    const int b = blockIdx.z;
    const int q0 = blockIdx.x * 64;
    const int tok0 = b * S;
    const int hoff = h * HEAD_DIM;

    const uint32_t aKh = smem_u32(sKh), aKl = smem_u32(sKl);
    const uint32_t aVh = smem_u32(sVh), aVl = smem_u32(sVl);

#pragma unroll
    for (int i = 0; i < 4; i++) {
        int seg = tid + i * 128;
        int row = seg >> 3;
        int cs = seg & 7;
        const void* sh = Qh_ + (size_t)(tok0 + q0 + row) * D_MODEL + hoff + cs * 8;
        const void* sl = Ql_ + (size_t)(tok0 + q0 + row) * D_MODEL + hoff + cs * 8;
        CP_ASYNC16(aKh + (row * 72 + cs * 8) * 2, sh);
        CP_ASYNC16(aKl + (row * 72 + cs * 8) * 2, sl);
    }
    CP_COMMIT;
    cp_wait<0>();
    __syncthreads();

    uint32_t qh[4][4], ql[4][4];
#pragma unroll
    for (int kt = 0; kt < 4; kt++) {
        uint32_t off = ((wid * 16 + (lane & 15)) * 72 + kt * 16 + (lane >> 4) * 8) * 2;
        ldsm_x4(qh[kt], aKh + off);
        ldsm_x4(ql[kt], aKl + off);
    }
    __syncthreads();

    float acc_o[8][4];
#pragma unroll
    for (int i = 0; i < 8; i++)
#pragma unroll
        for (int j = 0; j < 4; j++) acc_o[i][j] = 0.f;
    float mA = -1e30f, mB = -1e30f, lA = 0.f, lB = 0.f;

    for (int c0 = 0; c0 < S; c0 += 64) {
#pragma unroll
        for (int i = 0; i < 4; i++) {
            int seg = tid + i * 128;
            int row = seg >> 3;
            int cs = seg & 7;
            size_t g = (size_t)(tok0 + c0 + row) * D_MODEL + hoff + cs * 8;
            uint32_t d = (row * 72 + cs * 8) * 2;
            CP_ASYNC16(aKh + d, Kh_ + g);
            CP_ASYNC16(aKl + d, Kl_ + g);
            CP_ASYNC16(aVh + d, Vh_ + g);
            CP_ASYNC16(aVl + d, Vl_ + g);
        }
        CP_COMMIT;
        cp_wait<0>();
        __syncthreads();

        float s[8][4];
#pragma unroll
        for (int i = 0; i < 8; i++)
#pragma unroll
            for (int j = 0; j < 4; j++) s[i][j] = 0.f;

#pragma unroll
        for (int kt = 0; kt < 4; kt++) {
#pragma unroll
            for (int np = 0; np < 4; np++) {
                uint32_t off = ((np * 16 + ((lane >> 4) << 3) + (lane & 7)) * 72
                                + kt * 16 + ((lane >> 3) & 1) * 8) * 2;
                uint32_t bh[4], bl[4];
                ldsm_x4(bh, aKh + off);
                ldsm_x4(bl, aKl + off);
                mma_bf16(s[2 * np],     qh[kt], bh);
                mma_bf16(s[2 * np],     qh[kt], bl);
                mma_bf16(s[2 * np],     ql[kt], bh);
                mma_bf16(s[2 * np + 1], qh[kt], bh + 2);
                mma_bf16(s[2 * np + 1], qh[kt], bl + 2);
                mma_bf16(s[2 * np + 1], ql[kt], bh + 2);
            }
        }

        float mxA = -1e30f, mxB = -1e30f;
#pragma unroll
        for (int nt = 0; nt < 8; nt++) {
            s[nt][0] *= C_SCALE; s[nt][1] *= C_SCALE;
            s[nt][2] *= C_SCALE; s[nt][3] *= C_SCALE;
            mxA = fmaxf(mxA, fmaxf(s[nt][0], s[nt][1]));
            mxB = fmaxf(mxB, fmaxf(s[nt][2], s[nt][3]));
        }
        mxA = fmaxf(mxA, __shfl_xor_sync(0xffffffffu, mxA, 1));
        mxA = fmaxf(mxA, __shfl_xor_sync(0xffffffffu, mxA, 2));
        mxB = fmaxf(mxB, __shfl_xor_sync(0xffffffffu, mxB, 1));
        mxB = fmaxf(mxB, __shfl_xor_sync(0xffffffffu, mxB, 2));
        float mAn = fmaxf(mA, mxA);
        float mBn = fmaxf(mB, mxB);
        float facA = exp2_fast(mA - mAn);
        float facB = exp2_fast(mB - mBn);
        float sumA = 0.f, sumB = 0.f;
#pragma unroll
        for (int nt = 0; nt < 8; nt++) {
            s[nt][0] = exp2_fast(s[nt][0] - mAn);
            s[nt][1] = exp2_fast(s[nt][1] - mAn);
            s[nt][2] = exp2_fast(s[nt][2] - mBn);
            s[nt][3] = exp2_fast(s[nt][3] - mBn);
            sumA += s[nt][0] + s[nt][1];
            sumB += s[nt][2] + s[nt][3];
        }
        sumA += __shfl_xor_sync(0xffffffffu, sumA, 1);
        sumA += __shfl_xor_sync(0xffffffffu, sumA, 2);
        sumB += __shfl_xor_sync(0xffffffffu, sumB, 1);
        sumB += __shfl_xor_sync(0xffffffffu, sumB, 2);
        lA = lA * facA + sumA;
        lB = lB * facB + sumB;
        mA = mAn; mB = mBn;
#pragma unroll
        for (int dn = 0; dn < 8; dn++) {
            acc_o[dn][0] *= facA; acc_o[dn][1] *= facA;
            acc_o[dn][2] *= facB; acc_o[dn][3] *= facB;
        }

#pragma unroll
        for (int kt = 0; kt < 4; kt++) {
            uint32_t Ph[4], Pl[4];
            Ph[0] = pack_bf16x2(s[2 * kt][0], s[2 * kt][1]);
            Ph[1] = pack_bf16x2(s[2 * kt][2], s[2 * kt][3]);
            Ph[2] = pack_bf16x2(s[2 * kt + 1][0], s[2 * kt + 1][1]);
            Ph[3] = pack_bf16x2(s[2 * kt + 1][2], s[2 * kt + 1][3]);
            Pl[0] = pack_bf16x2(s[2 * kt][0] - bf16lo(Ph[0]), s[2 * kt][1] - bf16hi(Ph[0]));
            Pl[1] = pack_bf16x2(s[2 * kt][2] - bf16lo(Ph[1]), s[2 * kt][3] - bf16hi(Ph[1]));
            Pl[2] = pack_bf16x2(s[2 * kt + 1][0] - bf16lo(Ph[2]), s[2 * kt + 1][1] - bf16hi(Ph[2]));
            Pl[3] = pack_bf16x2(s[2 * kt + 1][2] - bf16lo(Ph[3]), s[2 * kt + 1][3] - bf16hi(Ph[3]));
#pragma unroll
            for (int dp = 0; dp < 4; dp++) {
                uint32_t off = ((kt * 16 + ((lane >> 3) & 1) * 8 + (lane & 7)) * 72
                                + dp * 16 + (lane >> 4) * 8) * 2;
                uint32_t vh[4], vl[4];
                ldsm_x4t(vh, aVh + off);
                ldsm_x4t(vl, aVl + off);
                mma_bf16(acc_o[2 * dp],     Ph, vh);
                mma_bf16(acc_o[2 * dp],     Ph, vl);
                mma_bf16(acc_o[2 * dp],     Pl, vh);
                mma_bf16(acc_o[2 * dp + 1], Ph, vh + 2);
                mma_bf16(acc_o[2 * dp + 1], Ph, vl + 2);
                mma_bf16(acc_o[2 * dp + 1], Pl, vh + 2);
            }
        }
        __syncthreads();
    }

    float invA = 1.0f / lA, invB = 1.0f / lB;
    int rA = tok0 + q0 + wid * 16 + (lane >> 2);
#pragma unroll
    for (int dn = 0; dn < 8; dn++) {
        int col = hoff + dn * 8 + (lane & 3) * 2;
        float2 v0 = {acc_o[dn][0] * invA, acc_o[dn][1] * invA};
        float2 v1 = {acc_o[dn][2] * invB, acc_o[dn][3] * invB};
        *(float2*)&O[(size_t)rA * D_MODEL + col] = v0;
        *(float2*)&O[(size_t)(rA + 8) * D_MODEL + col] = v1;
    }
}

// ---------------------------------------------------------------------------
// Subtract projection; writes bf16 hi/lo directly for the final GEMM.
// ---------------------------------------------------------------------------
__global__ void subtract_proj(const float* __restrict__ O, const float* __restrict__ V,
                              const float* __restrict__ xsa,
                              __nv_bfloat16* __restrict__ oh, __nv_bfloat16* __restrict__ ol,
                              int tokens) {
    int gw = (blockIdx.x * blockDim.x + threadIdx.x) >> 5;
    int lane = threadIdx.x & 31;
    if (gw >= tokens * NUM_HEADS) return;
    int t = gw >> 4;
    int h = gw & 15;
    size_t base = (size_t)t * D_MODEL + h * HEAD_DIM;
    const float* v = V + base;
    const float* o = O + base;

    float o0 = o[lane], o1 = o[lane + 32];
    float v0 = v[lane], v1 = v[lane + 32];
    float dot = o0 * v0 + o1 * v1;
    float vn = v0 * v0 + v1 * v1;
#pragma unroll
    for (int off = 16; off > 0; off >>= 1) {
        dot += __shfl_xor_sync(0xffffffffu, dot, off);
        vn  += __shfl_xor_sync(0xffffffffu, vn, off);
    }
    float sc = xsa[0] * dot / (vn + 1e-8f);
    float r0 = o0 - sc * v0;
    float r1 = o1 - sc * v1;
    __nv_bfloat16 h0 = __float2bfloat16(r0);
    __nv_bfloat16 h1 = __float2bfloat16(r1);
    oh[base + lane] = h0;
    oh[base + lane + 32] = h1;
    ol[base + lane] = __float2bfloat16(r0 - __bfloat162float(h0));
    ol[base + lane + 32] = __float2bfloat16(r1 - __bfloat162float(h1));
}

// ---------------------------------------------------------------------------
// Launch
// ---------------------------------------------------------------------------
extern "C" void kernel_launch(void* const* d_in, const int* in_sizes, int n_in,
                              void* d_out, int out_size) {
    const float* x   = (const float*)d_in[0];
    const float* Wq  = (const float*)d_in[1];
    const float* Wk  = (const float*)d_in[2];
    const float* Wv  = (const float*)d_in[3];
    const float* Wo  = (const float*)d_in[4];
    const float* xsa = (const float*)d_in[5];

    const int M = in_sizes[0] / D_MODEL;   // 4096
    const int B = 2;
    const int S = M / B;                   // 2048

    float *v, *o;
    cudaGetSymbolAddress((void**)&v, g_v);
    cudaGetSymbolAddress((void**)&o, g_o);

    __nv_bfloat16 *xh, *xl, *qh, *ql, *kh, *kl, *vh, *vl, *oh, *ol;
    __nv_bfloat16 *wqh, *wql, *wkh, *wkl, *wvh, *wvl, *woh, *wol;
    cudaGetSymbolAddress((void**)&xh, g_xh);
    cudaGetSymbolAddress((void**)&xl, g_xl);
    cudaGetSymbolAddress((void**)&qh, g_qh);
    cudaGetSymbolAddress((void**)&ql, g_ql);
    cudaGetSymbolAddress((void**)&kh, g_kh);
    cudaGetSymbolAddress((void**)&kl, g_kl);
    cudaGetSymbolAddress((void**)&vh, g_vh);
    cudaGetSymbolAddress((void**)&vl, g_vl);
    cudaGetSymbolAddress((void**)&oh, g_oh);
    cudaGetSymbolAddress((void**)&ol, g_ol);
    cudaGetSymbolAddress((void**)&wqh, g_wqh);
    cudaGetSymbolAddress((void**)&wql, g_wql);
    cudaGetSymbolAddress((void**)&wkh, g_wkh);
    cudaGetSymbolAddress((void**)&wkl, g_wkl);
    cudaGetSymbolAddress((void**)&wvh, g_wvh);
    cudaGetSymbolAddress((void**)&wvl, g_wvl);
    cudaGetSymbolAddress((void**)&woh, g_woh);
    cudaGetSymbolAddress((void**)&wol, g_wol);

    static int attr_set = 0;
    if (!attr_set) {
        cudaFuncSetAttribute(gemm_mma, cudaFuncAttributeMaxDynamicSharedMemorySize,
                             GEMM_SMEM);
        attr_set = 1;
    }

    const int nx = M * D_MODEL;
    const int nw = D_MODEL * D_MODEL;

    split_bf16<<<nx / 1024, 256>>>(x, xh, xl, nx);
    dim3 gw4(nw / 1024, 4);
    split_bf16_w4<<<gw4, 256>>>(Wq, Wk, Wv, Wo, wqh, wql, wkh, wkl,
                                wvh, wvl, woh, wol, nw);

    dim3 gg(D_MODEL / 128, M / 128);   // (8, 32)
    gemm_mma<<<gg, 256, GEMM_SMEM>>>(xh, xl, wqh, wql, nullptr, qh, ql, M, D_MODEL, D_MODEL);
    gemm_mma<<<gg, 256, GEMM_SMEM>>>(xh, xl, wkh, wkl, nullptr, kh, kl, M, D_MODEL, D_MODEL);
    gemm_mma<<<gg, 256, GEMM_SMEM>>>(xh, xl, wvh, wvl, v, vh, vl, M, D_MODEL, D_MODEL);

    dim3 gattn(S / 64, NUM_HEADS, B);   // (32, 16, 2)
    attn_mma<<<gattn, 128>>>(qh, ql, kh, kl, vh, vl, o, S);

    int warps = M * NUM_HEADS;
    subtract_proj<<<(warps * 32 + 255) / 256, 256>>>(o, v, xsa, oh, ol, M);

    gemm_mma<<<gg, 256, GEMM_SMEM>>>(oh, ol, woh, wol, (float*)d_out, nullptr, nullptr,
                                     M, D_MODEL, D_MODEL);
}

// round 9
// speedup vs baseline: 1.1085x; 1.1085x over previous
#include <cuda_runtime.h>
#include <cuda_bf16.h>
#include <math.h>
#include <stdint.h>

#define D_MODEL   1024
#define NUM_HEADS 16
#define HEAD_DIM  64
#define NTOK      4096
// (1/sqrt(64)) * log2(e)
#define C_SCALE   0.18033688011112042f

// ---------------- static scratch (allocation-free rule) ----------------
__device__ float g_v[NTOK * D_MODEL];
__device__ float g_o[NTOK * D_MODEL];

__device__ __nv_bfloat16 g_xh[NTOK * D_MODEL];
__device__ __nv_bfloat16 g_xl[NTOK * D_MODEL];
__device__ __nv_bfloat16 g_qh[NTOK * D_MODEL];
__device__ __nv_bfloat16 g_ql[NTOK * D_MODEL];
__device__ __nv_bfloat16 g_kh[NTOK * D_MODEL];
__device__ __nv_bfloat16 g_kl[NTOK * D_MODEL];
__device__ __nv_bfloat16 g_vh[NTOK * D_MODEL];
__device__ __nv_bfloat16 g_vl[NTOK * D_MODEL];
__device__ __nv_bfloat16 g_oh[NTOK * D_MODEL];
__device__ __nv_bfloat16 g_ol[NTOK * D_MODEL];
__device__ __nv_bfloat16 g_wqh[D_MODEL * D_MODEL];
__device__ __nv_bfloat16 g_wql[D_MODEL * D_MODEL];
__device__ __nv_bfloat16 g_wkh[D_MODEL * D_MODEL];
__device__ __nv_bfloat16 g_wkl[D_MODEL * D_MODEL];
__device__ __nv_bfloat16 g_wvh[D_MODEL * D_MODEL];
__device__ __nv_bfloat16 g_wvl[D_MODEL * D_MODEL];
__device__ __nv_bfloat16 g_woh[D_MODEL * D_MODEL];
__device__ __nv_bfloat16 g_wol[D_MODEL * D_MODEL];

// ---------------- helpers ----------------
__device__ __forceinline__ uint32_t smem_u32(const void* p) {
    uint32_t a;
    asm("{ .reg .u64 t; cvta.to.shared.u64 t, %1; cvt.u32.u64 %0, t; }"
        : "=r"(a) : "l"(p));
    return a;
}

__device__ __forceinline__ void ldsm_x4(uint32_t* r, uint32_t addr) {
    asm volatile("ldmatrix.sync.aligned.m8n8.x4.shared.b16 {%0,%1,%2,%3}, [%4];"
                 : "=r"(r[0]), "=r"(r[1]), "=r"(r[2]), "=r"(r[3]) : "r"(addr));
}
__device__ __forceinline__ void ldsm_x4t(uint32_t* r, uint32_t addr) {
    asm volatile("ldmatrix.sync.aligned.m8n8.x4.trans.shared.b16 {%0,%1,%2,%3}, [%4];"
                 : "=r"(r[0]), "=r"(r[1]), "=r"(r[2]), "=r"(r[3]) : "r"(addr));
}
__device__ __forceinline__ void mma_bf16(float* d, const uint32_t* a, const uint32_t* b) {
    asm volatile(
        "mma.sync.aligned.m16n8k16.row.col.f32.bf16.bf16.f32 "
        "{%0,%1,%2,%3}, {%4,%5,%6,%7}, {%8,%9}, {%0,%1,%2,%3};"
        : "+f"(d[0]), "+f"(d[1]), "+f"(d[2]), "+f"(d[3])
        : "r"(a[0]), "r"(a[1]), "r"(a[2]), "r"(a[3]), "r"(b[0]), "r"(b[1]));
}

#define CP_ASYNC16(dst, src) \
    asm volatile("cp.async.cg.shared.global [%0], [%1], 16;" :: "r"(dst), "l"(src))
#define CP_COMMIT asm volatile("cp.async.commit_group;" ::: "memory")
template <int N>
__device__ __forceinline__ void cp_wait() {
    asm volatile("cp.async.wait_group %0;" :: "n"(N) : "memory");
}

__device__ __forceinline__ uint32_t pack_bf16x2(float lo, float hi) {
    __nv_bfloat162 t = __floats2bfloat162_rn(lo, hi);
    return *(uint32_t*)&t;
}
__device__ __forceinline__ float bf16lo(uint32_t p) { return __uint_as_float(p << 16); }
__device__ __forceinline__ float bf16hi(uint32_t p) { return __uint_as_float(p & 0xffff0000u); }

// fast 2^t on FMA pipe (t <= 0 expected), rel err < 2e-5
__device__ __forceinline__ float exp2_fast(float t) {
    t = fmaxf(t, -126.0f);
    float fn = floorf(t);
    float f = t - fn;
    float p = fmaf(f, 0.000154035f, 0.0013333558f);
    p = fmaf(f, p, 0.0096181291f);
    p = fmaf(f, p, 0.0555041087f);
    p = fmaf(f, p, 0.2402265070f);
    p = fmaf(f, p, 0.6931471806f);
    p = fmaf(f, p, 1.0f);
    int n = (int)fn;
    return p * __int_as_float((n + 127) << 23);
}

// ---------------------------------------------------------------------------
// fp32 -> (bf16 hi, bf16 lo) split
// ---------------------------------------------------------------------------
__device__ __forceinline__ void split_body(const float* __restrict__ x,
                                           __nv_bfloat16* __restrict__ h,
                                           __nv_bfloat16* __restrict__ l, int i) {
    float4 v = *(const float4*)(x + i);
    __nv_bfloat16 h0 = __float2bfloat16(v.x);
    __nv_bfloat16 h1 = __float2bfloat16(v.y);
    __nv_bfloat16 h2 = __float2bfloat16(v.z);
    __nv_bfloat16 h3 = __float2bfloat16(v.w);
    __nv_bfloat16 l0 = __float2bfloat16(v.x - __bfloat162float(h0));
    __nv_bfloat16 l1 = __float2bfloat16(v.y - __bfloat162float(h1));
    __nv_bfloat16 l2 = __float2bfloat16(v.z - __bfloat162float(h2));
    __nv_bfloat16 l3 = __float2bfloat16(v.w - __bfloat162float(h3));
    __nv_bfloat162* hp = (__nv_bfloat162*)(h + i);
    __nv_bfloat162* lp = (__nv_bfloat162*)(l + i);
    hp[0] = __nv_bfloat162(h0, h1); hp[1] = __nv_bfloat162(h2, h3);
    lp[0] = __nv_bfloat162(l0, l1); lp[1] = __nv_bfloat162(l2, l3);
}

__global__ void split_bf16(const float* __restrict__ x, __nv_bfloat16* __restrict__ h,
                           __nv_bfloat16* __restrict__ l, int n) {
    int i = (blockIdx.x * blockDim.x + threadIdx.x) * 4;
    if (i < n) split_body(x, h, l, i);
}

__global__ void split_bf16_w4(const float* w0, const float* w1, const float* w2,
                              const float* w3, __nv_bfloat16* h0, __nv_bfloat16* l0,
                              __nv_bfloat16* h1, __nv_bfloat16* l1,
                              __nv_bfloat16* h2, __nv_bfloat16* l2,
                              __nv_bfloat16* h3, __nv_bfloat16* l3, int n) {
    const float* w[4] = {w0, w1, w2, w3};
    __nv_bfloat16* h[4] = {h0, h1, h2, h3};
    __nv_bfloat16* l[4] = {l0, l1, l2, l3};
    int m = blockIdx.y;
    int i = (blockIdx.x * blockDim.x + threadIdx.x) * 4;
    if (i < n) split_body(w[m], h[m], l[m], i);
}

// ---------------------------------------------------------------------------
// HMMA split-bf16 GEMM, attention-style: 64x128 tile, 128 threads (4 warps,
// each warp = 64 rows x 32 cols), single-stage smem, no pipeline, 4 CTAs/SM.
// R8 had the Bl ldsm offset wrong (GA_T instead of GB_T) — fixed here.
// ---------------------------------------------------------------------------
#define GROWH   40                       // halves per smem row (32 data + 8 pad)
#define GA_T    (64 * GROWH * 2)         // 5120 B  (A tile)
#define GB_T    (128 * GROWH * 2)        // 10240 B (B tile)
// layout: Ah | Al | Bh | Bl
#define GOFF_AL GA_T
#define GOFF_BH (2 * GA_T)
#define GOFF_BL (2 * GA_T + GB_T)

__global__ __launch_bounds__(128, 4)
void gemm_mma(const __nv_bfloat16* __restrict__ Ah, const __nv_bfloat16* __restrict__ Al,
              const __nv_bfloat16* __restrict__ Bh, const __nv_bfloat16* __restrict__ Bl,
              float* __restrict__ C, __nv_bfloat16* __restrict__ Ch,
              __nv_bfloat16* __restrict__ Cl, int M, int N, int K) {
    __shared__ __align__(16) char smem[2 * GA_T + 2 * GB_T];   // 30720 B
    const uint32_t sb = smem_u32(smem);
    const int tid = threadIdx.x;
    const int lane = tid & 31;
    const int wid = tid >> 5;            // 0..3, warp n-offset = wid*32
    const int m0 = blockIdx.y * 64;
    const int n0 = blockIdx.x * 128;

    const __nv_bfloat16* aH = Ah + (size_t)m0 * K;
    const __nv_bfloat16* aL = Al + (size_t)m0 * K;
    const __nv_bfloat16* bH = Bh + (size_t)n0 * K;
    const __nv_bfloat16* bL = Bl + (size_t)n0 * K;

    float acc[4][4][4];
#pragma unroll
    for (int a = 0; a < 4; a++)
#pragma unroll
        for (int b = 0; b < 4; b++)
#pragma unroll
            for (int c = 0; c < 4; c++) acc[a][b][c] = 0.f;

    const int NCH = K / 32;   // 32

    for (int kc = 0; kc < NCH; kc++) {
        // ---- load: A 2 segs/thread (hi+lo), B 4 segs/thread (hi+lo) ----
        {
            int koff = kc * 32;
#pragma unroll
            for (int i = 0; i < 2; i++) {
                int seg = tid + i * 128;          // 0..255
                int row = seg >> 2;               // 0..63
                int cs = seg & 3;
                size_t g = (size_t)row * K + koff + cs * 8;
                uint32_t d = (row * GROWH + cs * 8) * 2;
                CP_ASYNC16(sb + d, aH + g);
                CP_ASYNC16(sb + GOFF_AL + d, aL + g);
            }
#pragma unroll
            for (int i = 0; i < 4; i++) {
                int seg = tid + i * 128;          // 0..511
                int row = seg >> 2;               // 0..127
                int cs = seg & 3;
                size_t g = (size_t)row * K + koff + cs * 8;
                uint32_t d = (row * GROWH + cs * 8) * 2;
                CP_ASYNC16(sb + GOFF_BH + d, bH + g);
                CP_ASYNC16(sb + GOFF_BL + d, bL + g);
            }
        }
        CP_COMMIT;
        cp_wait<0>();
        __syncthreads();

        // ---- compute ----
#pragma unroll
        for (int kk = 0; kk < 32; kk += 16) {
            uint32_t ah[4][4], al[4][4];
#pragma unroll
            for (int mt = 0; mt < 4; mt++) {
                uint32_t ar = sb + ((mt * 16 + (lane & 15)) * GROWH
                                    + kk + (lane >> 4) * 8) * 2;
                ldsm_x4(ah[mt], ar);
                ldsm_x4(al[mt], ar + GOFF_AL);
            }
#pragma unroll
            for (int npp = 0; npp < 2; npp++) {
                uint32_t br = sb + GOFF_BH
                            + ((wid * 32 + npp * 16 + ((lane >> 4) << 3) + (lane & 7)) * GROWH
                               + kk + ((lane >> 3) & 1) * 8) * 2;
                uint32_t bh[4], bl[4];
                ldsm_x4(bh, br);
                ldsm_x4(bl, br + GB_T);   // Bl sits GB_T after Bh (R8 bug: was GA_T)
#pragma unroll
                for (int mt = 0; mt < 4; mt++) {
                    mma_bf16(acc[mt][2 * npp],     ah[mt], bh);
                    mma_bf16(acc[mt][2 * npp],     ah[mt], bl);
                    mma_bf16(acc[mt][2 * npp],     al[mt], bh);
                    mma_bf16(acc[mt][2 * npp + 1], ah[mt], bh + 2);
                    mma_bf16(acc[mt][2 * npp + 1], ah[mt], bl + 2);
                    mma_bf16(acc[mt][2 * npp + 1], al[mt], bh + 2);
                }
            }
        }
        __syncthreads();
    }

    // ---- epilogue ----
#pragma unroll
    for (int mt = 0; mt < 4; mt++) {
#pragma unroll
        for (int nt = 0; nt < 4; nt++) {
            int r0 = m0 + mt * 16 + (lane >> 2);
            int col = n0 + wid * 32 + nt * 8 + (lane & 3) * 2;
            float d0 = acc[mt][nt][0], d1 = acc[mt][nt][1];
            float d2 = acc[mt][nt][2], d3 = acc[mt][nt][3];
            if (C) {
                float2 v0 = {d0, d1}, v1 = {d2, d3};
                *(float2*)&C[(size_t)r0 * N + col] = v0;
                *(float2*)&C[(size_t)(r0 + 8) * N + col] = v1;
            }
            if (Ch) {
                uint32_t ph0 = pack_bf16x2(d0, d1);
                uint32_t pl0 = pack_bf16x2(d0 - bf16lo(ph0), d1 - bf16hi(ph0));
                uint32_t ph1 = pack_bf16x2(d2, d3);
                uint32_t pl1 = pack_bf16x2(d2 - bf16lo(ph1), d3 - bf16hi(ph1));
                *(uint32_t*)&Ch[(size_t)r0 * N + col] = ph0;
                *(uint32_t*)&Cl[(size_t)r0 * N + col] = pl0;
                *(uint32_t*)&Ch[(size_t)(r0 + 8) * N + col] = ph1;
                *(uint32_t*)&Cl[(size_t)(r0 + 8) * N + col] = pl1;
            }
        }
    }
}

// ---------------------------------------------------------------------------
// HMMA flash attention — R5-exact version (64-q blocks, 128 thr, static smem)
// ---------------------------------------------------------------------------
__global__ __launch_bounds__(128)
void attn_mma(const __nv_bfloat16* __restrict__ Qh_, const __nv_bfloat16* __restrict__ Ql_,
              const __nv_bfloat16* __restrict__ Kh_, const __nv_bfloat16* __restrict__ Kl_,
              const __nv_bfloat16* __restrict__ Vh_, const __nv_bfloat16* __restrict__ Vl_,
              float* __restrict__ O, int S) {
    __shared__ __align__(16) uint16_t sKh[64 * 72];
    __shared__ __align__(16) uint16_t sKl[64 * 72];
    __shared__ __align__(16) uint16_t sVh[64 * 72];
    __shared__ __align__(16) uint16_t sVl[64 * 72];

    const int tid = threadIdx.x;
    const int lane = tid & 31;
    const int wid = tid >> 5;
    const int h = blockIdx.y;
    const int b = blockIdx.z;
    const int q0 = blockIdx.x * 64;
    const int tok0 = b * S;
    const int hoff = h * HEAD_DIM;

    const uint32_t aKh = smem_u32(sKh), aKl = smem_u32(sKl);
    const uint32_t aVh = smem_u32(sVh), aVl = smem_u32(sVl);

#pragma unroll
    for (int i = 0; i < 4; i++) {
        int seg = tid + i * 128;
        int row = seg >> 3;
        int cs = seg & 7;
        const void* sh = Qh_ + (size_t)(tok0 + q0 + row) * D_MODEL + hoff + cs * 8;
        const void* sl = Ql_ + (size_t)(tok0 + q0 + row) * D_MODEL + hoff + cs * 8;
        CP_ASYNC16(aKh + (row * 72 + cs * 8) * 2, sh);
        CP_ASYNC16(aKl + (row * 72 + cs * 8) * 2, sl);
    }
    CP_COMMIT;
    cp_wait<0>();
    __syncthreads();

    uint32_t qh[4][4], ql[4][4];
#pragma unroll
    for (int kt = 0; kt < 4; kt++) {
        uint32_t off = ((wid * 16 + (lane & 15)) * 72 + kt * 16 + (lane >> 4) * 8) * 2;
        ldsm_x4(qh[kt], aKh + off);
        ldsm_x4(ql[kt], aKl + off);
    }
    __syncthreads();

    float acc_o[8][4];
#pragma unroll
    for (int i = 0; i < 8; i++)
#pragma unroll
        for (int j = 0; j < 4; j++) acc_o[i][j] = 0.f;
    float mA = -1e30f, mB = -1e30f, lA = 0.f, lB = 0.f;

    for (int c0 = 0; c0 < S; c0 += 64) {
#pragma unroll
        for (int i = 0; i < 4; i++) {
            int seg = tid + i * 128;
            int row = seg >> 3;
            int cs = seg & 7;
            size_t g = (size_t)(tok0 + c0 + row) * D_MODEL + hoff + cs * 8;
            uint32_t d = (row * 72 + cs * 8) * 2;
            CP_ASYNC16(aKh + d, Kh_ + g);
            CP_ASYNC16(aKl + d, Kl_ + g);
            CP_ASYNC16(aVh + d, Vh_ + g);
            CP_ASYNC16(aVl + d, Vl_ + g);
        }
        CP_COMMIT;
        cp_wait<0>();
        __syncthreads();

        float s[8][4];
#pragma unroll
        for (int i = 0; i < 8; i++)
#pragma unroll
            for (int j = 0; j < 4; j++) s[i][j] = 0.f;

#pragma unroll
        for (int kt = 0; kt < 4; kt++) {
#pragma unroll
            for (int np = 0; np < 4; np++) {
                uint32_t off = ((np * 16 + ((lane >> 4) << 3) + (lane & 7)) * 72
                                + kt * 16 + ((lane >> 3) & 1) * 8) * 2;
                uint32_t bh[4], bl[4];
                ldsm_x4(bh, aKh + off);
                ldsm_x4(bl, aKl + off);
                mma_bf16(s[2 * np],     qh[kt], bh);
                mma_bf16(s[2 * np],     qh[kt], bl);
                mma_bf16(s[2 * np],     ql[kt], bh);
                mma_bf16(s[2 * np + 1], qh[kt], bh + 2);
                mma_bf16(s[2 * np + 1], qh[kt], bl + 2);
                mma_bf16(s[2 * np + 1], ql[kt], bh + 2);
            }
        }

        float mxA = -1e30f, mxB = -1e30f;
#pragma unroll
        for (int nt = 0; nt < 8; nt++) {
            s[nt][0] *= C_SCALE; s[nt][1] *= C_SCALE;
            s[nt][2] *= C_SCALE; s[nt][3] *= C_SCALE;
            mxA = fmaxf(mxA, fmaxf(s[nt][0], s[nt][1]));
            mxB = fmaxf(mxB, fmaxf(s[nt][2], s[nt][3]));
        }
        mxA = fmaxf(mxA, __shfl_xor_sync(0xffffffffu, mxA, 1));
        mxA = fmaxf(mxA, __shfl_xor_sync(0xffffffffu, mxA, 2));
        mxB = fmaxf(mxB, __shfl_xor_sync(0xffffffffu, mxB, 1));
        mxB = fmaxf(mxB, __shfl_xor_sync(0xffffffffu, mxB, 2));
        float mAn = fmaxf(mA, mxA);
        float mBn = fmaxf(mB, mxB);
        float facA = exp2_fast(mA - mAn);
        float facB = exp2_fast(mB - mBn);
        float sumA = 0.f, sumB = 0.f;
#pragma unroll
        for (int nt = 0; nt < 8; nt++) {
            s[nt][0] = exp2_fast(s[nt][0] - mAn);
            s[nt][1] = exp2_fast(s[nt][1] - mAn);
            s[nt][2] = exp2_fast(s[nt][2] - mBn);
            s[nt][3] = exp2_fast(s[nt][3] - mBn);
            sumA += s[nt][0] + s[nt][1];
            sumB += s[nt][2] + s[nt][3];
        }
        sumA += __shfl_xor_sync(0xffffffffu, sumA, 1);
        sumA += __shfl_xor_sync(0xffffffffu, sumA, 2);
        sumB += __shfl_xor_sync(0xffffffffu, sumB, 1);
        sumB += __shfl_xor_sync(0xffffffffu, sumB, 2);
        lA = lA * facA + sumA;
        lB = lB * facB + sumB;
        mA = mAn; mB = mBn;
#pragma unroll
        for (int dn = 0; dn < 8; dn++) {
            acc_o[dn][0] *= facA; acc_o[dn][1] *= facA;
            acc_o[dn][2] *= facB; acc_o[dn][3] *= facB;
        }

#pragma unroll
        for (int kt = 0; kt < 4; kt++) {
            uint32_t Ph[4], Pl[4];
            Ph[0] = pack_bf16x2(s[2 * kt][0], s[2 * kt][1]);
            Ph[1] = pack_bf16x2(s[2 * kt][2], s[2 * kt][3]);
            Ph[2] = pack_bf16x2(s[2 * kt + 1][0], s[2 * kt + 1][1]);
            Ph[3] = pack_bf16x2(s[2 * kt + 1][2], s[2 * kt + 1][3]);
            Pl[0] = pack_bf16x2(s[2 * kt][0] - bf16lo(Ph[0]), s[2 * kt][1] - bf16hi(Ph[0]));
            Pl[1] = pack_bf16x2(s[2 * kt][2] - bf16lo(Ph[1]), s[2 * kt][3] - bf16hi(Ph[1]));
            Pl[2] = pack_bf16x2(s[2 * kt + 1][0] - bf16lo(Ph[2]), s[2 * kt + 1][1] - bf16hi(Ph[2]));
            Pl[3] = pack_bf16x2(s[2 * kt + 1][2] - bf16lo(Ph[3]), s[2 * kt + 1][3] - bf16hi(Ph[3]));
#pragma unroll
            for (int dp = 0; dp < 4; dp++) {
                uint32_t off = ((kt * 16 + ((lane >> 3) & 1) * 8 + (lane & 7)) * 72
                                + dp * 16 + (lane >> 4) * 8) * 2;
                uint32_t vh[4], vl[4];
                ldsm_x4t(vh, aVh + off);
                ldsm_x4t(vl, aVl + off);
                mma_bf16(acc_o[2 * dp],     Ph, vh);
                mma_bf16(acc_o[2 * dp],     Ph, vl);
                mma_bf16(acc_o[2 * dp],     Pl, vh);
                mma_bf16(acc_o[2 * dp + 1], Ph, vh + 2);
                mma_bf16(acc_o[2 * dp + 1], Ph, vl + 2);
                mma_bf16(acc_o[2 * dp + 1], Pl, vh + 2);
            }
        }
        __syncthreads();
    }

    float invA = 1.0f / lA, invB = 1.0f / lB;
    int rA = tok0 + q0 + wid * 16 + (lane >> 2);
#pragma unroll
    for (int dn = 0; dn < 8; dn++) {
        int col = hoff + dn * 8 + (lane & 3) * 2;
        float2 v0 = {acc_o[dn][0] * invA, acc_o[dn][1] * invA};
        float2 v1 = {acc_o[dn][2] * invB, acc_o[dn][3] * invB};
        *(float2*)&O[(size_t)rA * D_MODEL + col] = v0;
        *(float2*)&O[(size_t)(rA + 8) * D_MODEL + col] = v1;
    }
}

// ---------------------------------------------------------------------------
// Subtract projection; writes bf16 hi/lo directly for the final GEMM.
// ---------------------------------------------------------------------------
__global__ void subtract_proj(const float* __restrict__ O, const float* __restrict__ V,
                              const float* __restrict__ xsa,
                              __nv_bfloat16* __restrict__ oh, __nv_bfloat16* __restrict__ ol,
                              int tokens) {
    int gw = (blockIdx.x * blockDim.x + threadIdx.x) >> 5;
    int lane = threadIdx.x & 31;
    if (gw >= tokens * NUM_HEADS) return;
    int t = gw >> 4;
    int h = gw & 15;
    size_t base = (size_t)t * D_MODEL + h * HEAD_DIM;
    const float* v = V + base;
    const float* o = O + base;

    float o0 = o[lane], o1 = o[lane + 32];
    float v0 = v[lane], v1 = v[lane + 32];
    float dot = o0 * v0 + o1 * v1;
    float vn = v0 * v0 + v1 * v1;
#pragma unroll
    for (int off = 16; off > 0; off >>= 1) {
        dot += __shfl_xor_sync(0xffffffffu, dot, off);
        vn  += __shfl_xor_sync(0xffffffffu, vn, off);
    }
    float sc = xsa[0] * dot / (vn + 1e-8f);
    float r0 = o0 - sc * v0;
    float r1 = o1 - sc * v1;
    __nv_bfloat16 h0 = __float2bfloat16(r0);
    __nv_bfloat16 h1 = __float2bfloat16(r1);
    oh[base + lane] = h0;
    oh[base + lane + 32] = h1;
    ol[base + lane] = __float2bfloat16(r0 - __bfloat162float(h0));
    ol[base + lane + 32] = __float2bfloat16(r1 - __bfloat162float(h1));
}

// ---------------------------------------------------------------------------
// Launch
// ---------------------------------------------------------------------------
extern "C" void kernel_launch(void* const* d_in, const int* in_sizes, int n_in,
                              void* d_out, int out_size) {
    const float* x   = (const float*)d_in[0];
    const float* Wq  = (const float*)d_in[1];
    const float* Wk  = (const float*)d_in[2];
    const float* Wv  = (const float*)d_in[3];
    const float* Wo  = (const float*)d_in[4];
    const float* xsa = (const float*)d_in[5];

    const int M = in_sizes[0] / D_MODEL;   // 4096
    const int B = 2;
    const int S = M / B;                   // 2048

    float *v, *o;
    cudaGetSymbolAddress((void**)&v, g_v);
    cudaGetSymbolAddress((void**)&o, g_o);

    __nv_bfloat16 *xh, *xl, *qh, *ql, *kh, *kl, *vh, *vl, *oh, *ol;
    __nv_bfloat16 *wqh, *wql, *wkh, *wkl, *wvh, *wvl, *woh, *wol;
    cudaGetSymbolAddress((void**)&xh, g_xh);
    cudaGetSymbolAddress((void**)&xl, g_xl);
    cudaGetSymbolAddress((void**)&qh, g_qh);
    cudaGetSymbolAddress((void**)&ql, g_ql);
    cudaGetSymbolAddress((void**)&kh, g_kh);
    cudaGetSymbolAddress((void**)&kl, g_kl);
    cudaGetSymbolAddress((void**)&vh, g_vh);
    cudaGetSymbolAddress((void**)&vl, g_vl);
    cudaGetSymbolAddress((void**)&oh, g_oh);
    cudaGetSymbolAddress((void**)&ol, g_ol);
    cudaGetSymbolAddress((void**)&wqh, g_wqh);
    cudaGetSymbolAddress((void**)&wql, g_wql);
    cudaGetSymbolAddress((void**)&wkh, g_wkh);
    cudaGetSymbolAddress((void**)&wkl, g_wkl);
    cudaGetSymbolAddress((void**)&wvh, g_wvh);
    cudaGetSymbolAddress((void**)&wvl, g_wvl);
    cudaGetSymbolAddress((void**)&woh, g_woh);
    cudaGetSymbolAddress((void**)&wol, g_wol);

    const int nx = M * D_MODEL;
    const int nw = D_MODEL * D_MODEL;

    split_bf16<<<nx / 1024, 256>>>(x, xh, xl, nx);
    dim3 gw4(nw / 1024, 4);
    split_bf16_w4<<<gw4, 256>>>(Wq, Wk, Wv, Wo, wqh, wql, wkh, wkl,
                                wvh, wvl, woh, wol, nw);

    dim3 gg(D_MODEL / 128, M / 64);   // (8, 64) = 512 CTAs
    gemm_mma<<<gg, 128>>>(xh, xl, wqh, wql, nullptr, qh, ql, M, D_MODEL, D_MODEL);
    gemm_mma<<<gg, 128>>>(xh, xl, wkh, wkl, nullptr, kh, kl, M, D_MODEL, D_MODEL);
    gemm_mma<<<gg, 128>>>(xh, xl, wvh, wvl, v, vh, vl, M, D_MODEL, D_MODEL);

    dim3 gattn(S / 64, NUM_HEADS, B);   // (32, 16, 2)
    attn_mma<<<gattn, 128>>>(qh, ql, kh, kl, vh, vl, o, S);

    int warps = M * NUM_HEADS;
    subtract_proj<<<(warps * 32 + 255) / 256, 256>>>(o, v, xsa, oh, ol, M);

    gemm_mma<<<gg, 128>>>(oh, ol, woh, wol, (float*)d_out, nullptr, nullptr,
                          M, D_MODEL, D_MODEL);
}

// round 10
// speedup vs baseline: 1.3465x; 1.2147x over previous
#include <cuda_runtime.h>
#include <cuda_fp16.h>
#include <math.h>
#include <stdint.h>

#define D_MODEL   1024
#define NUM_HEADS 16
#define HEAD_DIM  64
#define NTOK      4096
// (1/sqrt(64)) * log2(e)
#define C_SCALE   0.18033688011112042f

// ---------------- static scratch (allocation-free rule) ----------------
__device__ float g_v[NTOK * D_MODEL];
__device__ float g_o[NTOK * D_MODEL];

__device__ __half g_xh[NTOK * D_MODEL];
__device__ __half g_qh[NTOK * D_MODEL];
__device__ __half g_ql[NTOK * D_MODEL];
__device__ __half g_kh[NTOK * D_MODEL];
__device__ __half g_kl[NTOK * D_MODEL];
__device__ __half g_vh[NTOK * D_MODEL];
__device__ __half g_vl[NTOK * D_MODEL];
__device__ __half g_oh[NTOK * D_MODEL];
__device__ __half g_wqh[D_MODEL * D_MODEL];
__device__ __half g_wql[D_MODEL * D_MODEL];
__device__ __half g_wkh[D_MODEL * D_MODEL];
__device__ __half g_wkl[D_MODEL * D_MODEL];
__device__ __half g_wvh[D_MODEL * D_MODEL];
__device__ __half g_wvl[D_MODEL * D_MODEL];
__device__ __half g_woh[D_MODEL * D_MODEL];
__device__ __half g_wol[D_MODEL * D_MODEL];

// ---------------- helpers ----------------
__device__ __forceinline__ uint32_t smem_u32(const void* p) {
    uint32_t a;
    asm("{ .reg .u64 t; cvta.to.shared.u64 t, %1; cvt.u32.u64 %0, t; }"
        : "=r"(a) : "l"(p));
    return a;
}

__device__ __forceinline__ void ldsm_x4(uint32_t* r, uint32_t addr) {
    asm volatile("ldmatrix.sync.aligned.m8n8.x4.shared.b16 {%0,%1,%2,%3}, [%4];"
                 : "=r"(r[0]), "=r"(r[1]), "=r"(r[2]), "=r"(r[3]) : "r"(addr));
}
__device__ __forceinline__ void ldsm_x4t(uint32_t* r, uint32_t addr) {
    asm volatile("ldmatrix.sync.aligned.m8n8.x4.trans.shared.b16 {%0,%1,%2,%3}, [%4];"
                 : "=r"(r[0]), "=r"(r[1]), "=r"(r[2]), "=r"(r[3]) : "r"(addr));
}
__device__ __forceinline__ void mma_f16(float* d, const uint32_t* a, const uint32_t* b) {
    asm volatile(
        "mma.sync.aligned.m16n8k16.row.col.f32.f16.f16.f32 "
        "{%0,%1,%2,%3}, {%4,%5,%6,%7}, {%8,%9}, {%0,%1,%2,%3};"
        : "+f"(d[0]), "+f"(d[1]), "+f"(d[2]), "+f"(d[3])
        : "r"(a[0]), "r"(a[1]), "r"(a[2]), "r"(a[3]), "r"(b[0]), "r"(b[1]));
}

#define CP_ASYNC16(dst, src) \
    asm volatile("cp.async.cg.shared.global [%0], [%1], 16;" :: "r"(dst), "l"(src))
#define CP_COMMIT asm volatile("cp.async.commit_group;" ::: "memory")
template <int N>
__device__ __forceinline__ void cp_wait() {
    asm volatile("cp.async.wait_group %0;" :: "n"(N) : "memory");
}

__device__ __forceinline__ uint32_t pack_f16x2(float lo, float hi) {
    __half2 t = __floats2half2_rn(lo, hi);   // .x = lo (low 16 bits)
    return *(uint32_t*)&t;
}
__device__ __forceinline__ float f16lo(uint32_t p) {
    return __half2float(__ushort_as_half((unsigned short)(p & 0xffffu)));
}
__device__ __forceinline__ float f16hi(uint32_t p) {
    return __half2float(__ushort_as_half((unsigned short)(p >> 16)));
}

// fast 2^t on FMA pipe (t <= 0 expected), rel err < 2e-5
__device__ __forceinline__ float exp2_fast(float t) {
    t = fmaxf(t, -126.0f);
    float fn = floorf(t);
    float f = t - fn;
    float p = fmaf(f, 0.000154035f, 0.0013333558f);
    p = fmaf(f, p, 0.0096181291f);
    p = fmaf(f, p, 0.0555041087f);
    p = fmaf(f, p, 0.2402265070f);
    p = fmaf(f, p, 0.6931471806f);
    p = fmaf(f, p, 1.0f);
    int n = (int)fn;
    return p * __int_as_float((n + 127) << 23);
}

// ---------------------------------------------------------------------------
// fp32 -> fp16 (hi only) and fp32 -> (fp16 hi, fp16 lo)
// ---------------------------------------------------------------------------
__global__ void tofp16(const float* __restrict__ x, __half* __restrict__ h, int n) {
    int i = (blockIdx.x * blockDim.x + threadIdx.x) * 4;
    if (i >= n) return;
    float4 v = *(const float4*)(x + i);
    __half2* hp = (__half2*)(h + i);
    hp[0] = __floats2half2_rn(v.x, v.y);
    hp[1] = __floats2half2_rn(v.z, v.w);
}

__device__ __forceinline__ void split_body(const float* __restrict__ x,
                                           __half* __restrict__ h,
                                           __half* __restrict__ l, int i) {
    float4 v = *(const float4*)(x + i);
    __half h0 = __float2half_rn(v.x);
    __half h1 = __float2half_rn(v.y);
    __half h2 = __float2half_rn(v.z);
    __half h3 = __float2half_rn(v.w);
    __half l0 = __float2half_rn(v.x - __half2float(h0));
    __half l1 = __float2half_rn(v.y - __half2float(h1));
    __half l2 = __float2half_rn(v.z - __half2float(h2));
    __half l3 = __float2half_rn(v.w - __half2float(h3));
    __half2* hp = (__half2*)(h + i);
    __half2* lp = (__half2*)(l + i);
    hp[0] = __half2(h0, h1); hp[1] = __half2(h2, h3);
    lp[0] = __half2(l0, l1); lp[1] = __half2(l2, l3);
}

__global__ void split_f16_w4(const float* w0, const float* w1, const float* w2,
                             const float* w3, __half* h0, __half* l0,
                             __half* h1, __half* l1, __half* h2, __half* l2,
                             __half* h3, __half* l3, int n) {
    const float* w[4] = {w0, w1, w2, w3};
    __half* h[4] = {h0, h1, h2, h3};
    __half* l[4] = {l0, l1, l2, l3};
    int m = blockIdx.y;
    int i = (blockIdx.x * blockDim.x + threadIdx.x) * 4;
    if (i < n) split_body(w[m], h[m], l[m], i);
}

// ---------------------------------------------------------------------------
// HMMA 2-pass fp16 GEMM: C = Ah*(Bh+Bl)^T. A single fp16, B fp16 hi/lo.
// 64x128 tile, 128 thr (4 warps, each warp 64 rows x 32 cols), 4 CTAs/SM.
// ---------------------------------------------------------------------------
#define GROWH   40                       // halves per smem row (32 data + 8 pad)
#define GA_T    (64 * GROWH * 2)         // 5120 B  (A tile)
#define GB_T    (128 * GROWH * 2)        // 10240 B (B tile)
// layout: A | Bh | Bl   (Bl = Bh + GB_T)

__global__ __launch_bounds__(128, 4)
void gemm_mma(const __half* __restrict__ A,
              const __half* __restrict__ Bh, const __half* __restrict__ Bl,
              float* __restrict__ C, __half* __restrict__ Ch,
              __half* __restrict__ Cl, int M, int N, int K) {
    __shared__ __align__(16) char smem[GA_T + 2 * GB_T];   // 25600 B
    const uint32_t sb = smem_u32(smem);
    const int tid = threadIdx.x;
    const int lane = tid & 31;
    const int wid = tid >> 5;            // 0..3, warp n-offset = wid*32
    const int m0 = blockIdx.y * 64;
    const int n0 = blockIdx.x * 128;

    const __half* aP = A + (size_t)m0 * K;
    const __half* bH = Bh + (size_t)n0 * K;
    const __half* bL = Bl + (size_t)n0 * K;

    float acc[4][4][4];
#pragma unroll
    for (int a = 0; a < 4; a++)
#pragma unroll
        for (int b = 0; b < 4; b++)
#pragma unroll
            for (int c = 0; c < 4; c++) acc[a][b][c] = 0.f;

    const int NCH = K / 32;   // 32

    for (int kc = 0; kc < NCH; kc++) {
        int koff = kc * 32;
        // A: 256 segs (2/thread); B: 512 segs x2 tiles (8/thread)
#pragma unroll
        for (int i = 0; i < 2; i++) {
            int seg = tid + i * 128;
            int row = seg >> 2;
            int cs = seg & 3;
            size_t g = (size_t)row * K + koff + cs * 8;
            uint32_t d = (row * GROWH + cs * 8) * 2;
            CP_ASYNC16(sb + d, aP + g);
        }
#pragma unroll
        for (int i = 0; i < 4; i++) {
            int seg = tid + i * 128;
            int row = seg >> 2;               // 0..127
            int cs = seg & 3;
            size_t g = (size_t)row * K + koff + cs * 8;
            uint32_t d = GA_T + (row * GROWH + cs * 8) * 2;
            CP_ASYNC16(sb + d, bH + g);
            CP_ASYNC16(sb + d + GB_T, bL + g);
        }
        CP_COMMIT;
        cp_wait<0>();
        __syncthreads();

#pragma unroll
        for (int kk = 0; kk < 32; kk += 16) {
            uint32_t ah[4][4];
#pragma unroll
            for (int mt = 0; mt < 4; mt++) {
                uint32_t ar = sb + ((mt * 16 + (lane & 15)) * GROWH
                                    + kk + (lane >> 4) * 8) * 2;
                ldsm_x4(ah[mt], ar);
            }
#pragma unroll
            for (int npp = 0; npp < 2; npp++) {
                uint32_t br = sb + GA_T
                            + ((wid * 32 + npp * 16 + ((lane >> 4) << 3) + (lane & 7)) * GROWH
                               + kk + ((lane >> 3) & 1) * 8) * 2;
                uint32_t bh[4], bl[4];
                ldsm_x4(bh, br);
                ldsm_x4(bl, br + GB_T);
#pragma unroll
                for (int mt = 0; mt < 4; mt++) {
                    mma_f16(acc[mt][2 * npp],     ah[mt], bh);
                    mma_f16(acc[mt][2 * npp],     ah[mt], bl);
                    mma_f16(acc[mt][2 * npp + 1], ah[mt], bh + 2);
                    mma_f16(acc[mt][2 * npp + 1], ah[mt], bl + 2);
                }
            }
        }
        __syncthreads();
    }

    // ---- epilogue ----
#pragma unroll
    for (int mt = 0; mt < 4; mt++) {
#pragma unroll
        for (int nt = 0; nt < 4; nt++) {
            int r0 = m0 + mt * 16 + (lane >> 2);
            int col = n0 + wid * 32 + nt * 8 + (lane & 3) * 2;
            float d0 = acc[mt][nt][0], d1 = acc[mt][nt][1];
            float d2 = acc[mt][nt][2], d3 = acc[mt][nt][3];
            if (C) {
                float2 v0 = {d0, d1}, v1 = {d2, d3};
                *(float2*)&C[(size_t)r0 * N + col] = v0;
                *(float2*)&C[(size_t)(r0 + 8) * N + col] = v1;
            }
            if (Ch) {
                uint32_t ph0 = pack_f16x2(d0, d1);
                uint32_t ph1 = pack_f16x2(d2, d3);
                *(uint32_t*)&Ch[(size_t)r0 * N + col] = ph0;
                *(uint32_t*)&Ch[(size_t)(r0 + 8) * N + col] = ph1;
                if (Cl) {
                    uint32_t pl0 = pack_f16x2(d0 - f16lo(ph0), d1 - f16hi(ph0));
                    uint32_t pl1 = pack_f16x2(d2 - f16lo(ph1), d3 - f16hi(ph1));
                    *(uint32_t*)&Cl[(size_t)r0 * N + col] = pl0;
                    *(uint32_t*)&Cl[(size_t)(r0 + 8) * N + col] = pl1;
                }
            }
        }
    }
}

// ---------------------------------------------------------------------------
// HMMA flash attention, fp16: QK^T 3-pass (score precision), PV 2-pass
// (P nonneg, fp16 P hi suffices; V hi/lo). 64-q blocks, 128 thr.
// ---------------------------------------------------------------------------
__global__ __launch_bounds__(128)
void attn_mma(const __half* __restrict__ Qh_, const __half* __restrict__ Ql_,
              const __half* __restrict__ Kh_, const __half* __restrict__ Kl_,
              const __half* __restrict__ Vh_, const __half* __restrict__ Vl_,
              float* __restrict__ O, int S) {
    __shared__ __align__(16) uint16_t sKh[64 * 72];
    __shared__ __align__(16) uint16_t sKl[64 * 72];
    __shared__ __align__(16) uint16_t sVh[64 * 72];
    __shared__ __align__(16) uint16_t sVl[64 * 72];

    const int tid = threadIdx.x;
    const int lane = tid & 31;
    const int wid = tid >> 5;
    const int h = blockIdx.y;
    const int b = blockIdx.z;
    const int q0 = blockIdx.x * 64;
    const int tok0 = b * S;
    const int hoff = h * HEAD_DIM;

    const uint32_t aKh = smem_u32(sKh), aKl = smem_u32(sKl);
    const uint32_t aVh = smem_u32(sVh), aVl = smem_u32(sVl);

#pragma unroll
    for (int i = 0; i < 4; i++) {
        int seg = tid + i * 128;
        int row = seg >> 3;
        int cs = seg & 7;
        const void* sh = Qh_ + (size_t)(tok0 + q0 + row) * D_MODEL + hoff + cs * 8;
        const void* sl = Ql_ + (size_t)(tok0 + q0 + row) * D_MODEL + hoff + cs * 8;
        CP_ASYNC16(aKh + (row * 72 + cs * 8) * 2, sh);
        CP_ASYNC16(aKl + (row * 72 + cs * 8) * 2, sl);
    }
    CP_COMMIT;
    cp_wait<0>();
    __syncthreads();

    uint32_t qh[4][4], ql[4][4];
#pragma unroll
    for (int kt = 0; kt < 4; kt++) {
        uint32_t off = ((wid * 16 + (lane & 15)) * 72 + kt * 16 + (lane >> 4) * 8) * 2;
        ldsm_x4(qh[kt], aKh + off);
        ldsm_x4(ql[kt], aKl + off);
    }
    __syncthreads();

    float acc_o[8][4];
#pragma unroll
    for (int i = 0; i < 8; i++)
#pragma unroll
        for (int j = 0; j < 4; j++) acc_o[i][j] = 0.f;
    float mA = -1e30f, mB = -1e30f, lA = 0.f, lB = 0.f;

    for (int c0 = 0; c0 < S; c0 += 64) {
#pragma unroll
        for (int i = 0; i < 4; i++) {
            int seg = tid + i * 128;
            int row = seg >> 3;
            int cs = seg & 7;
            size_t g = (size_t)(tok0 + c0 + row) * D_MODEL + hoff + cs * 8;
            uint32_t d = (row * 72 + cs * 8) * 2;
            CP_ASYNC16(aKh + d, Kh_ + g);
            CP_ASYNC16(aKl + d, Kl_ + g);
            CP_ASYNC16(aVh + d, Vh_ + g);
            CP_ASYNC16(aVl + d, Vl_ + g);
        }
        CP_COMMIT;
        cp_wait<0>();
        __syncthreads();

        float s[8][4];
#pragma unroll
        for (int i = 0; i < 8; i++)
#pragma unroll
            for (int j = 0; j < 4; j++) s[i][j] = 0.f;

        // ---- S = Q K^T, 3-pass ----
#pragma unroll
        for (int kt = 0; kt < 4; kt++) {
#pragma unroll
            for (int np = 0; np < 4; np++) {
                uint32_t off = ((np * 16 + ((lane >> 4) << 3) + (lane & 7)) * 72
                                + kt * 16 + ((lane >> 3) & 1) * 8) * 2;
                uint32_t bh[4], bl[4];
                ldsm_x4(bh, aKh + off);
                ldsm_x4(bl, aKl + off);
                mma_f16(s[2 * np],     qh[kt], bh);
                mma_f16(s[2 * np],     qh[kt], bl);
                mma_f16(s[2 * np],     ql[kt], bh);
                mma_f16(s[2 * np + 1], qh[kt], bh + 2);
                mma_f16(s[2 * np + 1], qh[kt], bl + 2);
                mma_f16(s[2 * np + 1], ql[kt], bh + 2);
            }
        }

        float mxA = -1e30f, mxB = -1e30f;
#pragma unroll
        for (int nt = 0; nt < 8; nt++) {
            s[nt][0] *= C_SCALE; s[nt][1] *= C_SCALE;
            s[nt][2] *= C_SCALE; s[nt][3] *= C_SCALE;
            mxA = fmaxf(mxA, fmaxf(s[nt][0], s[nt][1]));
            mxB = fmaxf(mxB, fmaxf(s[nt][2], s[nt][3]));
        }
        mxA = fmaxf(mxA, __shfl_xor_sync(0xffffffffu, mxA, 1));
        mxA = fmaxf(mxA, __shfl_xor_sync(0xffffffffu, mxA, 2));
        mxB = fmaxf(mxB, __shfl_xor_sync(0xffffffffu, mxB, 1));
        mxB = fmaxf(mxB, __shfl_xor_sync(0xffffffffu, mxB, 2));
        float mAn = fmaxf(mA, mxA);
        float mBn = fmaxf(mB, mxB);
        float facA = exp2_fast(mA - mAn);
        float facB = exp2_fast(mB - mBn);
        float sumA = 0.f, sumB = 0.f;
#pragma unroll
        for (int nt = 0; nt < 8; nt++) {
            s[nt][0] = exp2_fast(s[nt][0] - mAn);
            s[nt][1] = exp2_fast(s[nt][1] - mAn);
            s[nt][2] = exp2_fast(s[nt][2] - mBn);
            s[nt][3] = exp2_fast(s[nt][3] - mBn);
            sumA += s[nt][0] + s[nt][1];
            sumB += s[nt][2] + s[nt][3];
        }
        sumA += __shfl_xor_sync(0xffffffffu, sumA, 1);
        sumA += __shfl_xor_sync(0xffffffffu, sumA, 2);
        sumB += __shfl_xor_sync(0xffffffffu, sumB, 1);
        sumB += __shfl_xor_sync(0xffffffffu, sumB, 2);
        lA = lA * facA + sumA;
        lB = lB * facB + sumB;
        mA = mAn; mB = mBn;
#pragma unroll
        for (int dn = 0; dn < 8; dn++) {
            acc_o[dn][0] *= facA; acc_o[dn][1] *= facA;
            acc_o[dn][2] *= facB; acc_o[dn][3] *= facB;
        }

        // ---- O += P V, 2-pass: Ph * (Vh + Vl) ----
#pragma unroll
        for (int kt = 0; kt < 4; kt++) {
            uint32_t Ph[4];
            Ph[0] = pack_f16x2(s[2 * kt][0], s[2 * kt][1]);
            Ph[1] = pack_f16x2(s[2 * kt][2], s[2 * kt][3]);
            Ph[2] = pack_f16x2(s[2 * kt + 1][0], s[2 * kt + 1][1]);
            Ph[3] = pack_f16x2(s[2 * kt + 1][2], s[2 * kt + 1][3]);
#pragma unroll
            for (int dp = 0; dp < 4; dp++) {
                uint32_t off = ((kt * 16 + ((lane >> 3) & 1) * 8 + (lane & 7)) * 72
                                + dp * 16 + (lane >> 4) * 8) * 2;
                uint32_t vh[4], vl[4];
                ldsm_x4t(vh, aVh + off);
                ldsm_x4t(vl, aVl + off);
                mma_f16(acc_o[2 * dp],     Ph, vh);
                mma_f16(acc_o[2 * dp],     Ph, vl);
                mma_f16(acc_o[2 * dp + 1], Ph, vh + 2);
                mma_f16(acc_o[2 * dp + 1], Ph, vl + 2);
            }
        }
        __syncthreads();
    }

    float invA = 1.0f / lA, invB = 1.0f / lB;
    int rA = tok0 + q0 + wid * 16 + (lane >> 2);
#pragma unroll
    for (int dn = 0; dn < 8; dn++) {
        int col = hoff + dn * 8 + (lane & 3) * 2;
        float2 v0 = {acc_o[dn][0] * invA, acc_o[dn][1] * invA};
        float2 v1 = {acc_o[dn][2] * invB, acc_o[dn][3] * invB};
        *(float2*)&O[(size_t)rA * D_MODEL + col] = v0;
        *(float2*)&O[(size_t)(rA + 8) * D_MODEL + col] = v1;
    }
}

// ---------------------------------------------------------------------------
// Subtract projection; writes fp16 (hi only — final GEMM is 2-pass on W side).
// ---------------------------------------------------------------------------
__global__ void subtract_proj(const float* __restrict__ O, const float* __restrict__ V,
                              const float* __restrict__ xsa,
                              __half* __restrict__ oh, int tokens) {
    int gw = (blockIdx.x * blockDim.x + threadIdx.x) >> 5;
    int lane = threadIdx.x & 31;
    if (gw >= tokens * NUM_HEADS) return;
    int t = gw >> 4;
    int h = gw & 15;
    size_t base = (size_t)t * D_MODEL + h * HEAD_DIM;
    const float* v = V + base;
    const float* o = O + base;

    float o0 = o[lane], o1 = o[lane + 32];
    float v0 = v[lane], v1 = v[lane + 32];
    float dot = o0 * v0 + o1 * v1;
    float vn = v0 * v0 + v1 * v1;
#pragma unroll
    for (int off = 16; off > 0; off >>= 1) {
        dot += __shfl_xor_sync(0xffffffffu, dot, off);
        vn  += __shfl_xor_sync(0xffffffffu, vn, off);
    }
    float sc = xsa[0] * dot / (vn + 1e-8f);
    oh[base + lane]      = __float2half_rn(o0 - sc * v0);
    oh[base + lane + 32] = __float2half_rn(o1 - sc * v1);
}

// ---------------------------------------------------------------------------
// Launch
// ---------------------------------------------------------------------------
extern "C" void kernel_launch(void* const* d_in, const int* in_sizes, int n_in,
                              void* d_out, int out_size) {
    const float* x   = (const float*)d_in[0];
    const float* Wq  = (const float*)d_in[1];
    const float* Wk  = (const float*)d_in[2];
    const float* Wv  = (const float*)d_in[3];
    const float* Wo  = (const float*)d_in[4];
    const float* xsa = (const float*)d_in[5];

    const int M = in_sizes[0] / D_MODEL;   // 4096
    const int B = 2;
    const int S = M / B;                   // 2048

    float *v, *o;
    cudaGetSymbolAddress((void**)&v, g_v);
    cudaGetSymbolAddress((void**)&o, g_o);

    __half *xh, *qh, *ql, *kh, *kl, *vh, *vl, *oh;
    __half *wqh, *wql, *wkh, *wkl, *wvh, *wvl, *woh, *wol;
    cudaGetSymbolAddress((void**)&xh, g_xh);
    cudaGetSymbolAddress((void**)&qh, g_qh);
    cudaGetSymbolAddress((void**)&ql, g_ql);
    cudaGetSymbolAddress((void**)&kh, g_kh);
    cudaGetSymbolAddress((void**)&kl, g_kl);
    cudaGetSymbolAddress((void**)&vh, g_vh);
    cudaGetSymbolAddress((void**)&vl, g_vl);
    cudaGetSymbolAddress((void**)&oh, g_oh);
    cudaGetSymbolAddress((void**)&wqh, g_wqh);
    cudaGetSymbolAddress((void**)&wql, g_wql);
    cudaGetSymbolAddress((void**)&wkh, g_wkh);
    cudaGetSymbolAddress((void**)&wkl, g_wkl);
    cudaGetSymbolAddress((void**)&wvh, g_wvh);
    cudaGetSymbolAddress((void**)&wvl, g_wvl);
    cudaGetSymbolAddress((void**)&woh, g_woh);
    cudaGetSymbolAddress((void**)&wol, g_wol);

    const int nx = M * D_MODEL;
    const int nw = D_MODEL * D_MODEL;

    tofp16<<<nx / 1024, 256>>>(x, xh, nx);
    dim3 gw4(nw / 1024, 4);
    split_f16_w4<<<gw4, 256>>>(Wq, Wk, Wv, Wo, wqh, wql, wkh, wkl,
                               wvh, wvl, woh, wol, nw);

    dim3 gg(D_MODEL / 128, M / 64);   // (8, 64) = 512 CTAs
    gemm_mma<<<gg, 128>>>(xh, wqh, wql, nullptr, qh, ql, M, D_MODEL, D_MODEL);
    gemm_mma<<<gg, 128>>>(xh, wkh, wkl, nullptr, kh, kl, M, D_MODEL, D_MODEL);
    gemm_mma<<<gg, 128>>>(xh, wvh, wvl, v, vh, vl, M, D_MODEL, D_MODEL);

    dim3 gattn(S / 64, NUM_HEADS, B);   // (32, 16, 2)
    attn_mma<<<gattn, 128>>>(qh, ql, kh, kl, vh, vl, o, S);

    int warps = M * NUM_HEADS;
    subtract_proj<<<(warps * 32 + 255) / 256, 256>>>(o, v, xsa, oh, M);

    gemm_mma<<<gg, 128>>>(oh, woh, wol, (float*)d_out, nullptr, nullptr,
                          M, D_MODEL, D_MODEL);
}

// round 11
// speedup vs baseline: 1.4274x; 1.0601x over previous
#include <cuda_runtime.h>
#include <cuda_fp16.h>
#include <math.h>
#include <stdint.h>

#define D_MODEL   1024
#define NUM_HEADS 16
#define HEAD_DIM  64
#define NTOK      4096
// (1/sqrt(64)) * log2(e)
#define C_SCALE   0.18033688011112042f

// ---------------- static scratch (allocation-free rule) ----------------
__device__ float g_v[NTOK * D_MODEL];

__device__ __half g_xh[NTOK * D_MODEL];
__device__ __half g_qh[NTOK * D_MODEL];
__device__ __half g_kh[NTOK * D_MODEL];
__device__ __half g_kl[NTOK * D_MODEL];
__device__ __half g_vh[NTOK * D_MODEL];
__device__ __half g_vl[NTOK * D_MODEL];
__device__ __half g_oh[NTOK * D_MODEL];
__device__ __half g_wqh[D_MODEL * D_MODEL];
__device__ __half g_wql[D_MODEL * D_MODEL];
__device__ __half g_wkh[D_MODEL * D_MODEL];
__device__ __half g_wkl[D_MODEL * D_MODEL];
__device__ __half g_wvh[D_MODEL * D_MODEL];
__device__ __half g_wvl[D_MODEL * D_MODEL];
__device__ __half g_woh[D_MODEL * D_MODEL];
__device__ __half g_wol[D_MODEL * D_MODEL];

// ---------------- helpers ----------------
__device__ __forceinline__ uint32_t smem_u32(const void* p) {
    uint32_t a;
    asm("{ .reg .u64 t; cvta.to.shared.u64 t, %1; cvt.u32.u64 %0, t; }"
        : "=r"(a) : "l"(p));
    return a;
}

__device__ __forceinline__ void ldsm_x4(uint32_t* r, uint32_t addr) {
    asm volatile("ldmatrix.sync.aligned.m8n8.x4.shared.b16 {%0,%1,%2,%3}, [%4];"
                 : "=r"(r[0]), "=r"(r[1]), "=r"(r[2]), "=r"(r[3]) : "r"(addr));
}
__device__ __forceinline__ void ldsm_x4t(uint32_t* r, uint32_t addr) {
    asm volatile("ldmatrix.sync.aligned.m8n8.x4.trans.shared.b16 {%0,%1,%2,%3}, [%4];"
                 : "=r"(r[0]), "=r"(r[1]), "=r"(r[2]), "=r"(r[3]) : "r"(addr));
}
__device__ __forceinline__ void mma_f16(float* d, const uint32_t* a, const uint32_t* b) {
    asm volatile(
        "mma.sync.aligned.m16n8k16.row.col.f32.f16.f16.f32 "
        "{%0,%1,%2,%3}, {%4,%5,%6,%7}, {%8,%9}, {%0,%1,%2,%3};"
        : "+f"(d[0]), "+f"(d[1]), "+f"(d[2]), "+f"(d[3])
        : "r"(a[0]), "r"(a[1]), "r"(a[2]), "r"(a[3]), "r"(b[0]), "r"(b[1]));
}

#define CP_ASYNC16(dst, src) \
    asm volatile("cp.async.cg.shared.global [%0], [%1], 16;" :: "r"(dst), "l"(src))
#define CP_COMMIT asm volatile("cp.async.commit_group;" ::: "memory")
template <int N>
__device__ __forceinline__ void cp_wait() {
    asm volatile("cp.async.wait_group %0;" :: "n"(N) : "memory");
}

__device__ __forceinline__ uint32_t pack_f16x2(float lo, float hi) {
    __half2 t = __floats2half2_rn(lo, hi);   // .x = lo (low 16 bits)
    return *(uint32_t*)&t;
}
__device__ __forceinline__ float f16lo(uint32_t p) {
    return __half2float(__ushort_as_half((unsigned short)(p & 0xffffu)));
}
__device__ __forceinline__ float f16hi(uint32_t p) {
    return __half2float(__ushort_as_half((unsigned short)(p >> 16)));
}

// fast 2^t on FMA pipe (t <= 0 expected), rel err < 2e-5
__device__ __forceinline__ float exp2_fast(float t) {
    t = fmaxf(t, -126.0f);
    float fn = floorf(t);
    float f = t - fn;
    float p = fmaf(f, 0.000154035f, 0.0013333558f);
    p = fmaf(f, p, 0.0096181291f);
    p = fmaf(f, p, 0.0555041087f);
    p = fmaf(f, p, 0.2402265070f);
    p = fmaf(f, p, 0.6931471806f);
    p = fmaf(f, p, 1.0f);
    int n = (int)fn;
    return p * __int_as_float((n + 127) << 23);
}

// ---------------------------------------------------------------------------
// fp32 -> fp16 (hi only) and fp32 -> (fp16 hi, fp16 lo)
// ---------------------------------------------------------------------------
__global__ void tofp16(const float* __restrict__ x, __half* __restrict__ h, int n) {
    int i = (blockIdx.x * blockDim.x + threadIdx.x) * 4;
    if (i >= n) return;
    float4 v = *(const float4*)(x + i);
    __half2* hp = (__half2*)(h + i);
    hp[0] = __floats2half2_rn(v.x, v.y);
    hp[1] = __floats2half2_rn(v.z, v.w);
}

__device__ __forceinline__ void split_body(const float* __restrict__ x,
                                           __half* __restrict__ h,
                                           __half* __restrict__ l, int i) {
    float4 v = *(const float4*)(x + i);
    __half h0 = __float2half_rn(v.x);
    __half h1 = __float2half_rn(v.y);
    __half h2 = __float2half_rn(v.z);
    __half h3 = __float2half_rn(v.w);
    __half l0 = __float2half_rn(v.x - __half2float(h0));
    __half l1 = __float2half_rn(v.y - __half2float(h1));
    __half l2 = __float2half_rn(v.z - __half2float(h2));
    __half l3 = __float2half_rn(v.w - __half2float(h3));
    __half2* hp = (__half2*)(h + i);
    __half2* lp = (__half2*)(l + i);
    hp[0] = __half2(h0, h1); hp[1] = __half2(h2, h3);
    lp[0] = __half2(l0, l1); lp[1] = __half2(l2, l3);
}

__global__ void split_f16_w4(const float* w0, const float* w1, const float* w2,
                             const float* w3, __half* h0, __half* l0,
                             __half* h1, __half* l1, __half* h2, __half* l2,
                             __half* h3, __half* l3, int n) {
    const float* w[4] = {w0, w1, w2, w3};
    __half* h[4] = {h0, h1, h2, h3};
    __half* l[4] = {l0, l1, l2, l3};
    int m = blockIdx.y;
    int i = (blockIdx.x * blockDim.x + threadIdx.x) * 4;
    if (i < n) split_body(w[m], h[m], l[m], i);
}

// ---------------------------------------------------------------------------
// HMMA 2-pass fp16 GEMM: C = Ah*(Bh+Bl)^T. (unchanged from R10 — known good)
// ---------------------------------------------------------------------------
#define GROWH   40
#define GA_T    (64 * GROWH * 2)
#define GB_T    (128 * GROWH * 2)

__global__ __launch_bounds__(128, 4)
void gemm_mma(const __half* __restrict__ A,
              const __half* __restrict__ Bh, const __half* __restrict__ Bl,
              float* __restrict__ C, __half* __restrict__ Ch,
              __half* __restrict__ Cl, int M, int N, int K) {
    __shared__ __align__(16) char smem[GA_T + 2 * GB_T];
    const uint32_t sb = smem_u32(smem);
    const int tid = threadIdx.x;
    const int lane = tid & 31;
    const int wid = tid >> 5;
    const int m0 = blockIdx.y * 64;
    const int n0 = blockIdx.x * 128;

    const __half* aP = A + (size_t)m0 * K;
    const __half* bH = Bh + (size_t)n0 * K;
    const __half* bL = Bl + (size_t)n0 * K;

    float acc[4][4][4];
#pragma unroll
    for (int a = 0; a < 4; a++)
#pragma unroll
        for (int b = 0; b < 4; b++)
#pragma unroll
            for (int c = 0; c < 4; c++) acc[a][b][c] = 0.f;

    const int NCH = K / 32;

    for (int kc = 0; kc < NCH; kc++) {
        int koff = kc * 32;
#pragma unroll
        for (int i = 0; i < 2; i++) {
            int seg = tid + i * 128;
            int row = seg >> 2;
            int cs = seg & 3;
            size_t g = (size_t)row * K + koff + cs * 8;
            uint32_t d = (row * GROWH + cs * 8) * 2;
            CP_ASYNC16(sb + d, aP + g);
        }
#pragma unroll
        for (int i = 0; i < 4; i++) {
            int seg = tid + i * 128;
            int row = seg >> 2;
            int cs = seg & 3;
            size_t g = (size_t)row * K + koff + cs * 8;
            uint32_t d = GA_T + (row * GROWH + cs * 8) * 2;
            CP_ASYNC16(sb + d, bH + g);
            CP_ASYNC16(sb + d + GB_T, bL + g);
        }
        CP_COMMIT;
        cp_wait<0>();
        __syncthreads();

#pragma unroll
        for (int kk = 0; kk < 32; kk += 16) {
            uint32_t ah[4][4];
#pragma unroll
            for (int mt = 0; mt < 4; mt++) {
                uint32_t ar = sb + ((mt * 16 + (lane & 15)) * GROWH
                                    + kk + (lane >> 4) * 8) * 2;
                ldsm_x4(ah[mt], ar);
            }
#pragma unroll
            for (int npp = 0; npp < 2; npp++) {
                uint32_t br = sb + GA_T
                            + ((wid * 32 + npp * 16 + ((lane >> 4) << 3) + (lane & 7)) * GROWH
                               + kk + ((lane >> 3) & 1) * 8) * 2;
                uint32_t bh[4], bl[4];
                ldsm_x4(bh, br);
                ldsm_x4(bl, br + GB_T);
#pragma unroll
                for (int mt = 0; mt < 4; mt++) {
                    mma_f16(acc[mt][2 * npp],     ah[mt], bh);
                    mma_f16(acc[mt][2 * npp],     ah[mt], bl);
                    mma_f16(acc[mt][2 * npp + 1], ah[mt], bh + 2);
                    mma_f16(acc[mt][2 * npp + 1], ah[mt], bl + 2);
                }
            }
        }
        __syncthreads();
    }

#pragma unroll
    for (int mt = 0; mt < 4; mt++) {
#pragma unroll
        for (int nt = 0; nt < 4; nt++) {
            int r0 = m0 + mt * 16 + (lane >> 2);
            int col = n0 + wid * 32 + nt * 8 + (lane & 3) * 2;
            float d0 = acc[mt][nt][0], d1 = acc[mt][nt][1];
            float d2 = acc[mt][nt][2], d3 = acc[mt][nt][3];
            if (C) {
                float2 v0 = {d0, d1}, v1 = {d2, d3};
                *(float2*)&C[(size_t)r0 * N + col] = v0;
                *(float2*)&C[(size_t)(r0 + 8) * N + col] = v1;
            }
            if (Ch) {
                uint32_t ph0 = pack_f16x2(d0, d1);
                uint32_t ph1 = pack_f16x2(d2, d3);
                *(uint32_t*)&Ch[(size_t)r0 * N + col] = ph0;
                *(uint32_t*)&Ch[(size_t)(r0 + 8) * N + col] = ph1;
                if (Cl) {
                    uint32_t pl0 = pack_f16x2(d0 - f16lo(ph0), d1 - f16hi(ph0));
                    uint32_t pl1 = pack_f16x2(d2 - f16lo(ph1), d3 - f16hi(ph1));
                    *(uint32_t*)&Cl[(size_t)r0 * N + col] = pl0;
                    *(uint32_t*)&Cl[(size_t)(r0 + 8) * N + col] = pl1;
                }
            }
        }
    }
}

// ---------------------------------------------------------------------------
// HMMA flash attention, fp16. QK^T 2-pass (Q single, K hi/lo), PV 2-pass
// (P single, V hi/lo). Subtract-projection FUSED into the epilogue:
// oh = fp16(o - xsa*(o.v/(|v|^2+eps))*v), written directly for the final GEMM.
// ---------------------------------------------------------------------------
__global__ __launch_bounds__(128)
void attn_mma(const __half* __restrict__ Qh_,
              const __half* __restrict__ Kh_, const __half* __restrict__ Kl_,
              const __half* __restrict__ Vh_, const __half* __restrict__ Vl_,
              const float* __restrict__ Vf, const float* __restrict__ xsa,
              __half* __restrict__ Oh, int S) {
    __shared__ __align__(16) uint16_t sKh[64 * 72];
    __shared__ __align__(16) uint16_t sKl[64 * 72];
    __shared__ __align__(16) uint16_t sVh[64 * 72];
    __shared__ __align__(16) uint16_t sVl[64 * 72];

    const int tid = threadIdx.x;
    const int lane = tid & 31;
    const int wid = tid >> 5;
    const int h = blockIdx.y;
    const int b = blockIdx.z;
    const int q0 = blockIdx.x * 64;
    const int tok0 = b * S;
    const int hoff = h * HEAD_DIM;

    const uint32_t aKh = smem_u32(sKh), aKl = smem_u32(sKl);
    const uint32_t aVh = smem_u32(sVh), aVl = smem_u32(sVl);

    // stage Q (hi only) through sKh
#pragma unroll
    for (int i = 0; i < 4; i++) {
        int seg = tid + i * 128;
        int row = seg >> 3;
        int cs = seg & 7;
        const void* sh = Qh_ + (size_t)(tok0 + q0 + row) * D_MODEL + hoff + cs * 8;
        CP_ASYNC16(aKh + (row * 72 + cs * 8) * 2, sh);
    }
    CP_COMMIT;
    cp_wait<0>();
    __syncthreads();

    uint32_t qh[4][4];
#pragma unroll
    for (int kt = 0; kt < 4; kt++) {
        uint32_t off = ((wid * 16 + (lane & 15)) * 72 + kt * 16 + (lane >> 4) * 8) * 2;
        ldsm_x4(qh[kt], aKh + off);
    }
    __syncthreads();

    float acc_o[8][4];
#pragma unroll
    for (int i = 0; i < 8; i++)
#pragma unroll
        for (int j = 0; j < 4; j++) acc_o[i][j] = 0.f;
    float mA = -1e30f, mB = -1e30f, lA = 0.f, lB = 0.f;

    for (int c0 = 0; c0 < S; c0 += 64) {
#pragma unroll
        for (int i = 0; i < 4; i++) {
            int seg = tid + i * 128;
            int row = seg >> 3;
            int cs = seg & 7;
            size_t g = (size_t)(tok0 + c0 + row) * D_MODEL + hoff + cs * 8;
            uint32_t d = (row * 72 + cs * 8) * 2;
            CP_ASYNC16(aKh + d, Kh_ + g);
            CP_ASYNC16(aKl + d, Kl_ + g);
            CP_ASYNC16(aVh + d, Vh_ + g);
            CP_ASYNC16(aVl + d, Vl_ + g);
        }
        CP_COMMIT;
        cp_wait<0>();
        __syncthreads();

        float s[8][4];
#pragma unroll
        for (int i = 0; i < 8; i++)
#pragma unroll
            for (int j = 0; j < 4; j++) s[i][j] = 0.f;

        // ---- S = Q K^T, 2-pass: Qh * (Kh + Kl) ----
#pragma unroll
        for (int kt = 0; kt < 4; kt++) {
#pragma unroll
            for (int np = 0; np < 4; np++) {
                uint32_t off = ((np * 16 + ((lane >> 4) << 3) + (lane & 7)) * 72
                                + kt * 16 + ((lane >> 3) & 1) * 8) * 2;
                uint32_t bh[4], bl[4];
                ldsm_x4(bh, aKh + off);
                ldsm_x4(bl, aKl + off);
                mma_f16(s[2 * np],     qh[kt], bh);
                mma_f16(s[2 * np],     qh[kt], bl);
                mma_f16(s[2 * np + 1], qh[kt], bh + 2);
                mma_f16(s[2 * np + 1], qh[kt], bl + 2);
            }
        }

        float mxA = -1e30f, mxB = -1e30f;
#pragma unroll
        for (int nt = 0; nt < 8; nt++) {
            s[nt][0] *= C_SCALE; s[nt][1] *= C_SCALE;
            s[nt][2] *= C_SCALE; s[nt][3] *= C_SCALE;
            mxA = fmaxf(mxA, fmaxf(s[nt][0], s[nt][1]));
            mxB = fmaxf(mxB, fmaxf(s[nt][2], s[nt][3]));
        }
        mxA = fmaxf(mxA, __shfl_xor_sync(0xffffffffu, mxA, 1));
        mxA = fmaxf(mxA, __shfl_xor_sync(0xffffffffu, mxA, 2));
        mxB = fmaxf(mxB, __shfl_xor_sync(0xffffffffu, mxB, 1));
        mxB = fmaxf(mxB, __shfl_xor_sync(0xffffffffu, mxB, 2));
        float mAn = fmaxf(mA, mxA);
        float mBn = fmaxf(mB, mxB);
        float facA = exp2_fast(mA - mAn);
        float facB = exp2_fast(mB - mBn);
        float sumA = 0.f, sumB = 0.f;
#pragma unroll
        for (int nt = 0; nt < 8; nt++) {
            s[nt][0] = exp2_fast(s[nt][0] - mAn);
            s[nt][1] = exp2_fast(s[nt][1] - mAn);
            s[nt][2] = exp2_fast(s[nt][2] - mBn);
            s[nt][3] = exp2_fast(s[nt][3] - mBn);
            sumA += s[nt][0] + s[nt][1];
            sumB += s[nt][2] + s[nt][3];
        }
        sumA += __shfl_xor_sync(0xffffffffu, sumA, 1);
        sumA += __shfl_xor_sync(0xffffffffu, sumA, 2);
        sumB += __shfl_xor_sync(0xffffffffu, sumB, 1);
        sumB += __shfl_xor_sync(0xffffffffu, sumB, 2);
        lA = lA * facA + sumA;
        lB = lB * facB + sumB;
        mA = mAn; mB = mBn;
#pragma unroll
        for (int dn = 0; dn < 8; dn++) {
            acc_o[dn][0] *= facA; acc_o[dn][1] *= facA;
            acc_o[dn][2] *= facB; acc_o[dn][3] *= facB;
        }

        // ---- O += P V, 2-pass: Ph * (Vh + Vl) ----
#pragma unroll
        for (int kt = 0; kt < 4; kt++) {
            uint32_t Ph[4];
            Ph[0] = pack_f16x2(s[2 * kt][0], s[2 * kt][1]);
            Ph[1] = pack_f16x2(s[2 * kt][2], s[2 * kt][3]);
            Ph[2] = pack_f16x2(s[2 * kt + 1][0], s[2 * kt + 1][1]);
            Ph[3] = pack_f16x2(s[2 * kt + 1][2], s[2 * kt + 1][3]);
#pragma unroll
            for (int dp = 0; dp < 4; dp++) {
                uint32_t off = ((kt * 16 + ((lane >> 3) & 1) * 8 + (lane & 7)) * 72
                                + dp * 16 + (lane >> 4) * 8) * 2;
                uint32_t vh[4], vl[4];
                ldsm_x4t(vh, aVh + off);
                ldsm_x4t(vl, aVl + off);
                mma_f16(acc_o[2 * dp],     Ph, vh);
                mma_f16(acc_o[2 * dp],     Ph, vl);
                mma_f16(acc_o[2 * dp + 1], Ph, vh + 2);
                mma_f16(acc_o[2 * dp + 1], Ph, vl + 2);
            }
        }
        __syncthreads();
    }

    // ---- epilogue: normalize + FUSED subtract-projection, write fp16 ----
    float invA = 1.0f / lA, invB = 1.0f / lB;
    float xs = xsa[0];
    int rowA = tok0 + q0 + wid * 16 + (lane >> 2);
    int rowB = rowA + 8;
    float dotA = 0.f, vnA = 0.f, dotB = 0.f, vnB = 0.f;
#pragma unroll
    for (int dn = 0; dn < 8; dn++) {
        int col = hoff + dn * 8 + (lane & 3) * 2;
        float2 va = *(const float2*)&Vf[(size_t)rowA * D_MODEL + col];
        float2 vb = *(const float2*)&Vf[(size_t)rowB * D_MODEL + col];
        float o0 = acc_o[dn][0] * invA, o1 = acc_o[dn][1] * invA;
        float o2 = acc_o[dn][2] * invB, o3 = acc_o[dn][3] * invB;
        acc_o[dn][0] = o0; acc_o[dn][1] = o1;
        acc_o[dn][2] = o2; acc_o[dn][3] = o3;
        dotA += o0 * va.x + o1 * va.y;
        vnA  += va.x * va.x + va.y * va.y;
        dotB += o2 * vb.x + o3 * vb.y;
        vnB  += vb.x * vb.x + vb.y * vb.y;
    }
    dotA += __shfl_xor_sync(0xffffffffu, dotA, 1);
    dotA += __shfl_xor_sync(0xffffffffu, dotA, 2);
    vnA  += __shfl_xor_sync(0xffffffffu, vnA, 1);
    vnA  += __shfl_xor_sync(0xffffffffu, vnA, 2);
    dotB += __shfl_xor_sync(0xffffffffu, dotB, 1);
    dotB += __shfl_xor_sync(0xffffffffu, dotB, 2);
    vnB  += __shfl_xor_sync(0xffffffffu, vnB, 1);
    vnB  += __shfl_xor_sync(0xffffffffu, vnB, 2);
    float scA = xs * dotA / (vnA + 1e-8f);
    float scB = xs * dotB / (vnB + 1e-8f);
#pragma unroll
    for (int dn = 0; dn < 8; dn++) {
        int col = hoff + dn * 8 + (lane & 3) * 2;
        float2 va = *(const float2*)&Vf[(size_t)rowA * D_MODEL + col];
        float2 vb = *(const float2*)&Vf[(size_t)rowB * D_MODEL + col];
        uint32_t pa = pack_f16x2(acc_o[dn][0] - scA * va.x,
                                 acc_o[dn][1] - scA * va.y);
        uint32_t pb = pack_f16x2(acc_o[dn][2] - scB * vb.x,
                                 acc_o[dn][3] - scB * vb.y);
        *(uint32_t*)&Oh[(size_t)rowA * D_MODEL + col] = pa;
        *(uint32_t*)&Oh[(size_t)rowB * D_MODEL + col] = pb;
    }
}

// ---------------------------------------------------------------------------
// Launch
// ---------------------------------------------------------------------------
extern "C" void kernel_launch(void* const* d_in, const int* in_sizes, int n_in,
                              void* d_out, int out_size) {
    const float* x   = (const float*)d_in[0];
    const float* Wq  = (const float*)d_in[1];
    const float* Wk  = (const float*)d_in[2];
    const float* Wv  = (const float*)d_in[3];
    const float* Wo  = (const float*)d_in[4];
    const float* xsa = (const float*)d_in[5];

    const int M = in_sizes[0] / D_MODEL;   // 4096
    const int B = 2;
    const int S = M / B;                   // 2048

    float* v;
    cudaGetSymbolAddress((void**)&v, g_v);

    __half *xh, *qh, *kh, *kl, *vh, *vl, *oh;
    __half *wqh, *wql, *wkh, *wkl, *wvh, *wvl, *woh, *wol;
    cudaGetSymbolAddress((void**)&xh, g_xh);
    cudaGetSymbolAddress((void**)&qh, g_qh);
    cudaGetSymbolAddress((void**)&kh, g_kh);
    cudaGetSymbolAddress((void**)&kl, g_kl);
    cudaGetSymbolAddress((void**)&vh, g_vh);
    cudaGetSymbolAddress((void**)&vl, g_vl);
    cudaGetSymbolAddress((void**)&oh, g_oh);
    cudaGetSymbolAddress((void**)&wqh, g_wqh);
    cudaGetSymbolAddress((void**)&wql, g_wql);
    cudaGetSymbolAddress((void**)&wkh, g_wkh);
    cudaGetSymbolAddress((void**)&wkl, g_wkl);
    cudaGetSymbolAddress((void**)&wvh, g_wvh);
    cudaGetSymbolAddress((void**)&wvl, g_wvl);
    cudaGetSymbolAddress((void**)&woh, g_woh);
    cudaGetSymbolAddress((void**)&wol, g_wol);

    const int nx = M * D_MODEL;
    const int nw = D_MODEL * D_MODEL;

    tofp16<<<nx / 1024, 256>>>(x, xh, nx);
    dim3 gw4(nw / 1024, 4);
    split_f16_w4<<<gw4, 256>>>(Wq, Wk, Wv, Wo, wqh, wql, wkh, wkl,
                               wvh, wvl, woh, wol, nw);

    dim3 gg(D_MODEL / 128, M / 64);   // (8, 64) = 512 CTAs
    gemm_mma<<<gg, 128>>>(xh, wqh, wql, nullptr, qh, nullptr, M, D_MODEL, D_MODEL);
    gemm_mma<<<gg, 128>>>(xh, wkh, wkl, nullptr, kh, kl, M, D_MODEL, D_MODEL);
    gemm_mma<<<gg, 128>>>(xh, wvh, wvl, v, vh, vl, M, D_MODEL, D_MODEL);

    dim3 gattn(S / 64, NUM_HEADS, B);   // (32, 16, 2)
    attn_mma<<<gattn, 128>>>(qh, kh, kl, vh, vl, v, xsa, oh, S);

    gemm_mma<<<gg, 128>>>(oh, woh, wol, (float*)d_out, nullptr, nullptr,
                          M, D_MODEL, D_MODEL);
}

// round 12
// speedup vs baseline: 1.7445x; 1.2221x over previous
#include <cuda_runtime.h>
#include <cuda_fp16.h>
#include <math.h>
#include <stdint.h>

#define D_MODEL   1024
#define NUM_HEADS 16
#define HEAD_DIM  64
#define NTOK      4096
// (1/sqrt(64)) * log2(e)
#define C_SCALE   0.18033688011112042f

// ---------------- static scratch (allocation-free rule) ----------------
__device__ float g_v[NTOK * D_MODEL];

__device__ __half g_xh[NTOK * D_MODEL];
__device__ __half g_qh[NTOK * D_MODEL];
__device__ __half g_kh[NTOK * D_MODEL];
__device__ __half g_vh[NTOK * D_MODEL];
__device__ __half g_oh[NTOK * D_MODEL];
__device__ __half g_wqh[D_MODEL * D_MODEL];
__device__ __half g_wql[D_MODEL * D_MODEL];
__device__ __half g_wkh[D_MODEL * D_MODEL];
__device__ __half g_wkl[D_MODEL * D_MODEL];
__device__ __half g_wvh[D_MODEL * D_MODEL];
__device__ __half g_wvl[D_MODEL * D_MODEL];
__device__ __half g_woh[D_MODEL * D_MODEL];
__device__ __half g_wol[D_MODEL * D_MODEL];

// ---------------- helpers ----------------
__device__ __forceinline__ uint32_t smem_u32(const void* p) {
    uint32_t a;
    asm("{ .reg .u64 t; cvta.to.shared.u64 t, %1; cvt.u32.u64 %0, t; }"
        : "=r"(a) : "l"(p));
    return a;
}

__device__ __forceinline__ void ldsm_x4(uint32_t* r, uint32_t addr) {
    asm volatile("ldmatrix.sync.aligned.m8n8.x4.shared.b16 {%0,%1,%2,%3}, [%4];"
                 : "=r"(r[0]), "=r"(r[1]), "=r"(r[2]), "=r"(r[3]) : "r"(addr));
}
__device__ __forceinline__ void ldsm_x4t(uint32_t* r, uint32_t addr) {
    asm volatile("ldmatrix.sync.aligned.m8n8.x4.trans.shared.b16 {%0,%1,%2,%3}, [%4];"
                 : "=r"(r[0]), "=r"(r[1]), "=r"(r[2]), "=r"(r[3]) : "r"(addr));
}
__device__ __forceinline__ void mma_f16(float* d, const uint32_t* a, const uint32_t* b) {
    asm volatile(
        "mma.sync.aligned.m16n8k16.row.col.f32.f16.f16.f32 "
        "{%0,%1,%2,%3}, {%4,%5,%6,%7}, {%8,%9}, {%0,%1,%2,%3};"
        : "+f"(d[0]), "+f"(d[1]), "+f"(d[2]), "+f"(d[3])
        : "r"(a[0]), "r"(a[1]), "r"(a[2]), "r"(a[3]), "r"(b[0]), "r"(b[1]));
}

#define CP_ASYNC16(dst, src) \
    asm volatile("cp.async.cg.shared.global [%0], [%1], 16;" :: "r"(dst), "l"(src))
#define CP_COMMIT asm volatile("cp.async.commit_group;" ::: "memory")
template <int N>
__device__ __forceinline__ void cp_wait() {
    asm volatile("cp.async.wait_group %0;" :: "n"(N) : "memory");
}

__device__ __forceinline__ uint32_t pack_f16x2(float lo, float hi) {
    __half2 t = __floats2half2_rn(lo, hi);   // .x = lo (low 16 bits)
    return *(uint32_t*)&t;
}
__device__ __forceinline__ float f16lo(uint32_t p) {
    return __half2float(__ushort_as_half((unsigned short)(p & 0xffffu)));
}
__device__ __forceinline__ float f16hi(uint32_t p) {
    return __half2float(__ushort_as_half((unsigned short)(p >> 16)));
}

// fast 2^t on FMA pipe (t <= 0 expected), rel err < 2e-5
__device__ __forceinline__ float exp2_fast(float t) {
    t = fmaxf(t, -126.0f);
    float fn = floorf(t);
    float f = t - fn;
    float p = fmaf(f, 0.000154035f, 0.0013333558f);
    p = fmaf(f, p, 0.0096181291f);
    p = fmaf(f, p, 0.0555041087f);
    p = fmaf(f, p, 0.2402265070f);
    p = fmaf(f, p, 0.6931471806f);
    p = fmaf(f, p, 1.0f);
    int n = (int)fn;
    return p * __int_as_float((n + 127) << 23);
}

// ---------------------------------------------------------------------------
// fp32 -> fp16 (hi only) and fp32 -> (fp16 hi, fp16 lo)
// ---------------------------------------------------------------------------
__global__ void tofp16(const float* __restrict__ x, __half* __restrict__ h, int n) {
    int i = (blockIdx.x * blockDim.x + threadIdx.x) * 4;
    if (i >= n) return;
    float4 v = *(const float4*)(x + i);
    __half2* hp = (__half2*)(h + i);
    hp[0] = __floats2half2_rn(v.x, v.y);
    hp[1] = __floats2half2_rn(v.z, v.w);
}

__device__ __forceinline__ void split_body(const float* __restrict__ x,
                                           __half* __restrict__ h,
                                           __half* __restrict__ l, int i) {
    float4 v = *(const float4*)(x + i);
    __half h0 = __float2half_rn(v.x);
    __half h1 = __float2half_rn(v.y);
    __half h2 = __float2half_rn(v.z);
    __half h3 = __float2half_rn(v.w);
    __half l0 = __float2half_rn(v.x - __half2float(h0));
    __half l1 = __float2half_rn(v.y - __half2float(h1));
    __half l2 = __float2half_rn(v.z - __half2float(h2));
    __half l3 = __float2half_rn(v.w - __half2float(h3));
    __half2* hp = (__half2*)(h + i);
    __half2* lp = (__half2*)(l + i);
    hp[0] = __half2(h0, h1); hp[1] = __half2(h2, h3);
    lp[0] = __half2(l0, l1); lp[1] = __half2(l2, l3);
}

__global__ void split_f16_w4(const float* w0, const float* w1, const float* w2,
                             const float* w3, __half* h0, __half* l0,
                             __half* h1, __half* l1, __half* h2, __half* l2,
                             __half* h3, __half* l3, int n) {
    const float* w[4] = {w0, w1, w2, w3};
    __half* h[4] = {h0, h1, h2, h3};
    __half* l[4] = {l0, l1, l2, l3};
    int m = blockIdx.y;
    int i = (blockIdx.x * blockDim.x + threadIdx.x) * 4;
    if (i < n) split_body(w[m], h[m], l[m], i);
}

// ---------------------------------------------------------------------------
// HMMA 2-pass fp16 GEMM: C = Ah*(Bh+Bl)^T. (unchanged — known good)
// ---------------------------------------------------------------------------
#define GROWH   40
#define GA_T    (64 * GROWH * 2)
#define GB_T    (128 * GROWH * 2)

__global__ __launch_bounds__(128, 4)
void gemm_mma(const __half* __restrict__ A,
              const __half* __restrict__ Bh, const __half* __restrict__ Bl,
              float* __restrict__ C, __half* __restrict__ Ch,
              __half* __restrict__ Cl, int M, int N, int K) {
    __shared__ __align__(16) char smem[GA_T + 2 * GB_T];
    const uint32_t sb = smem_u32(smem);
    const int tid = threadIdx.x;
    const int lane = tid & 31;
    const int wid = tid >> 5;
    const int m0 = blockIdx.y * 64;
    const int n0 = blockIdx.x * 128;

    const __half* aP = A + (size_t)m0 * K;
    const __half* bH = Bh + (size_t)n0 * K;
    const __half* bL = Bl + (size_t)n0 * K;

    float acc[4][4][4];
#pragma unroll
    for (int a = 0; a < 4; a++)
#pragma unroll
        for (int b = 0; b < 4; b++)
#pragma unroll
            for (int c = 0; c < 4; c++) acc[a][b][c] = 0.f;

    const int NCH = K / 32;

    for (int kc = 0; kc < NCH; kc++) {
        int koff = kc * 32;
#pragma unroll
        for (int i = 0; i < 2; i++) {
            int seg = tid + i * 128;
            int row = seg >> 2;
            int cs = seg & 3;
            size_t g = (size_t)row * K + koff + cs * 8;
            uint32_t d = (row * GROWH + cs * 8) * 2;
            CP_ASYNC16(sb + d, aP + g);
        }
#pragma unroll
        for (int i = 0; i < 4; i++) {
            int seg = tid + i * 128;
            int row = seg >> 2;
            int cs = seg & 3;
            size_t g = (size_t)row * K + koff + cs * 8;
            uint32_t d = GA_T + (row * GROWH + cs * 8) * 2;
            CP_ASYNC16(sb + d, bH + g);
            CP_ASYNC16(sb + d + GB_T, bL + g);
        }
        CP_COMMIT;
        cp_wait<0>();
        __syncthreads();

#pragma unroll
        for (int kk = 0; kk < 32; kk += 16) {
            uint32_t ah[4][4];
#pragma unroll
            for (int mt = 0; mt < 4; mt++) {
                uint32_t ar = sb + ((mt * 16 + (lane & 15)) * GROWH
                                    + kk + (lane >> 4) * 8) * 2;
                ldsm_x4(ah[mt], ar);
            }
#pragma unroll
            for (int npp = 0; npp < 2; npp++) {
                uint32_t br = sb + GA_T
                            + ((wid * 32 + npp * 16 + ((lane >> 4) << 3) + (lane & 7)) * GROWH
                               + kk + ((lane >> 3) & 1) * 8) * 2;
                uint32_t bh[4], bl[4];
                ldsm_x4(bh, br);
                ldsm_x4(bl, br + GB_T);
#pragma unroll
                for (int mt = 0; mt < 4; mt++) {
                    mma_f16(acc[mt][2 * npp],     ah[mt], bh);
                    mma_f16(acc[mt][2 * npp],     ah[mt], bl);
                    mma_f16(acc[mt][2 * npp + 1], ah[mt], bh + 2);
                    mma_f16(acc[mt][2 * npp + 1], ah[mt], bl + 2);
                }
            }
        }
        __syncthreads();
    }

#pragma unroll
    for (int mt = 0; mt < 4; mt++) {
#pragma unroll
        for (int nt = 0; nt < 4; nt++) {
            int r0 = m0 + mt * 16 + (lane >> 2);
            int col = n0 + wid * 32 + nt * 8 + (lane & 3) * 2;
            float d0 = acc[mt][nt][0], d1 = acc[mt][nt][1];
            float d2 = acc[mt][nt][2], d3 = acc[mt][nt][3];
            if (C) {
                float2 v0 = {d0, d1}, v1 = {d2, d3};
                *(float2*)&C[(size_t)r0 * N + col] = v0;
                *(float2*)&C[(size_t)(r0 + 8) * N + col] = v1;
            }
            if (Ch) {
                uint32_t ph0 = pack_f16x2(d0, d1);
                uint32_t ph1 = pack_f16x2(d2, d3);
                *(uint32_t*)&Ch[(size_t)r0 * N + col] = ph0;
                *(uint32_t*)&Ch[(size_t)(r0 + 8) * N + col] = ph1;
                if (Cl) {
                    uint32_t pl0 = pack_f16x2(d0 - f16lo(ph0), d1 - f16hi(ph0));
                    uint32_t pl1 = pack_f16x2(d2 - f16lo(ph1), d3 - f16hi(ph1));
                    *(uint32_t*)&Cl[(size_t)r0 * N + col] = pl0;
                    *(uint32_t*)&Cl[(size_t)(r0 + 8) * N + col] = pl1;
                }
            }
        }
    }
}

// ---------------------------------------------------------------------------
// HMMA flash attention, fp16 single-pass MMAs: QK^T = Qh*Kh, O += Ph*Vh.
// Subtract-projection fused into the epilogue (fp32 V), writes fp16 Oh.
// ---------------------------------------------------------------------------
__global__ __launch_bounds__(128)
void attn_mma(const __half* __restrict__ Qh_,
              const __half* __restrict__ Kh_, const __half* __restrict__ Vh_,
              const float* __restrict__ Vf, const float* __restrict__ xsa,
              __half* __restrict__ Oh, int S) {
    __shared__ __align__(16) uint16_t sK[64 * 72];
    __shared__ __align__(16) uint16_t sV[64 * 72];

    const int tid = threadIdx.x;
    const int lane = tid & 31;
    const int wid = tid >> 5;
    const int h = blockIdx.y;
    const int b = blockIdx.z;
    const int q0 = blockIdx.x * 64;
    const int tok0 = b * S;
    const int hoff = h * HEAD_DIM;

    const uint32_t aK = smem_u32(sK), aV = smem_u32(sV);

    // stage Q through sK
#pragma unroll
    for (int i = 0; i < 4; i++) {
        int seg = tid + i * 128;
        int row = seg >> 3;
        int cs = seg & 7;
        const void* sh = Qh_ + (size_t)(tok0 + q0 + row) * D_MODEL + hoff + cs * 8;
        CP_ASYNC16(aK + (row * 72 + cs * 8) * 2, sh);
    }
    CP_COMMIT;
    cp_wait<0>();
    __syncthreads();

    uint32_t qh[4][4];
#pragma unroll
    for (int kt = 0; kt < 4; kt++) {
        uint32_t off = ((wid * 16 + (lane & 15)) * 72 + kt * 16 + (lane >> 4) * 8) * 2;
        ldsm_x4(qh[kt], aK + off);
    }
    __syncthreads();

    float acc_o[8][4];
#pragma unroll
    for (int i = 0; i < 8; i++)
#pragma unroll
        for (int j = 0; j < 4; j++) acc_o[i][j] = 0.f;
    float mA = -1e30f, mB = -1e30f, lA = 0.f, lB = 0.f;

    for (int c0 = 0; c0 < S; c0 += 64) {
#pragma unroll
        for (int i = 0; i < 4; i++) {
            int seg = tid + i * 128;
            int row = seg >> 3;
            int cs = seg & 7;
            size_t g = (size_t)(tok0 + c0 + row) * D_MODEL + hoff + cs * 8;
            uint32_t d = (row * 72 + cs * 8) * 2;
            CP_ASYNC16(aK + d, Kh_ + g);
            CP_ASYNC16(aV + d, Vh_ + g);
        }
        CP_COMMIT;
        cp_wait<0>();
        __syncthreads();

        float s[8][4];
#pragma unroll
        for (int i = 0; i < 8; i++)
#pragma unroll
            for (int j = 0; j < 4; j++) s[i][j] = 0.f;

        // ---- S = Q K^T, 1-pass ----
#pragma unroll
        for (int kt = 0; kt < 4; kt++) {
#pragma unroll
            for (int np = 0; np < 4; np++) {
                uint32_t off = ((np * 16 + ((lane >> 4) << 3) + (lane & 7)) * 72
                                + kt * 16 + ((lane >> 3) & 1) * 8) * 2;
                uint32_t bh[4];
                ldsm_x4(bh, aK + off);
                mma_f16(s[2 * np],     qh[kt], bh);
                mma_f16(s[2 * np + 1], qh[kt], bh + 2);
            }
        }

        float mxA = -1e30f, mxB = -1e30f;
#pragma unroll
        for (int nt = 0; nt < 8; nt++) {
            s[nt][0] *= C_SCALE; s[nt][1] *= C_SCALE;
            s[nt][2] *= C_SCALE; s[nt][3] *= C_SCALE;
            mxA = fmaxf(mxA, fmaxf(s[nt][0], s[nt][1]));
            mxB = fmaxf(mxB, fmaxf(s[nt][2], s[nt][3]));
        }
        mxA = fmaxf(mxA, __shfl_xor_sync(0xffffffffu, mxA, 1));
        mxA = fmaxf(mxA, __shfl_xor_sync(0xffffffffu, mxA, 2));
        mxB = fmaxf(mxB, __shfl_xor_sync(0xffffffffu, mxB, 1));
        mxB = fmaxf(mxB, __shfl_xor_sync(0xffffffffu, mxB, 2));
        float mAn = fmaxf(mA, mxA);
        float mBn = fmaxf(mB, mxB);
        float facA = exp2_fast(mA - mAn);
        float facB = exp2_fast(mB - mBn);
        float sumA = 0.f, sumB = 0.f;
#pragma unroll
        for (int nt = 0; nt < 8; nt++) {
            s[nt][0] = exp2_fast(s[nt][0] - mAn);
            s[nt][1] = exp2_fast(s[nt][1] - mAn);
            s[nt][2] = exp2_fast(s[nt][2] - mBn);
            s[nt][3] = exp2_fast(s[nt][3] - mBn);
            sumA += s[nt][0] + s[nt][1];
            sumB += s[nt][2] + s[nt][3];
        }
        sumA += __shfl_xor_sync(0xffffffffu, sumA, 1);
        sumA += __shfl_xor_sync(0xffffffffu, sumA, 2);
        sumB += __shfl_xor_sync(0xffffffffu, sumB, 1);
        sumB += __shfl_xor_sync(0xffffffffu, sumB, 2);
        lA = lA * facA + sumA;
        lB = lB * facB + sumB;
        mA = mAn; mB = mBn;
#pragma unroll
        for (int dn = 0; dn < 8; dn++) {
            acc_o[dn][0] *= facA; acc_o[dn][1] *= facA;
            acc_o[dn][2] *= facB; acc_o[dn][3] *= facB;
        }

        // ---- O += P V, 1-pass ----
#pragma unroll
        for (int kt = 0; kt < 4; kt++) {
            uint32_t Ph[4];
            Ph[0] = pack_f16x2(s[2 * kt][0], s[2 * kt][1]);
            Ph[1] = pack_f16x2(s[2 * kt][2], s[2 * kt][3]);
            Ph[2] = pack_f16x2(s[2 * kt + 1][0], s[2 * kt + 1][1]);
            Ph[3] = pack_f16x2(s[2 * kt + 1][2], s[2 * kt + 1][3]);
#pragma unroll
            for (int dp = 0; dp < 4; dp++) {
                uint32_t off = ((kt * 16 + ((lane >> 3) & 1) * 8 + (lane & 7)) * 72
                                + dp * 16 + (lane >> 4) * 8) * 2;
                uint32_t vh[4];
                ldsm_x4t(vh, aV + off);
                mma_f16(acc_o[2 * dp],     Ph, vh);
                mma_f16(acc_o[2 * dp + 1], Ph, vh + 2);
            }
        }
        __syncthreads();
    }

    // ---- epilogue: normalize + fused subtract-projection, write fp16 ----
    float invA = 1.0f / lA, invB = 1.0f / lB;
    float xs = xsa[0];
    int rowA = tok0 + q0 + wid * 16 + (lane >> 2);
    int rowB = rowA + 8;
    float dotA = 0.f, vnA = 0.f, dotB = 0.f, vnB = 0.f;
#pragma unroll
    for (int dn = 0; dn < 8; dn++) {
        int col = hoff + dn * 8 + (lane & 3) * 2;
        float2 va = *(const float2*)&Vf[(size_t)rowA * D_MODEL + col];
        float2 vb = *(const float2*)&Vf[(size_t)rowB * D_MODEL + col];
        float o0 = acc_o[dn][0] * invA, o1 = acc_o[dn][1] * invA;
        float o2 = acc_o[dn][2] * invB, o3 = acc_o[dn][3] * invB;
        acc_o[dn][0] = o0; acc_o[dn][1] = o1;
        acc_o[dn][2] = o2; acc_o[dn][3] = o3;
        dotA += o0 * va.x + o1 * va.y;
        vnA  += va.x * va.x + va.y * va.y;
        dotB += o2 * vb.x + o3 * vb.y;
        vnB  += vb.x * vb.x + vb.y * vb.y;
    }
    dotA += __shfl_xor_sync(0xffffffffu, dotA, 1);
    dotA += __shfl_xor_sync(0xffffffffu, dotA, 2);
    vnA  += __shfl_xor_sync(0xffffffffu, vnA, 1);
    vnA  += __shfl_xor_sync(0xffffffffu, vnA, 2);
    dotB += __shfl_xor_sync(0xffffffffu, dotB, 1);
    dotB += __shfl_xor_sync(0xffffffffu, dotB, 2);
    vnB  += __shfl_xor_sync(0xffffffffu, vnB, 1);
    vnB  += __shfl_xor_sync(0xffffffffu, vnB, 2);
    float scA = xs * dotA / (vnA + 1e-8f);
    float scB = xs * dotB / (vnB + 1e-8f);
#pragma unroll
    for (int dn = 0; dn < 8; dn++) {
        int col = hoff + dn * 8 + (lane & 3) * 2;
        float2 va = *(const float2*)&Vf[(size_t)rowA * D_MODEL + col];
        float2 vb = *(const float2*)&Vf[(size_t)rowB * D_MODEL + col];
        uint32_t pa = pack_f16x2(acc_o[dn][0] - scA * va.x,
                                 acc_o[dn][1] - scA * va.y);
        uint32_t pb = pack_f16x2(acc_o[dn][2] - scB * vb.x,
                                 acc_o[dn][3] - scB * vb.y);
        *(uint32_t*)&Oh[(size_t)rowA * D_MODEL + col] = pa;
        *(uint32_t*)&Oh[(size_t)rowB * D_MODEL + col] = pb;
    }
}

// ---------------------------------------------------------------------------
// Launch
// ---------------------------------------------------------------------------
extern "C" void kernel_launch(void* const* d_in, const int* in_sizes, int n_in,
                              void* d_out, int out_size) {
    const float* x   = (const float*)d_in[0];
    const float* Wq  = (const float*)d_in[1];
    const float* Wk  = (const float*)d_in[2];
    const float* Wv  = (const float*)d_in[3];
    const float* Wo  = (const float*)d_in[4];
    const float* xsa = (const float*)d_in[5];

    const int M = in_sizes[0] / D_MODEL;   // 4096
    const int B = 2;
    const int S = M / B;                   // 2048

    float* v;
    cudaGetSymbolAddress((void**)&v, g_v);

    __half *xh, *qh, *kh, *vh, *oh;
    __half *wqh, *wql, *wkh, *wkl, *wvh, *wvl, *woh, *wol;
    cudaGetSymbolAddress((void**)&xh, g_xh);
    cudaGetSymbolAddress((void**)&qh, g_qh);
    cudaGetSymbolAddress((void**)&kh, g_kh);
    cudaGetSymbolAddress((void**)&vh, g_vh);
    cudaGetSymbolAddress((void**)&oh, g_oh);
    cudaGetSymbolAddress((void**)&wqh, g_wqh);
    cudaGetSymbolAddress((void**)&wql, g_wql);
    cudaGetSymbolAddress((void**)&wkh, g_wkh);
    cudaGetSymbolAddress((void**)&wkl, g_wkl);
    cudaGetSymbolAddress((void**)&wvh, g_wvh);
    cudaGetSymbolAddress((void**)&wvl, g_wvl);
    cudaGetSymbolAddress((void**)&woh, g_woh);
    cudaGetSymbolAddress((void**)&wol, g_wol);

    const int nx = M * D_MODEL;
    const int nw = D_MODEL * D_MODEL;

    tofp16<<<nx / 1024, 256>>>(x, xh, nx);
    dim3 gw4(nw / 1024, 4);
    split_f16_w4<<<gw4, 256>>>(Wq, Wk, Wv, Wo, wqh, wql, wkh, wkl,
                               wvh, wvl, woh, wol, nw);

    dim3 gg(D_MODEL / 128, M / 64);   // (8, 64) = 512 CTAs
    gemm_mma<<<gg, 128>>>(xh, wqh, wql, nullptr, qh, nullptr, M, D_MODEL, D_MODEL);
    gemm_mma<<<gg, 128>>>(xh, wkh, wkl, nullptr, kh, nullptr, M, D_MODEL, D_MODEL);
    gemm_mma<<<gg, 128>>>(xh, wvh, wvl, v, vh, nullptr, M, D_MODEL, D_MODEL);

    dim3 gattn(S / 64, NUM_HEADS, B);   // (32, 16, 2)
    attn_mma<<<gattn, 128>>>(qh, kh, vh, v, xsa, oh, S);

    gemm_mma<<<gg, 128>>>(oh, woh, wol, (float*)d_out, nullptr, nullptr,
                          M, D_MODEL, D_MODEL);
}

// round 13
// speedup vs baseline: 1.9672x; 1.1277x over previous
#include <cuda_runtime.h>
#include <cuda_fp16.h>
#include <math.h>
#include <stdint.h>

#define D_MODEL   1024
#define NUM_HEADS 16
#define HEAD_DIM  64
#define NTOK      4096
// (1/sqrt(64)) * log2(e)
#define C_SCALE   0.18033688011112042f

// ---------------- static scratch (allocation-free rule) ----------------
__device__ float g_v[NTOK * D_MODEL];

__device__ __half g_xh[NTOK * D_MODEL];
__device__ __half g_qh[NTOK * D_MODEL];
__device__ __half g_kh[NTOK * D_MODEL];
__device__ __half g_vh[NTOK * D_MODEL];
__device__ __half g_oh[NTOK * D_MODEL];
__device__ __half g_wqh[D_MODEL * D_MODEL];
__device__ __half g_wkh[D_MODEL * D_MODEL];
__device__ __half g_wvh[D_MODEL * D_MODEL];
__device__ __half g_wvl[D_MODEL * D_MODEL];
__device__ __half g_woh[D_MODEL * D_MODEL];
__device__ __half g_wol[D_MODEL * D_MODEL];

// ---------------- helpers ----------------
__device__ __forceinline__ uint32_t smem_u32(const void* p) {
    uint32_t a;
    asm("{ .reg .u64 t; cvta.to.shared.u64 t, %1; cvt.u32.u64 %0, t; }"
        : "=r"(a) : "l"(p));
    return a;
}

__device__ __forceinline__ void ldsm_x4(uint32_t* r, uint32_t addr) {
    asm volatile("ldmatrix.sync.aligned.m8n8.x4.shared.b16 {%0,%1,%2,%3}, [%4];"
                 : "=r"(r[0]), "=r"(r[1]), "=r"(r[2]), "=r"(r[3]) : "r"(addr));
}
__device__ __forceinline__ void ldsm_x4t(uint32_t* r, uint32_t addr) {
    asm volatile("ldmatrix.sync.aligned.m8n8.x4.trans.shared.b16 {%0,%1,%2,%3}, [%4];"
                 : "=r"(r[0]), "=r"(r[1]), "=r"(r[2]), "=r"(r[3]) : "r"(addr));
}
__device__ __forceinline__ void mma_f16(float* d, const uint32_t* a, const uint32_t* b) {
    asm volatile(
        "mma.sync.aligned.m16n8k16.row.col.f32.f16.f16.f32 "
        "{%0,%1,%2,%3}, {%4,%5,%6,%7}, {%8,%9}, {%0,%1,%2,%3};"
        : "+f"(d[0]), "+f"(d[1]), "+f"(d[2]), "+f"(d[3])
        : "r"(a[0]), "r"(a[1]), "r"(a[2]), "r"(a[3]), "r"(b[0]), "r"(b[1]));
}

#define CP_ASYNC16(dst, src) \
    asm volatile("cp.async.cg.shared.global [%0], [%1], 16;" :: "r"(dst), "l"(src))
#define CP_COMMIT asm volatile("cp.async.commit_group;" ::: "memory")
template <int N>
__device__ __forceinline__ void cp_wait() {
    asm volatile("cp.async.wait_group %0;" :: "n"(N) : "memory");
}

__device__ __forceinline__ uint32_t pack_f16x2(float lo, float hi) {
    __half2 t = __floats2half2_rn(lo, hi);   // .x = lo (low 16 bits)
    return *(uint32_t*)&t;
}
__device__ __forceinline__ float f16lo(uint32_t p) {
    return __half2float(__ushort_as_half((unsigned short)(p & 0xffffu)));
}
__device__ __forceinline__ float f16hi(uint32_t p) {
    return __half2float(__ushort_as_half((unsigned short)(p >> 16)));
}

// fast 2^t on FMA pipe (t <= 0 expected), rel err < 2e-5
__device__ __forceinline__ float exp2_fast(float t) {
    t = fmaxf(t, -126.0f);
    float fn = floorf(t);
    float f = t - fn;
    float p = fmaf(f, 0.000154035f, 0.0013333558f);
    p = fmaf(f, p, 0.0096181291f);
    p = fmaf(f, p, 0.0555041087f);
    p = fmaf(f, p, 0.2402265070f);
    p = fmaf(f, p, 0.6931471806f);
    p = fmaf(f, p, 1.0f);
    int n = (int)fn;
    return p * __int_as_float((n + 127) << 23);
}

// ---------------------------------------------------------------------------
// fp32 -> fp16 conversions
// ---------------------------------------------------------------------------
__global__ void tofp16(const float* __restrict__ x, __half* __restrict__ h, int n) {
    int i = (blockIdx.x * blockDim.x + threadIdx.x) * 4;
    if (i >= n) return;
    float4 v = *(const float4*)(x + i);
    __half2* hp = (__half2*)(h + i);
    hp[0] = __floats2half2_rn(v.x, v.y);
    hp[1] = __floats2half2_rn(v.z, v.w);
}

// hi-only for 2 matrices (Wq, Wk) in one launch
__global__ void tofp16_w2(const float* w0, const float* w1,
                          __half* h0, __half* h1, int n) {
    const float* w[2] = {w0, w1};
    __half* h[2] = {h0, h1};
    int m = blockIdx.y;
    int i = (blockIdx.x * blockDim.x + threadIdx.x) * 4;
    if (i >= n) return;
    float4 v = *(const float4*)(w[m] + i);
    __half2* hp = (__half2*)(h[m] + i);
    hp[0] = __floats2half2_rn(v.x, v.y);
    hp[1] = __floats2half2_rn(v.z, v.w);
}

// hi/lo split for 2 matrices (Wv, Wo) in one launch
__global__ void split_f16_w2(const float* w0, const float* w1,
                             __half* h0, __half* l0, __half* h1, __half* l1, int n) {
    const float* w[2] = {w0, w1};
    __half* h[2] = {h0, h1};
    __half* l[2] = {l0, l1};
    int m = blockIdx.y;
    int i = (blockIdx.x * blockDim.x + threadIdx.x) * 4;
    if (i >= n) return;
    float4 v = *(const float4*)(w[m] + i);
    __half h0v = __float2half_rn(v.x);
    __half h1v = __float2half_rn(v.y);
    __half h2v = __float2half_rn(v.z);
    __half h3v = __float2half_rn(v.w);
    __half2* hp = (__half2*)(h[m] + i);
    __half2* lp = (__half2*)(l[m] + i);
    hp[0] = __half2(h0v, h1v); hp[1] = __half2(h2v, h3v);
    lp[0] = __half2(__float2half_rn(v.x - __half2float(h0v)),
                    __float2half_rn(v.y - __half2float(h1v)));
    lp[1] = __half2(__float2half_rn(v.z - __half2float(h2v)),
                    __float2half_rn(v.w - __half2float(h3v)));
}

// ---------------------------------------------------------------------------
// HMMA fp16 GEMM, templated passes:
//   TWO_PASS=true : C = A*(Bh+Bl)^T
//   TWO_PASS=false: C = A*Bh^T  (Bl unused)
// 64x128 tile, 128 thr, 4 CTAs/SM.
// ---------------------------------------------------------------------------
#define GROWH   40
#define GA_T    (64 * GROWH * 2)
#define GB_T    (128 * GROWH * 2)

template <bool TWO_PASS>
__global__ __launch_bounds__(128, 4)
void gemm_mma(const __half* __restrict__ A,
              const __half* __restrict__ Bh, const __half* __restrict__ Bl,
              float* __restrict__ C, __half* __restrict__ Ch,
              int M, int N, int K) {
    __shared__ __align__(16) char smem[GA_T + 2 * GB_T];
    const uint32_t sb = smem_u32(smem);
    const int tid = threadIdx.x;
    const int lane = tid & 31;
    const int wid = tid >> 5;
    const int m0 = blockIdx.y * 64;
    const int n0 = blockIdx.x * 128;

    const __half* aP = A + (size_t)m0 * K;
    const __half* bH = Bh + (size_t)n0 * K;
    const __half* bL = TWO_PASS ? Bl + (size_t)n0 * K : nullptr;

    float acc[4][4][4];
#pragma unroll
    for (int a = 0; a < 4; a++)
#pragma unroll
        for (int b = 0; b < 4; b++)
#pragma unroll
            for (int c = 0; c < 4; c++) acc[a][b][c] = 0.f;

    const int NCH = K / 32;

    for (int kc = 0; kc < NCH; kc++) {
        int koff = kc * 32;
#pragma unroll
        for (int i = 0; i < 2; i++) {
            int seg = tid + i * 128;
            int row = seg >> 2;
            int cs = seg & 3;
            size_t g = (size_t)row * K + koff + cs * 8;
            uint32_t d = (row * GROWH + cs * 8) * 2;
            CP_ASYNC16(sb + d, aP + g);
        }
#pragma unroll
        for (int i = 0; i < 4; i++) {
            int seg = tid + i * 128;
            int row = seg >> 2;
            int cs = seg & 3;
            size_t g = (size_t)row * K + koff + cs * 8;
            uint32_t d = GA_T + (row * GROWH + cs * 8) * 2;
            CP_ASYNC16(sb + d, bH + g);
            if (TWO_PASS) CP_ASYNC16(sb + d + GB_T, bL + g);
        }
        CP_COMMIT;
        cp_wait<0>();
        __syncthreads();

#pragma unroll
        for (int kk = 0; kk < 32; kk += 16) {
            uint32_t ah[4][4];
#pragma unroll
            for (int mt = 0; mt < 4; mt++) {
                uint32_t ar = sb + ((mt * 16 + (lane & 15)) * GROWH
                                    + kk + (lane >> 4) * 8) * 2;
                ldsm_x4(ah[mt], ar);
            }
#pragma unroll
            for (int npp = 0; npp < 2; npp++) {
                uint32_t br = sb + GA_T
                            + ((wid * 32 + npp * 16 + ((lane >> 4) << 3) + (lane & 7)) * GROWH
                               + kk + ((lane >> 3) & 1) * 8) * 2;
                uint32_t bh[4], bl[4];
                ldsm_x4(bh, br);
                if (TWO_PASS) ldsm_x4(bl, br + GB_T);
#pragma unroll
                for (int mt = 0; mt < 4; mt++) {
                    mma_f16(acc[mt][2 * npp],     ah[mt], bh);
                    if (TWO_PASS) mma_f16(acc[mt][2 * npp], ah[mt], bl);
                    mma_f16(acc[mt][2 * npp + 1], ah[mt], bh + 2);
                    if (TWO_PASS) mma_f16(acc[mt][2 * npp + 1], ah[mt], bl + 2);
                }
            }
        }
        __syncthreads();
    }

#pragma unroll
    for (int mt = 0; mt < 4; mt++) {
#pragma unroll
        for (int nt = 0; nt < 4; nt++) {
            int r0 = m0 + mt * 16 + (lane >> 2);
            int col = n0 + wid * 32 + nt * 8 + (lane & 3) * 2;
            float d0 = acc[mt][nt][0], d1 = acc[mt][nt][1];
            float d2 = acc[mt][nt][2], d3 = acc[mt][nt][3];
            if (C) {
                float2 v0 = {d0, d1}, v1 = {d2, d3};
                *(float2*)&C[(size_t)r0 * N + col] = v0;
                *(float2*)&C[(size_t)(r0 + 8) * N + col] = v1;
            }
            if (Ch) {
                *(uint32_t*)&Ch[(size_t)r0 * N + col] = pack_f16x2(d0, d1);
                *(uint32_t*)&Ch[(size_t)(r0 + 8) * N + col] = pack_f16x2(d2, d3);
            }
        }
    }
}

// ---------------------------------------------------------------------------
// HMMA flash attention, fp16 single-pass MMAs (unchanged from R12 — known good)
// ---------------------------------------------------------------------------
__global__ __launch_bounds__(128)
void attn_mma(const __half* __restrict__ Qh_,
              const __half* __restrict__ Kh_, const __half* __restrict__ Vh_,
              const float* __restrict__ Vf, const float* __restrict__ xsa,
              __half* __restrict__ Oh, int S) {
    __shared__ __align__(16) uint16_t sK[64 * 72];
    __shared__ __align__(16) uint16_t sV[64 * 72];

    const int tid = threadIdx.x;
    const int lane = tid & 31;
    const int wid = tid >> 5;
    const int h = blockIdx.y;
    const int b = blockIdx.z;
    const int q0 = blockIdx.x * 64;
    const int tok0 = b * S;
    const int hoff = h * HEAD_DIM;

    const uint32_t aK = smem_u32(sK), aV = smem_u32(sV);

#pragma unroll
    for (int i = 0; i < 4; i++) {
        int seg = tid + i * 128;
        int row = seg >> 3;
        int cs = seg & 7;
        const void* sh = Qh_ + (size_t)(tok0 + q0 + row) * D_MODEL + hoff + cs * 8;
        CP_ASYNC16(aK + (row * 72 + cs * 8) * 2, sh);
    }
    CP_COMMIT;
    cp_wait<0>();
    __syncthreads();

    uint32_t qh[4][4];
#pragma unroll
    for (int kt = 0; kt < 4; kt++) {
        uint32_t off = ((wid * 16 + (lane & 15)) * 72 + kt * 16 + (lane >> 4) * 8) * 2;
        ldsm_x4(qh[kt], aK + off);
    }
    __syncthreads();

    float acc_o[8][4];
#pragma unroll
    for (int i = 0; i < 8; i++)
#pragma unroll
        for (int j = 0; j < 4; j++) acc_o[i][j] = 0.f;
    float mA = -1e30f, mB = -1e30f, lA = 0.f, lB = 0.f;

    for (int c0 = 0; c0 < S; c0 += 64) {
#pragma unroll
        for (int i = 0; i < 4; i++) {
            int seg = tid + i * 128;
            int row = seg >> 3;
            int cs = seg & 7;
            size_t g = (size_t)(tok0 + c0 + row) * D_MODEL + hoff + cs * 8;
            uint32_t d = (row * 72 + cs * 8) * 2;
            CP_ASYNC16(aK + d, Kh_ + g);
            CP_ASYNC16(aV + d, Vh_ + g);
        }
        CP_COMMIT;
        cp_wait<0>();
        __syncthreads();

        float s[8][4];
#pragma unroll
        for (int i = 0; i < 8; i++)
#pragma unroll
            for (int j = 0; j < 4; j++) s[i][j] = 0.f;

#pragma unroll
        for (int kt = 0; kt < 4; kt++) {
#pragma unroll
            for (int np = 0; np < 4; np++) {
                uint32_t off = ((np * 16 + ((lane >> 4) << 3) + (lane & 7)) * 72
                                + kt * 16 + ((lane >> 3) & 1) * 8) * 2;
                uint32_t bh[4];
                ldsm_x4(bh, aK + off);
                mma_f16(s[2 * np],     qh[kt], bh);
                mma_f16(s[2 * np + 1], qh[kt], bh + 2);
            }
        }

        float mxA = -1e30f, mxB = -1e30f;
#pragma unroll
        for (int nt = 0; nt < 8; nt++) {
            s[nt][0] *= C_SCALE; s[nt][1] *= C_SCALE;
            s[nt][2] *= C_SCALE; s[nt][3] *= C_SCALE;
            mxA = fmaxf(mxA, fmaxf(s[nt][0], s[nt][1]));
            mxB = fmaxf(mxB, fmaxf(s[nt][2], s[nt][3]));
        }
        mxA = fmaxf(mxA, __shfl_xor_sync(0xffffffffu, mxA, 1));
        mxA = fmaxf(mxA, __shfl_xor_sync(0xffffffffu, mxA, 2));
        mxB = fmaxf(mxB, __shfl_xor_sync(0xffffffffu, mxB, 1));
        mxB = fmaxf(mxB, __shfl_xor_sync(0xffffffffu, mxB, 2));
        float mAn = fmaxf(mA, mxA);
        float mBn = fmaxf(mB, mxB);
        float facA = exp2_fast(mA - mAn);
        float facB = exp2_fast(mB - mBn);
        float sumA = 0.f, sumB = 0.f;
#pragma unroll
        for (int nt = 0; nt < 8; nt++) {
            s[nt][0] = exp2_fast(s[nt][0] - mAn);
            s[nt][1] = exp2_fast(s[nt][1] - mAn);
            s[nt][2] = exp2_fast(s[nt][2] - mBn);
            s[nt][3] = exp2_fast(s[nt][3] - mBn);
            sumA += s[nt][0] + s[nt][1];
            sumB += s[nt][2] + s[nt][3];
        }
        sumA += __shfl_xor_sync(0xffffffffu, sumA, 1);
        sumA += __shfl_xor_sync(0xffffffffu, sumA, 2);
        sumB += __shfl_xor_sync(0xffffffffu, sumB, 1);
        sumB += __shfl_xor_sync(0xffffffffu, sumB, 2);
        lA = lA * facA + sumA;
        lB = lB * facB + sumB;
        mA = mAn; mB = mBn;
#pragma unroll
        for (int dn = 0; dn < 8; dn++) {
            acc_o[dn][0] *= facA; acc_o[dn][1] *= facA;
            acc_o[dn][2] *= facB; acc_o[dn][3] *= facB;
        }

#pragma unroll
        for (int kt = 0; kt < 4; kt++) {
            uint32_t Ph[4];
            Ph[0] = pack_f16x2(s[2 * kt][0], s[2 * kt][1]);
            Ph[1] = pack_f16x2(s[2 * kt][2], s[2 * kt][3]);
            Ph[2] = pack_f16x2(s[2 * kt + 1][0], s[2 * kt + 1][1]);
            Ph[3] = pack_f16x2(s[2 * kt + 1][2], s[2 * kt + 1][3]);
#pragma unroll
            for (int dp = 0; dp < 4; dp++) {
                uint32_t off = ((kt * 16 + ((lane >> 3) & 1) * 8 + (lane & 7)) * 72
                                + dp * 16 + (lane >> 4) * 8) * 2;
                uint32_t vh[4];
                ldsm_x4t(vh, aV + off);
                mma_f16(acc_o[2 * dp],     Ph, vh);
                mma_f16(acc_o[2 * dp + 1], Ph, vh + 2);
            }
        }
        __syncthreads();
    }

    float invA = 1.0f / lA, invB = 1.0f / lB;
    float xs = xsa[0];
    int rowA = tok0 + q0 + wid * 16 + (lane >> 2);
    int rowB = rowA + 8;
    float dotA = 0.f, vnA = 0.f, dotB = 0.f, vnB = 0.f;
#pragma unroll
    for (int dn = 0; dn < 8; dn++) {
        int col = hoff + dn * 8 + (lane & 3) * 2;
        float2 va = *(const float2*)&Vf[(size_t)rowA * D_MODEL + col];
        float2 vb = *(const float2*)&Vf[(size_t)rowB * D_MODEL + col];
        float o0 = acc_o[dn][0] * invA, o1 = acc_o[dn][1] * invA;
        float o2 = acc_o[dn][2] * invB, o3 = acc_o[dn][3] * invB;
        acc_o[dn][0] = o0; acc_o[dn][1] = o1;
        acc_o[dn][2] = o2; acc_o[dn][3] = o3;
        dotA += o0 * va.x + o1 * va.y;
        vnA  += va.x * va.x + va.y * va.y;
        dotB += o2 * vb.x + o3 * vb.y;
        vnB  += vb.x * vb.x + vb.y * vb.y;
    }
    dotA += __shfl_xor_sync(0xffffffffu, dotA, 1);
    dotA += __shfl_xor_sync(0xffffffffu, dotA, 2);
    vnA  += __shfl_xor_sync(0xffffffffu, vnA, 1);
    vnA  += __shfl_xor_sync(0xffffffffu, vnA, 2);
    dotB += __shfl_xor_sync(0xffffffffu, dotB, 1);
    dotB += __shfl_xor_sync(0xffffffffu, dotB, 2);
    vnB  += __shfl_xor_sync(0xffffffffu, vnB, 1);
    vnB  += __shfl_xor_sync(0xffffffffu, vnB, 2);
    float scA = xs * dotA / (vnA + 1e-8f);
    float scB = xs * dotB / (vnB + 1e-8f);
#pragma unroll
    for (int dn = 0; dn < 8; dn++) {
        int col = hoff + dn * 8 + (lane & 3) * 2;
        float2 va = *(const float2*)&Vf[(size_t)rowA * D_MODEL + col];
        float2 vb = *(const float2*)&Vf[(size_t)rowB * D_MODEL + col];
        uint32_t pa = pack_f16x2(acc_o[dn][0] - scA * va.x,
                                 acc_o[dn][1] - scA * va.y);
        uint32_t pb = pack_f16x2(acc_o[dn][2] - scB * vb.x,
                                 acc_o[dn][3] - scB * vb.y);
        *(uint32_t*)&Oh[(size_t)rowA * D_MODEL + col] = pa;
        *(uint32_t*)&Oh[(size_t)rowB * D_MODEL + col] = pb;
    }
}

// ---------------------------------------------------------------------------
// Launch
// ---------------------------------------------------------------------------
extern "C" void kernel_launch(void* const* d_in, const int* in_sizes, int n_in,
                              void* d_out, int out_size) {
    const float* x   = (const float*)d_in[0];
    const float* Wq  = (const float*)d_in[1];
    const float* Wk  = (const float*)d_in[2];
    const float* Wv  = (const float*)d_in[3];
    const float* Wo  = (const float*)d_in[4];
    const float* xsa = (const float*)d_in[5];

    const int M = in_sizes[0] / D_MODEL;   // 4096
    const int B = 2;
    const int S = M / B;                   // 2048

    float* v;
    cudaGetSymbolAddress((void**)&v, g_v);

    __half *xh, *qh, *kh, *vh, *oh;
    __half *wqh, *wkh, *wvh, *wvl, *woh, *wol;
    cudaGetSymbolAddress((void**)&xh, g_xh);
    cudaGetSymbolAddress((void**)&qh, g_qh);
    cudaGetSymbolAddress((void**)&kh, g_kh);
    cudaGetSymbolAddress((void**)&vh, g_vh);
    cudaGetSymbolAddress((void**)&oh, g_oh);
    cudaGetSymbolAddress((void**)&wqh, g_wqh);
    cudaGetSymbolAddress((void**)&wkh, g_wkh);
    cudaGetSymbolAddress((void**)&wvh, g_wvh);
    cudaGetSymbolAddress((void**)&wvl, g_wvl);
    cudaGetSymbolAddress((void**)&woh, g_woh);
    cudaGetSymbolAddress((void**)&wol, g_wol);

    const int nx = M * D_MODEL;
    const int nw = D_MODEL * D_MODEL;

    tofp16<<<nx / 1024, 256>>>(x, xh, nx);
    dim3 gw2(nw / 1024, 2);
    tofp16_w2<<<gw2, 256>>>(Wq, Wk, wqh, wkh, nw);
    split_f16_w2<<<gw2, 256>>>(Wv, Wo, wvh, wvl, woh, wol, nw);

    dim3 gg(D_MODEL / 128, M / 64);   // (8, 64) = 512 CTAs
    gemm_mma<false><<<gg, 128>>>(xh, wqh, nullptr, nullptr, qh, M, D_MODEL, D_MODEL);
    gemm_mma<false><<<gg, 128>>>(xh, wkh, nullptr, nullptr, kh, M, D_MODEL, D_MODEL);
    gemm_mma<true><<<gg, 128>>>(xh, wvh, wvl, v, vh, M, D_MODEL, D_MODEL);

    dim3 gattn(S / 64, NUM_HEADS, B);   // (32, 16, 2)
    attn_mma<<<gattn, 128>>>(qh, kh, vh, v, xsa, oh, S);

    gemm_mma<true><<<gg, 128>>>(oh, woh, wol, (float*)d_out, nullptr, M, D_MODEL, D_MODEL);
}

// round 14
// speedup vs baseline: 2.1819x; 1.1091x over previous
#include <cuda_runtime.h>
#include <cuda_fp16.h>
#include <math.h>
#include <stdint.h>

#define D_MODEL   1024
#define NUM_HEADS 16
#define HEAD_DIM  64
#define NTOK      4096
// (1/sqrt(64)) * log2(e)
#define C_SCALE   0.18033688011112042f

// ---------------- static scratch (allocation-free rule) ----------------
__device__ float g_v[NTOK * D_MODEL];

__device__ __half g_xh[NTOK * D_MODEL];
__device__ __half g_qh[NTOK * D_MODEL];
__device__ __half g_kh[NTOK * D_MODEL];
__device__ __half g_vh[NTOK * D_MODEL];
__device__ __half g_oh[NTOK * D_MODEL];
__device__ __half g_wqh[D_MODEL * D_MODEL];
__device__ __half g_wkh[D_MODEL * D_MODEL];
__device__ __half g_wvh[D_MODEL * D_MODEL];
__device__ __half g_wvl[D_MODEL * D_MODEL];
__device__ __half g_woh[D_MODEL * D_MODEL];

// ---------------- helpers ----------------
__device__ __forceinline__ uint32_t smem_u32(const void* p) {
    uint32_t a;
    asm("{ .reg .u64 t; cvta.to.shared.u64 t, %1; cvt.u32.u64 %0, t; }"
        : "=r"(a) : "l"(p));
    return a;
}

__device__ __forceinline__ void ldsm_x4(uint32_t* r, uint32_t addr) {
    asm volatile("ldmatrix.sync.aligned.m8n8.x4.shared.b16 {%0,%1,%2,%3}, [%4];"
                 : "=r"(r[0]), "=r"(r[1]), "=r"(r[2]), "=r"(r[3]) : "r"(addr));
}
__device__ __forceinline__ void ldsm_x4t(uint32_t* r, uint32_t addr) {
    asm volatile("ldmatrix.sync.aligned.m8n8.x4.trans.shared.b16 {%0,%1,%2,%3}, [%4];"
                 : "=r"(r[0]), "=r"(r[1]), "=r"(r[2]), "=r"(r[3]) : "r"(addr));
}
__device__ __forceinline__ void mma_f16(float* d, const uint32_t* a, const uint32_t* b) {
    asm volatile(
        "mma.sync.aligned.m16n8k16.row.col.f32.f16.f16.f32 "
        "{%0,%1,%2,%3}, {%4,%5,%6,%7}, {%8,%9}, {%0,%1,%2,%3};"
        : "+f"(d[0]), "+f"(d[1]), "+f"(d[2]), "+f"(d[3])
        : "r"(a[0]), "r"(a[1]), "r"(a[2]), "r"(a[3]), "r"(b[0]), "r"(b[1]));
}

#define CP_ASYNC16(dst, src) \
    asm volatile("cp.async.cg.shared.global [%0], [%1], 16;" :: "r"(dst), "l"(src))
#define CP_COMMIT asm volatile("cp.async.commit_group;" ::: "memory")
template <int N>
__device__ __forceinline__ void cp_wait() {
    asm volatile("cp.async.wait_group %0;" :: "n"(N) : "memory");
}

__device__ __forceinline__ uint32_t pack_f16x2(float lo, float hi) {
    __half2 t = __floats2half2_rn(lo, hi);   // .x = lo (low 16 bits)
    return *(uint32_t*)&t;
}

// fast 2^t on FMA pipe (t <= 0 expected), rel err < 2e-5
__device__ __forceinline__ float exp2_fast(float t) {
    t = fmaxf(t, -126.0f);
    float fn = floorf(t);
    float f = t - fn;
    float p = fmaf(f, 0.000154035f, 0.0013333558f);
    p = fmaf(f, p, 0.0096181291f);
    p = fmaf(f, p, 0.0555041087f);
    p = fmaf(f, p, 0.2402265070f);
    p = fmaf(f, p, 0.6931471806f);
    p = fmaf(f, p, 1.0f);
    int n = (int)fn;
    return p * __int_as_float((n + 127) << 23);
}

// ---------------------------------------------------------------------------
// Fused conversion kernel: block ranges map to tasks.
//   blocks [0, 4096):      x  -> xh       (hi only, 4M elems)
//   blocks [4096, 5120):   Wq -> wqh      (1M)
//   blocks [5120, 6144):   Wk -> wkh      (1M)
//   blocks [6144, 7168):   Wo -> woh      (1M)
//   blocks [7168, 8192):   Wv -> wvh,wvl  (split, 1M)
// 256 threads, 4 fp32 per thread.
// ---------------------------------------------------------------------------
__global__ void convert_all(const float* __restrict__ x,
                            const float* __restrict__ Wq, const float* __restrict__ Wk,
                            const float* __restrict__ Wv, const float* __restrict__ Wo,
                            __half* __restrict__ xh, __half* __restrict__ wqh,
                            __half* __restrict__ wkh, __half* __restrict__ wvh,
                            __half* __restrict__ wvl, __half* __restrict__ woh) {
    int blk = blockIdx.x;
    const float* src;
    __half* dst;
    bool split = false;
    if (blk < 4096)      { src = x;  dst = xh;  }
    else if (blk < 5120) { src = Wq; dst = wqh; blk -= 4096; }
    else if (blk < 6144) { src = Wk; dst = wkh; blk -= 5120; }
    else if (blk < 7168) { src = Wo; dst = woh; blk -= 6144; }
    else                 { src = Wv; dst = wvh; blk -= 7168; split = true; }

    int i = (blk * 256 + threadIdx.x) * 4;
    float4 v = *(const float4*)(src + i);
    __half h0 = __float2half_rn(v.x);
    __half h1 = __float2half_rn(v.y);
    __half h2 = __float2half_rn(v.z);
    __half h3 = __float2half_rn(v.w);
    __half2* hp = (__half2*)(dst + i);
    hp[0] = __half2(h0, h1);
    hp[1] = __half2(h2, h3);
    if (split) {
        __half2* lp = (__half2*)(wvl + i);
        lp[0] = __half2(__float2half_rn(v.x - __half2float(h0)),
                        __float2half_rn(v.y - __half2float(h1)));
        lp[1] = __half2(__float2half_rn(v.z - __half2float(h2)),
                        __float2half_rn(v.w - __half2float(h3)));
    }
}

// ---------------------------------------------------------------------------
// HMMA fp16 GEMM, templated passes (64x128 tile, 128 thr, 4 CTAs/SM):
//   TWO_PASS=true : C = A*(Bh+Bl)^T
//   TWO_PASS=false: C = A*Bh^T
// ---------------------------------------------------------------------------
#define GROWH   40
#define GA_T    (64 * GROWH * 2)
#define GB_T    (128 * GROWH * 2)

template <bool TWO_PASS>
__device__ __forceinline__ void gemm_body(const __half* aP, const __half* bH,
                                          const __half* bL, float* C, __half* Ch,
                                          int m0, int n0, int N, int K,
                                          uint32_t sb, char* smem_raw) {
    const int tid = threadIdx.x;
    const int lane = tid & 31;
    const int wid = tid >> 5;

    float acc[4][4][4];
#pragma unroll
    for (int a = 0; a < 4; a++)
#pragma unroll
        for (int b = 0; b < 4; b++)
#pragma unroll
            for (int c = 0; c < 4; c++) acc[a][b][c] = 0.f;

    const int NCH = K / 32;

    for (int kc = 0; kc < NCH; kc++) {
        int koff = kc * 32;
#pragma unroll
        for (int i = 0; i < 2; i++) {
            int seg = tid + i * 128;
            int row = seg >> 2;
            int cs = seg & 3;
            size_t g = (size_t)row * K + koff + cs * 8;
            uint32_t d = (row * GROWH + cs * 8) * 2;
            CP_ASYNC16(sb + d, aP + g);
        }
#pragma unroll
        for (int i = 0; i < 4; i++) {
            int seg = tid + i * 128;
            int row = seg >> 2;
            int cs = seg & 3;
            size_t g = (size_t)row * K + koff + cs * 8;
            uint32_t d = GA_T + (row * GROWH + cs * 8) * 2;
            CP_ASYNC16(sb + d, bH + g);
            if (TWO_PASS) CP_ASYNC16(sb + d + GB_T, bL + g);
        }
        CP_COMMIT;
        cp_wait<0>();
        __syncthreads();

#pragma unroll
        for (int kk = 0; kk < 32; kk += 16) {
            uint32_t ah[4][4];
#pragma unroll
            for (int mt = 0; mt < 4; mt++) {
                uint32_t ar = sb + ((mt * 16 + (lane & 15)) * GROWH
                                    + kk + (lane >> 4) * 8) * 2;
                ldsm_x4(ah[mt], ar);
            }
#pragma unroll
            for (int npp = 0; npp < 2; npp++) {
                uint32_t br = sb + GA_T
                            + ((wid * 32 + npp * 16 + ((lane >> 4) << 3) + (lane & 7)) * GROWH
                               + kk + ((lane >> 3) & 1) * 8) * 2;
                uint32_t bh[4], bl[4];
                ldsm_x4(bh, br);
                if (TWO_PASS) ldsm_x4(bl, br + GB_T);
#pragma unroll
                for (int mt = 0; mt < 4; mt++) {
                    mma_f16(acc[mt][2 * npp],     ah[mt], bh);
                    if (TWO_PASS) mma_f16(acc[mt][2 * npp], ah[mt], bl);
                    mma_f16(acc[mt][2 * npp + 1], ah[mt], bh + 2);
                    if (TWO_PASS) mma_f16(acc[mt][2 * npp + 1], ah[mt], bl + 2);
                }
            }
        }
        __syncthreads();
    }

#pragma unroll
    for (int mt = 0; mt < 4; mt++) {
#pragma unroll
        for (int nt = 0; nt < 4; nt++) {
            int r0 = m0 + mt * 16 + (lane >> 2);
            int col = n0 + wid * 32 + nt * 8 + (lane & 3) * 2;
            float d0 = acc[mt][nt][0], d1 = acc[mt][nt][1];
            float d2 = acc[mt][nt][2], d3 = acc[mt][nt][3];
            if (C) {
                float2 v0 = {d0, d1}, v1 = {d2, d3};
                *(float2*)&C[(size_t)r0 * N + col] = v0;
                *(float2*)&C[(size_t)(r0 + 8) * N + col] = v1;
            }
            if (Ch) {
                *(uint32_t*)&Ch[(size_t)r0 * N + col] = pack_f16x2(d0, d1);
                *(uint32_t*)&Ch[(size_t)(r0 + 8) * N + col] = pack_f16x2(d2, d3);
            }
        }
    }
}

template <bool TWO_PASS>
__global__ __launch_bounds__(128, 4)
void gemm_mma(const __half* __restrict__ A,
              const __half* __restrict__ Bh, const __half* __restrict__ Bl,
              float* __restrict__ C, __half* __restrict__ Ch,
              int M, int N, int K) {
    __shared__ __align__(16) char smem[GA_T + 2 * GB_T];
    gemm_body<TWO_PASS>(A + (size_t)blockIdx.y * 64 * K,
                        Bh + (size_t)blockIdx.x * 128 * K,
                        TWO_PASS ? Bl + (size_t)blockIdx.x * 128 * K : nullptr,
                        C, Ch, blockIdx.y * 64, blockIdx.x * 128, N, K,
                        smem_u32(smem), smem);
}

// Fused Q+K projection: blockIdx.x in [0,8) -> Wq/qh, [8,16) -> Wk/kh. 1-pass.
__global__ __launch_bounds__(128, 4)
void gemm_qk(const __half* __restrict__ A,
             const __half* __restrict__ Bq, const __half* __restrict__ Bk,
             __half* __restrict__ Cq, __half* __restrict__ Ck,
             int M, int N, int K) {
    __shared__ __align__(16) char smem[GA_T + 2 * GB_T];
    const bool isK = blockIdx.x >= 8;
    const __half* Bh = isK ? Bk : Bq;
    __half* Ch = isK ? Ck : Cq;
    const int nb = blockIdx.x & 7;
    gemm_body<false>(A + (size_t)blockIdx.y * 64 * K,
                     Bh + (size_t)nb * 128 * K, nullptr,
                     nullptr, Ch, blockIdx.y * 64, nb * 128, N, K,
                     smem_u32(smem), smem);
}

// ---------------------------------------------------------------------------
// HMMA flash attention (unchanged from R13 — known good)
// ---------------------------------------------------------------------------
__global__ __launch_bounds__(128)
void attn_mma(const __half* __restrict__ Qh_,
              const __half* __restrict__ Kh_, const __half* __restrict__ Vh_,
              const float* __restrict__ Vf, const float* __restrict__ xsa,
              __half* __restrict__ Oh, int S) {
    __shared__ __align__(16) uint16_t sK[64 * 72];
    __shared__ __align__(16) uint16_t sV[64 * 72];

    const int tid = threadIdx.x;
    const int lane = tid & 31;
    const int wid = tid >> 5;
    const int h = blockIdx.y;
    const int b = blockIdx.z;
    const int q0 = blockIdx.x * 64;
    const int tok0 = b * S;
    const int hoff = h * HEAD_DIM;

    const uint32_t aK = smem_u32(sK), aV = smem_u32(sV);

#pragma unroll
    for (int i = 0; i < 4; i++) {
        int seg = tid + i * 128;
        int row = seg >> 3;
        int cs = seg & 7;
        const void* sh = Qh_ + (size_t)(tok0 + q0 + row) * D_MODEL + hoff + cs * 8;
        CP_ASYNC16(aK + (row * 72 + cs * 8) * 2, sh);
    }
    CP_COMMIT;
    cp_wait<0>();
    __syncthreads();

    uint32_t qh[4][4];
#pragma unroll
    for (int kt = 0; kt < 4; kt++) {
        uint32_t off = ((wid * 16 + (lane & 15)) * 72 + kt * 16 + (lane >> 4) * 8) * 2;
        ldsm_x4(qh[kt], aK + off);
    }
    __syncthreads();

    float acc_o[8][4];
#pragma unroll
    for (int i = 0; i < 8; i++)
#pragma unroll
        for (int j = 0; j < 4; j++) acc_o[i][j] = 0.f;
    float mA = -1e30f, mB = -1e30f, lA = 0.f, lB = 0.f;

    for (int c0 = 0; c0 < S; c0 += 64) {
#pragma unroll
        for (int i = 0; i < 4; i++) {
            int seg = tid + i * 128;
            int row = seg >> 3;
            int cs = seg & 7;
            size_t g = (size_t)(tok0 + c0 + row) * D_MODEL + hoff + cs * 8;
            uint32_t d = (row * 72 + cs * 8) * 2;
            CP_ASYNC16(aK + d, Kh_ + g);
            CP_ASYNC16(aV + d, Vh_ + g);
        }
        CP_COMMIT;
        cp_wait<0>();
        __syncthreads();

        float s[8][4];
#pragma unroll
        for (int i = 0; i < 8; i++)
#pragma unroll
            for (int j = 0; j < 4; j++) s[i][j] = 0.f;

#pragma unroll
        for (int kt = 0; kt < 4; kt++) {
#pragma unroll
            for (int np = 0; np < 4; np++) {
                uint32_t off = ((np * 16 + ((lane >> 4) << 3) + (lane & 7)) * 72
                                + kt * 16 + ((lane >> 3) & 1) * 8) * 2;
                uint32_t bh[4];
                ldsm_x4(bh, aK + off);
                mma_f16(s[2 * np],     qh[kt], bh);
                mma_f16(s[2 * np + 1], qh[kt], bh + 2);
            }
        }

        float mxA = -1e30f, mxB = -1e30f;
#pragma unroll
        for (int nt = 0; nt < 8; nt++) {
            s[nt][0] *= C_SCALE; s[nt][1] *= C_SCALE;
            s[nt][2] *= C_SCALE; s[nt][3] *= C_SCALE;
            mxA = fmaxf(mxA, fmaxf(s[nt][0], s[nt][1]));
            mxB = fmaxf(mxB, fmaxf(s[nt][2], s[nt][3]));
        }
        mxA = fmaxf(mxA, __shfl_xor_sync(0xffffffffu, mxA, 1));
        mxA = fmaxf(mxA, __shfl_xor_sync(0xffffffffu, mxA, 2));
        mxB = fmaxf(mxB, __shfl_xor_sync(0xffffffffu, mxB, 1));
        mxB = fmaxf(mxB, __shfl_xor_sync(0xffffffffu, mxB, 2));
        float mAn = fmaxf(mA, mxA);
        float mBn = fmaxf(mB, mxB);
        float facA = exp2_fast(mA - mAn);
        float facB = exp2_fast(mB - mBn);
        float sumA = 0.f, sumB = 0.f;
#pragma unroll
        for (int nt = 0; nt < 8; nt++) {
            s[nt][0] = exp2_fast(s[nt][0] - mAn);
            s[nt][1] = exp2_fast(s[nt][1] - mAn);
            s[nt][2] = exp2_fast(s[nt][2] - mBn);
            s[nt][3] = exp2_fast(s[nt][3] - mBn);
            sumA += s[nt][0] + s[nt][1];
            sumB += s[nt][2] + s[nt][3];
        }
        sumA += __shfl_xor_sync(0xffffffffu, sumA, 1);
        sumA += __shfl_xor_sync(0xffffffffu, sumA, 2);
        sumB += __shfl_xor_sync(0xffffffffu, sumB, 1);
        sumB += __shfl_xor_sync(0xffffffffu, sumB, 2);
        lA = lA * facA + sumA;
        lB = lB * facB + sumB;
        mA = mAn; mB = mBn;
#pragma unroll
        for (int dn = 0; dn < 8; dn++) {
            acc_o[dn][0] *= facA; acc_o[dn][1] *= facA;
            acc_o[dn][2] *= facB; acc_o[dn][3] *= facB;
        }

#pragma unroll
        for (int kt = 0; kt < 4; kt++) {
            uint32_t Ph[4];
            Ph[0] = pack_f16x2(s[2 * kt][0], s[2 * kt][1]);
            Ph[1] = pack_f16x2(s[2 * kt][2], s[2 * kt][3]);
            Ph[2] = pack_f16x2(s[2 * kt + 1][0], s[2 * kt + 1][1]);
            Ph[3] = pack_f16x2(s[2 * kt + 1][2], s[2 * kt + 1][3]);
#pragma unroll
            for (int dp = 0; dp < 4; dp++) {
                uint32_t off = ((kt * 16 + ((lane >> 3) & 1) * 8 + (lane & 7)) * 72
                                + dp * 16 + (lane >> 4) * 8) * 2;
                uint32_t vh[4];
                ldsm_x4t(vh, aV + off);
                mma_f16(acc_o[2 * dp],     Ph, vh);
                mma_f16(acc_o[2 * dp + 1], Ph, vh + 2);
            }
        }
        __syncthreads();
    }

    float invA = 1.0f / lA, invB = 1.0f / lB;
    float xs = xsa[0];
    int rowA = tok0 + q0 + wid * 16 + (lane >> 2);
    int rowB = rowA + 8;
    float dotA = 0.f, vnA = 0.f, dotB = 0.f, vnB = 0.f;
#pragma unroll
    for (int dn = 0; dn < 8; dn++) {
        int col = hoff + dn * 8 + (lane & 3) * 2;
        float2 va = *(const float2*)&Vf[(size_t)rowA * D_MODEL + col];
        float2 vb = *(const float2*)&Vf[(size_t)rowB * D_MODEL + col];
        float o0 = acc_o[dn][0] * invA, o1 = acc_o[dn][1] * invA;
        float o2 = acc_o[dn][2] * invB, o3 = acc_o[dn][3] * invB;
        acc_o[dn][0] = o0; acc_o[dn][1] = o1;
        acc_o[dn][2] = o2; acc_o[dn][3] = o3;
        dotA += o0 * va.x + o1 * va.y;
        vnA  += va.x * va.x + va.y * va.y;
        dotB += o2 * vb.x + o3 * vb.y;
        vnB  += vb.x * vb.x + vb.y * vb.y;
    }
    dotA += __shfl_xor_sync(0xffffffffu, dotA, 1);
    dotA += __shfl_xor_sync(0xffffffffu, dotA, 2);
    vnA  += __shfl_xor_sync(0xffffffffu, vnA, 1);
    vnA  += __shfl_xor_sync(0xffffffffu, vnA, 2);
    dotB += __shfl_xor_sync(0xffffffffu, dotB, 1);
    dotB += __shfl_xor_sync(0xffffffffu, dotB, 2);
    vnB  += __shfl_xor_sync(0xffffffffu, vnB, 1);
    vnB  += __shfl_xor_sync(0xffffffffu, vnB, 2);
    float scA = xs * dotA / (vnA + 1e-8f);
    float scB = xs * dotB / (vnB + 1e-8f);
#pragma unroll
    for (int dn = 0; dn < 8; dn++) {
        int col = hoff + dn * 8 + (lane & 3) * 2;
        float2 va = *(const float2*)&Vf[(size_t)rowA * D_MODEL + col];
        float2 vb = *(const float2*)&Vf[(size_t)rowB * D_MODEL + col];
        uint32_t pa = pack_f16x2(acc_o[dn][0] - scA * va.x,
                                 acc_o[dn][1] - scA * va.y);
        uint32_t pb = pack_f16x2(acc_o[dn][2] - scB * vb.x,
                                 acc_o[dn][3] - scB * vb.y);
        *(uint32_t*)&Oh[(size_t)rowA * D_MODEL + col] = pa;
        *(uint32_t*)&Oh[(size_t)rowB * D_MODEL + col] = pb;
    }
}

// ---------------------------------------------------------------------------
// Launch
// ---------------------------------------------------------------------------
extern "C" void kernel_launch(void* const* d_in, const int* in_sizes, int n_in,
                              void* d_out, int out_size) {
    const float* x   = (const float*)d_in[0];
    const float* Wq  = (const float*)d_in[1];
    const float* Wk  = (const float*)d_in[2];
    const float* Wv  = (const float*)d_in[3];
    const float* Wo  = (const float*)d_in[4];
    const float* xsa = (const float*)d_in[5];

    const int M = in_sizes[0] / D_MODEL;   // 4096
    const int B = 2;
    const int S = M / B;                   // 2048

    float* v;
    cudaGetSymbolAddress((void**)&v, g_v);

    __half *xh, *qh, *kh, *vh, *oh;
    __half *wqh, *wkh, *wvh, *wvl, *woh;
    cudaGetSymbolAddress((void**)&xh, g_xh);
    cudaGetSymbolAddress((void**)&qh, g_qh);
    cudaGetSymbolAddress((void**)&kh, g_kh);
    cudaGetSymbolAddress((void**)&vh, g_vh);
    cudaGetSymbolAddress((void**)&oh, g_oh);
    cudaGetSymbolAddress((void**)&wqh, g_wqh);
    cudaGetSymbolAddress((void**)&wkh, g_wkh);
    cudaGetSymbolAddress((void**)&wvh, g_wvh);
    cudaGetSymbolAddress((void**)&wvl, g_wvl);
    cudaGetSymbolAddress((void**)&woh, g_woh);

    // one fused conversion launch: 4096 (x) + 4*1024 (weights) = 8192 blocks
    convert_all<<<8192, 256>>>(x, Wq, Wk, Wv, Wo, xh, wqh, wkh, wvh, wvl, woh);

    dim3 gqk(16, M / 64);   // Q and K projections in one launch (1024 CTAs)
    gemm_qk<<<gqk, 128>>>(xh, wqh, wkh, qh, kh, M, D_MODEL, D_MODEL);

    dim3 gg(D_MODEL / 128, M / 64);   // (8, 64) = 512 CTAs
    gemm_mma<true><<<gg, 128>>>(xh, wvh, wvl, v, vh, M, D_MODEL, D_MODEL);

    dim3 gattn(S / 64, NUM_HEADS, B);   // (32, 16, 2)
    attn_mma<<<gattn, 128>>>(qh, kh, vh, v, xsa, oh, S);

    gemm_mma<false><<<gg, 128>>>(oh, woh, nullptr, (float*)d_out, nullptr,
                                 M, D_MODEL, D_MODEL);
}

// round 15
// speedup vs baseline: 2.2754x; 1.0429x over previous
#include <cuda_runtime.h>
#include <cuda_fp16.h>
#include <math.h>
#include <stdint.h>

#define D_MODEL   1024
#define NUM_HEADS 16
#define HEAD_DIM  64
#define NTOK      4096
// (1/sqrt(64)) * log2(e)
#define C_SCALE   0.18033688011112042f

// ---------------- static scratch (allocation-free rule) ----------------
__device__ float g_v[NTOK * D_MODEL];

__device__ __half g_xh[NTOK * D_MODEL];
__device__ __half g_qh[NTOK * D_MODEL];
__device__ __half g_kh[NTOK * D_MODEL];
__device__ __half g_vh[NTOK * D_MODEL];
__device__ __half g_oh[NTOK * D_MODEL];
__device__ __half g_wqh[D_MODEL * D_MODEL];
__device__ __half g_wkh[D_MODEL * D_MODEL];
__device__ __half g_wvh[D_MODEL * D_MODEL];
__device__ __half g_wvl[D_MODEL * D_MODEL];
__device__ __half g_woh[D_MODEL * D_MODEL];

// ---------------- helpers ----------------
__device__ __forceinline__ uint32_t smem_u32(const void* p) {
    uint32_t a;
    asm("{ .reg .u64 t; cvta.to.shared.u64 t, %1; cvt.u32.u64 %0, t; }"
        : "=r"(a) : "l"(p));
    return a;
}

__device__ __forceinline__ void ldsm_x4(uint32_t* r, uint32_t addr) {
    asm volatile("ldmatrix.sync.aligned.m8n8.x4.shared.b16 {%0,%1,%2,%3}, [%4];"
                 : "=r"(r[0]), "=r"(r[1]), "=r"(r[2]), "=r"(r[3]) : "r"(addr));
}
__device__ __forceinline__ void ldsm_x4t(uint32_t* r, uint32_t addr) {
    asm volatile("ldmatrix.sync.aligned.m8n8.x4.trans.shared.b16 {%0,%1,%2,%3}, [%4];"
                 : "=r"(r[0]), "=r"(r[1]), "=r"(r[2]), "=r"(r[3]) : "r"(addr));
}
__device__ __forceinline__ void mma_f16(float* d, const uint32_t* a, const uint32_t* b) {
    asm volatile(
        "mma.sync.aligned.m16n8k16.row.col.f32.f16.f16.f32 "
        "{%0,%1,%2,%3}, {%4,%5,%6,%7}, {%8,%9}, {%0,%1,%2,%3};"
        : "+f"(d[0]), "+f"(d[1]), "+f"(d[2]), "+f"(d[3])
        : "r"(a[0]), "r"(a[1]), "r"(a[2]), "r"(a[3]), "r"(b[0]), "r"(b[1]));
}

#define CP_ASYNC16(dst, src) \
    asm volatile("cp.async.cg.shared.global [%0], [%1], 16;" :: "r"(dst), "l"(src))
#define CP_COMMIT asm volatile("cp.async.commit_group;" ::: "memory")
template <int N>
__device__ __forceinline__ void cp_wait() {
    asm volatile("cp.async.wait_group %0;" :: "n"(N) : "memory");
}

__device__ __forceinline__ uint32_t pack_f16x2(float lo, float hi) {
    __half2 t = __floats2half2_rn(lo, hi);   // .x = lo (low 16 bits)
    return *(uint32_t*)&t;
}

// fast 2^t on the fma/alu pipes only (no cvt): magic-constant rounding +
// degree-4 poly on [-0.5, 0.5]; rel err < 5e-5.
__device__ __forceinline__ float exp2_fast(float t) {
    t = fmaxf(t, -126.0f);
    float z = t + 12582912.0f;                 // 2^23 * 1.5: round-to-nearest
    int n = __float_as_int(z);                 // low bits = round(t)
    float f = t - (z - 12582912.0f);           // f in [-0.5, 0.5]
    float p = fmaf(f, 0.0096181291f, 0.0555041087f);
    p = fmaf(f, p, 0.2402265070f);
    p = fmaf(f, p, 0.6931471806f);
    p = fmaf(f, p, 1.0f);
    return p * __int_as_float((n << 23) + 0x3f800000);
}

// ---------------------------------------------------------------------------
// Fused conversion kernel (unchanged from R14)
// ---------------------------------------------------------------------------
__global__ void convert_all(const float* __restrict__ x,
                            const float* __restrict__ Wq, const float* __restrict__ Wk,
                            const float* __restrict__ Wv, const float* __restrict__ Wo,
                            __half* __restrict__ xh, __half* __restrict__ wqh,
                            __half* __restrict__ wkh, __half* __restrict__ wvh,
                            __half* __restrict__ wvl, __half* __restrict__ woh) {
    int blk = blockIdx.x;
    const float* src;
    __half* dst;
    bool split = false;
    if (blk < 4096)      { src = x;  dst = xh;  }
    else if (blk < 5120) { src = Wq; dst = wqh; blk -= 4096; }
    else if (blk < 6144) { src = Wk; dst = wkh; blk -= 5120; }
    else if (blk < 7168) { src = Wo; dst = woh; blk -= 6144; }
    else                 { src = Wv; dst = wvh; blk -= 7168; split = true; }

    int i = (blk * 256 + threadIdx.x) * 4;
    float4 v = *(const float4*)(src + i);
    __half h0 = __float2half_rn(v.x);
    __half h1 = __float2half_rn(v.y);
    __half h2 = __float2half_rn(v.z);
    __half h3 = __float2half_rn(v.w);
    __half2* hp = (__half2*)(dst + i);
    hp[0] = __half2(h0, h1);
    hp[1] = __half2(h2, h3);
    if (split) {
        __half2* lp = (__half2*)(wvl + i);
        lp[0] = __half2(__float2half_rn(v.x - __half2float(h0)),
                        __float2half_rn(v.y - __half2float(h1)));
        lp[1] = __half2(__float2half_rn(v.z - __half2float(h2)),
                        __float2half_rn(v.w - __half2float(h3)));
    }
}

// ---------------------------------------------------------------------------
// HMMA fp16 GEMM body with output scale (for pre-scaling Q by C_SCALE).
// ---------------------------------------------------------------------------
#define GROWH   40
#define GA_T    (64 * GROWH * 2)
#define GB_T    (128 * GROWH * 2)

template <bool TWO_PASS>
__device__ __forceinline__ void gemm_body(const __half* aP, const __half* bH,
                                          const __half* bL, float* C, __half* Ch,
                                          float oscale, int m0, int n0, int N, int K,
                                          uint32_t sb) {
    const int tid = threadIdx.x;
    const int lane = tid & 31;
    const int wid = tid >> 5;

    float acc[4][4][4];
#pragma unroll
    for (int a = 0; a < 4; a++)
#pragma unroll
        for (int b = 0; b < 4; b++)
#pragma unroll
            for (int c = 0; c < 4; c++) acc[a][b][c] = 0.f;

    const int NCH = K / 32;

    for (int kc = 0; kc < NCH; kc++) {
        int koff = kc * 32;
#pragma unroll
        for (int i = 0; i < 2; i++) {
            int seg = tid + i * 128;
            int row = seg >> 2;
            int cs = seg & 3;
            size_t g = (size_t)row * K + koff + cs * 8;
            uint32_t d = (row * GROWH + cs * 8) * 2;
            CP_ASYNC16(sb + d, aP + g);
        }
#pragma unroll
        for (int i = 0; i < 4; i++) {
            int seg = tid + i * 128;
            int row = seg >> 2;
            int cs = seg & 3;
            size_t g = (size_t)row * K + koff + cs * 8;
            uint32_t d = GA_T + (row * GROWH + cs * 8) * 2;
            CP_ASYNC16(sb + d, bH + g);
            if (TWO_PASS) CP_ASYNC16(sb + d + GB_T, bL + g);
        }
        CP_COMMIT;
        cp_wait<0>();
        __syncthreads();

#pragma unroll
        for (int kk = 0; kk < 32; kk += 16) {
            uint32_t ah[4][4];
#pragma unroll
            for (int mt = 0; mt < 4; mt++) {
                uint32_t ar = sb + ((mt * 16 + (lane & 15)) * GROWH
                                    + kk + (lane >> 4) * 8) * 2;
                ldsm_x4(ah[mt], ar);
            }
#pragma unroll
            for (int npp = 0; npp < 2; npp++) {
                uint32_t br = sb + GA_T
                            + ((wid * 32 + npp * 16 + ((lane >> 4) << 3) + (lane & 7)) * GROWH
                               + kk + ((lane >> 3) & 1) * 8) * 2;
                uint32_t bh[4], bl[4];
                ldsm_x4(bh, br);
                if (TWO_PASS) ldsm_x4(bl, br + GB_T);
#pragma unroll
                for (int mt = 0; mt < 4; mt++) {
                    mma_f16(acc[mt][2 * npp],     ah[mt], bh);
                    if (TWO_PASS) mma_f16(acc[mt][2 * npp], ah[mt], bl);
                    mma_f16(acc[mt][2 * npp + 1], ah[mt], bh + 2);
                    if (TWO_PASS) mma_f16(acc[mt][2 * npp + 1], ah[mt], bl + 2);
                }
            }
        }
        __syncthreads();
    }

#pragma unroll
    for (int mt = 0; mt < 4; mt++) {
#pragma unroll
        for (int nt = 0; nt < 4; nt++) {
            int r0 = m0 + mt * 16 + (lane >> 2);
            int col = n0 + wid * 32 + nt * 8 + (lane & 3) * 2;
            float d0 = acc[mt][nt][0], d1 = acc[mt][nt][1];
            float d2 = acc[mt][nt][2], d3 = acc[mt][nt][3];
            if (C) {
                float2 v0 = {d0, d1}, v1 = {d2, d3};
                *(float2*)&C[(size_t)r0 * N + col] = v0;
                *(float2*)&C[(size_t)(r0 + 8) * N + col] = v1;
            }
            if (Ch) {
                *(uint32_t*)&Ch[(size_t)r0 * N + col] =
                    pack_f16x2(d0 * oscale, d1 * oscale);
                *(uint32_t*)&Ch[(size_t)(r0 + 8) * N + col] =
                    pack_f16x2(d2 * oscale, d3 * oscale);
            }
        }
    }
}

template <bool TWO_PASS>
__global__ __launch_bounds__(128, 4)
void gemm_mma(const __half* __restrict__ A,
              const __half* __restrict__ Bh, const __half* __restrict__ Bl,
              float* __restrict__ C, __half* __restrict__ Ch,
              int M, int N, int K) {
    __shared__ __align__(16) char smem[GA_T + 2 * GB_T];
    gemm_body<TWO_PASS>(A + (size_t)blockIdx.y * 64 * K,
                        Bh + (size_t)blockIdx.x * 128 * K,
                        TWO_PASS ? Bl + (size_t)blockIdx.x * 128 * K : nullptr,
                        C, Ch, 1.0f, blockIdx.y * 64, blockIdx.x * 128, N, K,
                        smem_u32(smem));
}

// Fused Q+K projection. Q output pre-scaled by C_SCALE (folds the softmax
// scale into the MMA operand; exact up to fp16 quantization).
__global__ __launch_bounds__(128, 4)
void gemm_qk(const __half* __restrict__ A,
             const __half* __restrict__ Bq, const __half* __restrict__ Bk,
             __half* __restrict__ Cq, __half* __restrict__ Ck,
             int M, int N, int K) {
    __shared__ __align__(16) char smem[GA_T + 2 * GB_T];
    const bool isK = blockIdx.x >= 8;
    const __half* Bh = isK ? Bk : Bq;
    __half* Ch = isK ? Ck : Cq;
    const float os = isK ? 1.0f : C_SCALE;
    const int nb = blockIdx.x & 7;
    gemm_body<false>(A + (size_t)blockIdx.y * 64 * K,
                     Bh + (size_t)nb * 128 * K, nullptr,
                     nullptr, Ch, os, blockIdx.y * 64, nb * 128, N, K,
                     smem_u32(smem));
}

// ---------------------------------------------------------------------------
// HMMA flash attention. Scores arrive pre-scaled (Q carries C_SCALE), so the
// softmax loop has no scale multiplies; exp2 is the cvt-free fast version.
// ---------------------------------------------------------------------------
__global__ __launch_bounds__(128)
void attn_mma(const __half* __restrict__ Qh_,
              const __half* __restrict__ Kh_, const __half* __restrict__ Vh_,
              const float* __restrict__ Vf, const float* __restrict__ xsa,
              __half* __restrict__ Oh, int S) {
    __shared__ __align__(16) uint16_t sK[64 * 72];
    __shared__ __align__(16) uint16_t sV[64 * 72];

    const int tid = threadIdx.x;
    const int lane = tid & 31;
    const int wid = tid >> 5;
    const int h = blockIdx.y;
    const int b = blockIdx.z;
    const int q0 = blockIdx.x * 64;
    const int tok0 = b * S;
    const int hoff = h * HEAD_DIM;

    const uint32_t aK = smem_u32(sK), aV = smem_u32(sV);

#pragma unroll
    for (int i = 0; i < 4; i++) {
        int seg = tid + i * 128;
        int row = seg >> 3;
        int cs = seg & 7;
        const void* sh = Qh_ + (size_t)(tok0 + q0 + row) * D_MODEL + hoff + cs * 8;
        CP_ASYNC16(aK + (row * 72 + cs * 8) * 2, sh);
    }
    CP_COMMIT;
    cp_wait<0>();
    __syncthreads();

    uint32_t qh[4][4];
#pragma unroll
    for (int kt = 0; kt < 4; kt++) {
        uint32_t off = ((wid * 16 + (lane & 15)) * 72 + kt * 16 + (lane >> 4) * 8) * 2;
        ldsm_x4(qh[kt], aK + off);
    }
    __syncthreads();

    float acc_o[8][4];
#pragma unroll
    for (int i = 0; i < 8; i++)
#pragma unroll
        for (int j = 0; j < 4; j++) acc_o[i][j] = 0.f;
    float mA = -1e30f, mB = -1e30f, lA = 0.f, lB = 0.f;

    for (int c0 = 0; c0 < S; c0 += 64) {
#pragma unroll
        for (int i = 0; i < 4; i++) {
            int seg = tid + i * 128;
            int row = seg >> 3;
            int cs = seg & 7;
            size_t g = (size_t)(tok0 + c0 + row) * D_MODEL + hoff + cs * 8;
            uint32_t d = (row * 72 + cs * 8) * 2;
            CP_ASYNC16(aK + d, Kh_ + g);
            CP_ASYNC16(aV + d, Vh_ + g);
        }
        CP_COMMIT;
        cp_wait<0>();
        __syncthreads();

        float s[8][4];
#pragma unroll
        for (int i = 0; i < 8; i++)
#pragma unroll
            for (int j = 0; j < 4; j++) s[i][j] = 0.f;

#pragma unroll
        for (int kt = 0; kt < 4; kt++) {
#pragma unroll
            for (int np = 0; np < 4; np++) {
                uint32_t off = ((np * 16 + ((lane >> 4) << 3) + (lane & 7)) * 72
                                + kt * 16 + ((lane >> 3) & 1) * 8) * 2;
                uint32_t bh[4];
                ldsm_x4(bh, aK + off);
                mma_f16(s[2 * np],     qh[kt], bh);
                mma_f16(s[2 * np + 1], qh[kt], bh + 2);
            }
        }

        float mxA = -1e30f, mxB = -1e30f;
#pragma unroll
        for (int nt = 0; nt < 8; nt++) {
            mxA = fmaxf(mxA, fmaxf(s[nt][0], s[nt][1]));
            mxB = fmaxf(mxB, fmaxf(s[nt][2], s[nt][3]));
        }
        mxA = fmaxf(mxA, __shfl_xor_sync(0xffffffffu, mxA, 1));
        mxA = fmaxf(mxA, __shfl_xor_sync(0xffffffffu, mxA, 2));
        mxB = fmaxf(mxB, __shfl_xor_sync(0xffffffffu, mxB, 1));
        mxB = fmaxf(mxB, __shfl_xor_sync(0xffffffffu, mxB, 2));
        float mAn = fmaxf(mA, mxA);
        float mBn = fmaxf(mB, mxB);
        float facA = exp2_fast(mA - mAn);
        float facB = exp2_fast(mB - mBn);
        float sumA = 0.f, sumB = 0.f;
#pragma unroll
        for (int nt = 0; nt < 8; nt++) {
            s[nt][0] = exp2_fast(s[nt][0] - mAn);
            s[nt][1] = exp2_fast(s[nt][1] - mAn);
            s[nt][2] = exp2_fast(s[nt][2] - mBn);
            s[nt][3] = exp2_fast(s[nt][3] - mBn);
            sumA += s[nt][0] + s[nt][1];
            sumB += s[nt][2] + s[nt][3];
        }
        sumA += __shfl_xor_sync(0xffffffffu, sumA, 1);
        sumA += __shfl_xor_sync(0xffffffffu, sumA, 2);
        sumB += __shfl_xor_sync(0xffffffffu, sumB, 1);
        sumB += __shfl_xor_sync(0xffffffffu, sumB, 2);
        lA = lA * facA + sumA;
        lB = lB * facB + sumB;
        mA = mAn; mB = mBn;
#pragma unroll
        for (int dn = 0; dn < 8; dn++) {
            acc_o[dn][0] *= facA; acc_o[dn][1] *= facA;
            acc_o[dn][2] *= facB; acc_o[dn][3] *= facB;
        }

#pragma unroll
        for (int kt = 0; kt < 4; kt++) {
            uint32_t Ph[4];
            Ph[0] = pack_f16x2(s[2 * kt][0], s[2 * kt][1]);
            Ph[1] = pack_f16x2(s[2 * kt][2], s[2 * kt][3]);
            Ph[2] = pack_f16x2(s[2 * kt + 1][0], s[2 * kt + 1][1]);
            Ph[3] = pack_f16x2(s[2 * kt + 1][2], s[2 * kt + 1][3]);
#pragma unroll
            for (int dp = 0; dp < 4; dp++) {
                uint32_t off = ((kt * 16 + ((lane >> 3) & 1) * 8 + (lane & 7)) * 72
                                + dp * 16 + (lane >> 4) * 8) * 2;
                uint32_t vh[4];
                ldsm_x4t(vh, aV + off);
                mma_f16(acc_o[2 * dp],     Ph, vh);
                mma_f16(acc_o[2 * dp + 1], Ph, vh + 2);
            }
        }
        __syncthreads();
    }

    float invA = 1.0f / lA, invB = 1.0f / lB;
    float xs = xsa[0];
    int rowA = tok0 + q0 + wid * 16 + (lane >> 2);
    int rowB = rowA + 8;
    float dotA = 0.f, vnA = 0.f, dotB = 0.f, vnB = 0.f;
#pragma unroll
    for (int dn = 0; dn < 8; dn++) {
        int col = hoff + dn * 8 + (lane & 3) * 2;
        float2 va = *(const float2*)&Vf[(size_t)rowA * D_MODEL + col];
        float2 vb = *(const float2*)&Vf[(size_t)rowB * D_MODEL + col];
        float o0 = acc_o[dn][0] * invA, o1 = acc_o[dn][1] * invA;
        float o2 = acc_o[dn][2] * invB, o3 = acc_o[dn][3] * invB;
        acc_o[dn][0] = o0; acc_o[dn][1] = o1;
        acc_o[dn][2] = o2; acc_o[dn][3] = o3;
        dotA += o0 * va.x + o1 * va.y;
        vnA  += va.x * va.x + va.y * va.y;
        dotB += o2 * vb.x + o3 * vb.y;
        vnB  += vb.x * vb.x + vb.y * vb.y;
    }
    dotA += __shfl_xor_sync(0xffffffffu, dotA, 1);
    dotA += __shfl_xor_sync(0xffffffffu, dotA, 2);
    vnA  += __shfl_xor_sync(0xffffffffu, vnA, 1);
    vnA  += __shfl_xor_sync(0xffffffffu, vnA, 2);
    dotB += __shfl_xor_sync(0xffffffffu, dotB, 1);
    dotB += __shfl_xor_sync(0xffffffffu, dotB, 2);
    vnB  += __shfl_xor_sync(0xffffffffu, vnB, 1);
    vnB  += __shfl_xor_sync(0xffffffffu, vnB, 2);
    float scA = xs * dotA / (vnA + 1e-8f);
    float scB = xs * dotB / (vnB + 1e-8f);
#pragma unroll
    for (int dn = 0; dn < 8; dn++) {
        int col = hoff + dn * 8 + (lane & 3) * 2;
        float2 va = *(const float2*)&Vf[(size_t)rowA * D_MODEL + col];
        float2 vb = *(const float2*)&Vf[(size_t)rowB * D_MODEL + col];
        uint32_t pa = pack_f16x2(acc_o[dn][0] - scA * va.x,
                                 acc_o[dn][1] - scA * va.y);
        uint32_t pb = pack_f16x2(acc_o[dn][2] - scB * vb.x,
                                 acc_o[dn][3] - scB * vb.y);
        *(uint32_t*)&Oh[(size_t)rowA * D_MODEL + col] = pa;
        *(uint32_t*)&Oh[(size_t)rowB * D_MODEL + col] = pb;
    }
}

// ---------------------------------------------------------------------------
// Launch
// ---------------------------------------------------------------------------
extern "C" void kernel_launch(void* const* d_in, const int* in_sizes, int n_in,
                              void* d_out, int out_size) {
    const float* x   = (const float*)d_in[0];
    const float* Wq  = (const float*)d_in[1];
    const float* Wk  = (const float*)d_in[2];
    const float* Wv  = (const float*)d_in[3];
    const float* Wo  = (const float*)d_in[4];
    const float* xsa = (const float*)d_in[5];

    const int M = in_sizes[0] / D_MODEL;   // 4096
    const int B = 2;
    const int S = M / B;                   // 2048

    float* v;
    cudaGetSymbolAddress((void**)&v, g_v);

    __half *xh, *qh, *kh, *vh, *oh;
    __half *wqh, *wkh, *wvh, *wvl, *woh;
    cudaGetSymbolAddress((void**)&xh, g_xh);
    cudaGetSymbolAddress((void**)&qh, g_qh);
    cudaGetSymbolAddress((void**)&kh, g_kh);
    cudaGetSymbolAddress((void**)&vh, g_vh);
    cudaGetSymbolAddress((void**)&oh, g_oh);
    cudaGetSymbolAddress((void**)&wqh, g_wqh);
    cudaGetSymbolAddress((void**)&wkh, g_wkh);
    cudaGetSymbolAddress((void**)&wvh, g_wvh);
    cudaGetSymbolAddress((void**)&wvl, g_wvl);
    cudaGetSymbolAddress((void**)&woh, g_woh);

    convert_all<<<8192, 256>>>(x, Wq, Wk, Wv, Wo, xh, wqh, wkh, wvh, wvl, woh);

    dim3 gqk(16, M / 64);   // Q and K projections in one launch
    gemm_qk<<<gqk, 128>>>(xh, wqh, wkh, qh, kh, M, D_MODEL, D_MODEL);

    dim3 gg(D_MODEL / 128, M / 64);
    gemm_mma<true><<<gg, 128>>>(xh, wvh, wvl, v, vh, M, D_MODEL, D_MODEL);

    dim3 gattn(S / 64, NUM_HEADS, B);
    attn_mma<<<gattn, 128>>>(qh, kh, vh, v, xsa, oh, S);

    gemm_mma<false><<<gg, 128>>>(oh, woh, nullptr, (float*)d_out, nullptr,
                                 M, D_MODEL, D_MODEL);
}

// round 16
// speedup vs baseline: 2.4214x; 1.0641x over previous
#include <cuda_runtime.h>
#include <cuda_fp16.h>
#include <math.h>
#include <stdint.h>

#define D_MODEL   1024
#define NUM_HEADS 16
#define HEAD_DIM  64
#define NTOK      4096
// (1/sqrt(64)) * log2(e)
#define C_SCALE   0.18033688011112042f

// ---------------- static scratch (allocation-free rule) ----------------
__device__ float g_v[NTOK * D_MODEL];

__device__ __half g_xh[NTOK * D_MODEL];
__device__ __half g_qh[NTOK * D_MODEL];
__device__ __half g_kh[NTOK * D_MODEL];
__device__ __half g_vh[NTOK * D_MODEL];
__device__ __half g_oh[NTOK * D_MODEL];
__device__ __half g_wqh[D_MODEL * D_MODEL];
__device__ __half g_wkh[D_MODEL * D_MODEL];
__device__ __half g_wvh[D_MODEL * D_MODEL];
__device__ __half g_woh[D_MODEL * D_MODEL];

// ---------------- helpers ----------------
__device__ __forceinline__ uint32_t smem_u32(const void* p) {
    uint32_t a;
    asm("{ .reg .u64 t; cvta.to.shared.u64 t, %1; cvt.u32.u64 %0, t; }"
        : "=r"(a) : "l"(p));
    return a;
}

__device__ __forceinline__ void ldsm_x4(uint32_t* r, uint32_t addr) {
    asm volatile("ldmatrix.sync.aligned.m8n8.x4.shared.b16 {%0,%1,%2,%3}, [%4];"
                 : "=r"(r[0]), "=r"(r[1]), "=r"(r[2]), "=r"(r[3]) : "r"(addr));
}
__device__ __forceinline__ void ldsm_x4t(uint32_t* r, uint32_t addr) {
    asm volatile("ldmatrix.sync.aligned.m8n8.x4.trans.shared.b16 {%0,%1,%2,%3}, [%4];"
                 : "=r"(r[0]), "=r"(r[1]), "=r"(r[2]), "=r"(r[3]) : "r"(addr));
}
__device__ __forceinline__ void mma_f16(float* d, const uint32_t* a, const uint32_t* b) {
    asm volatile(
        "mma.sync.aligned.m16n8k16.row.col.f32.f16.f16.f32 "
        "{%0,%1,%2,%3}, {%4,%5,%6,%7}, {%8,%9}, {%0,%1,%2,%3};"
        : "+f"(d[0]), "+f"(d[1]), "+f"(d[2]), "+f"(d[3])
        : "r"(a[0]), "r"(a[1]), "r"(a[2]), "r"(a[3]), "r"(b[0]), "r"(b[1]));
}

#define CP_ASYNC16(dst, src) \
    asm volatile("cp.async.cg.shared.global [%0], [%1], 16;" :: "r"(dst), "l"(src))
#define CP_COMMIT asm volatile("cp.async.commit_group;" ::: "memory")
template <int N>
__device__ __forceinline__ void cp_wait() {
    asm volatile("cp.async.wait_group %0;" :: "n"(N) : "memory");
}

__device__ __forceinline__ uint32_t pack_f16x2(float lo, float hi) {
    __half2 t = __floats2half2_rn(lo, hi);   // .x = lo (low 16 bits)
    return *(uint32_t*)&t;
}

// fast 2^t on the fma/alu pipes only (no cvt): magic-constant rounding +
// degree-4 poly on [-0.5, 0.5]; rel err < 5e-5. exp2_fast(0) == 1.0 exactly.
__device__ __forceinline__ float exp2_fast(float t) {
    t = fmaxf(t, -126.0f);
    float z = t + 12582912.0f;                 // 2^23 * 1.5: round-to-nearest
    int n = __float_as_int(z);                 // low bits = round(t)
    float f = t - (z - 12582912.0f);           // f in [-0.5, 0.5]
    float p = fmaf(f, 0.0096181291f, 0.0555041087f);
    p = fmaf(f, p, 0.2402265070f);
    p = fmaf(f, p, 0.6931471806f);
    p = fmaf(f, p, 1.0f);
    return p * __int_as_float((n << 23) + 0x3f800000);
}

// ---------------------------------------------------------------------------
// Fused conversion kernel: all hi-only now.
//   blocks [0, 4096):      x  -> xh
//   blocks [4096, 5120):   Wq -> wqh
//   blocks [5120, 6144):   Wk -> wkh
//   blocks [6144, 7168):   Wo -> woh
//   blocks [7168, 8192):   Wv -> wvh
// ---------------------------------------------------------------------------
__global__ void convert_all(const float* __restrict__ x,
                            const float* __restrict__ Wq, const float* __restrict__ Wk,
                            const float* __restrict__ Wv, const float* __restrict__ Wo,
                            __half* __restrict__ xh, __half* __restrict__ wqh,
                            __half* __restrict__ wkh, __half* __restrict__ wvh,
                            __half* __restrict__ woh) {
    int blk = blockIdx.x;
    const float* src;
    __half* dst;
    if (blk < 4096)      { src = x;  dst = xh;  }
    else if (blk < 5120) { src = Wq; dst = wqh; blk -= 4096; }
    else if (blk < 6144) { src = Wk; dst = wkh; blk -= 5120; }
    else if (blk < 7168) { src = Wo; dst = woh; blk -= 6144; }
    else                 { src = Wv; dst = wvh; blk -= 7168; }

    int i = (blk * 256 + threadIdx.x) * 4;
    float4 v = *(const float4*)(src + i);
    __half2* hp = (__half2*)(dst + i);
    hp[0] = __floats2half2_rn(v.x, v.y);
    hp[1] = __floats2half2_rn(v.z, v.w);
}

// ---------------------------------------------------------------------------
// HMMA fp16 GEMM body (1-pass), output scale, optional fp32 C + fp16 Ch.
// 64x128 tile, 128 thr, 4 CTAs/SM.
// ---------------------------------------------------------------------------
#define GROWH   40
#define GA_T    (64 * GROWH * 2)
#define GB_T    (128 * GROWH * 2)

__device__ __forceinline__ void gemm_body(const __half* aP, const __half* bH,
                                          float* C, __half* Ch, float oscale,
                                          int m0, int n0, int N, int K,
                                          uint32_t sb) {
    const int tid = threadIdx.x;
    const int lane = tid & 31;
    const int wid = tid >> 5;

    float acc[4][4][4];
#pragma unroll
    for (int a = 0; a < 4; a++)
#pragma unroll
        for (int b = 0; b < 4; b++)
#pragma unroll
            for (int c = 0; c < 4; c++) acc[a][b][c] = 0.f;

    const int NCH = K / 32;

    for (int kc = 0; kc < NCH; kc++) {
        int koff = kc * 32;
#pragma unroll
        for (int i = 0; i < 2; i++) {
            int seg = tid + i * 128;
            int row = seg >> 2;
            int cs = seg & 3;
            size_t g = (size_t)row * K + koff + cs * 8;
            uint32_t d = (row * GROWH + cs * 8) * 2;
            CP_ASYNC16(sb + d, aP + g);
        }
#pragma unroll
        for (int i = 0; i < 4; i++) {
            int seg = tid + i * 128;
            int row = seg >> 2;
            int cs = seg & 3;
            size_t g = (size_t)row * K + koff + cs * 8;
            uint32_t d = GA_T + (row * GROWH + cs * 8) * 2;
            CP_ASYNC16(sb + d, bH + g);
        }
        CP_COMMIT;
        cp_wait<0>();
        __syncthreads();

#pragma unroll
        for (int kk = 0; kk < 32; kk += 16) {
            uint32_t ah[4][4];
#pragma unroll
            for (int mt = 0; mt < 4; mt++) {
                uint32_t ar = sb + ((mt * 16 + (lane & 15)) * GROWH
                                    + kk + (lane >> 4) * 8) * 2;
                ldsm_x4(ah[mt], ar);
            }
#pragma unroll
            for (int npp = 0; npp < 2; npp++) {
                uint32_t br = sb + GA_T
                            + ((wid * 32 + npp * 16 + ((lane >> 4) << 3) + (lane & 7)) * GROWH
                               + kk + ((lane >> 3) & 1) * 8) * 2;
                uint32_t bh[4];
                ldsm_x4(bh, br);
#pragma unroll
                for (int mt = 0; mt < 4; mt++) {
                    mma_f16(acc[mt][2 * npp],     ah[mt], bh);
                    mma_f16(acc[mt][2 * npp + 1], ah[mt], bh + 2);
                }
            }
        }
        __syncthreads();
    }

#pragma unroll
    for (int mt = 0; mt < 4; mt++) {
#pragma unroll
        for (int nt = 0; nt < 4; nt++) {
            int r0 = m0 + mt * 16 + (lane >> 2);
            int col = n0 + wid * 32 + nt * 8 + (lane & 3) * 2;
            float d0 = acc[mt][nt][0], d1 = acc[mt][nt][1];
            float d2 = acc[mt][nt][2], d3 = acc[mt][nt][3];
            if (C) {
                float2 v0 = {d0, d1}, v1 = {d2, d3};
                *(float2*)&C[(size_t)r0 * N + col] = v0;
                *(float2*)&C[(size_t)(r0 + 8) * N + col] = v1;
            }
            if (Ch) {
                *(uint32_t*)&Ch[(size_t)r0 * N + col] =
                    pack_f16x2(d0 * oscale, d1 * oscale);
                *(uint32_t*)&Ch[(size_t)(r0 + 8) * N + col] =
                    pack_f16x2(d2 * oscale, d3 * oscale);
            }
        }
    }
}

// All three projections in one launch. blockIdx.x ranges:
//   [0,8): Q (output pre-scaled by C_SCALE), [8,16): K, [16,24): V (+fp32 C)
__global__ __launch_bounds__(128, 4)
void gemm_qkv(const __half* __restrict__ A,
              const __half* __restrict__ Bq, const __half* __restrict__ Bk,
              const __half* __restrict__ Bv,
              __half* __restrict__ Cq, __half* __restrict__ Ck,
              __half* __restrict__ Cv, float* __restrict__ Vf,
              int M, int N, int K) {
    __shared__ __align__(16) char smem[GA_T + GB_T];
    const int sel = blockIdx.x >> 3;     // 0=Q, 1=K, 2=V
    const int nb = blockIdx.x & 7;
    const __half* Bh = (sel == 0) ? Bq : (sel == 1) ? Bk : Bv;
    __half* Ch = (sel == 0) ? Cq : (sel == 1) ? Ck : Cv;
    float* C = (sel == 2) ? Vf : nullptr;
    const float os = (sel == 0) ? C_SCALE : 1.0f;
    gemm_body(A + (size_t)blockIdx.y * 64 * K,
              Bh + (size_t)nb * 128 * K,
              C, Ch, os, blockIdx.y * 64, nb * 128, N, K, smem_u32(smem));
}

// Output projection (1-pass, fp32 out).
__global__ __launch_bounds__(128, 4)
void gemm_out(const __half* __restrict__ A, const __half* __restrict__ Bh,
              float* __restrict__ C, int M, int N, int K) {
    __shared__ __align__(16) char smem[GA_T + GB_T];
    gemm_body(A + (size_t)blockIdx.y * 64 * K,
              Bh + (size_t)blockIdx.x * 128 * K,
              C, nullptr, 1.0f, blockIdx.y * 64, blockIdx.x * 128, N, K,
              smem_u32(smem));
}

// ---------------------------------------------------------------------------
// HMMA flash attention. Scores pre-scaled via Q. Warp-vote skips the acc_o
// rescale + fac exp2s when the running max is unchanged (bit-exact skip).
// ---------------------------------------------------------------------------
__global__ __launch_bounds__(128)
void attn_mma(const __half* __restrict__ Qh_,
              const __half* __restrict__ Kh_, const __half* __restrict__ Vh_,
              const float* __restrict__ Vf, const float* __restrict__ xsa,
              __half* __restrict__ Oh, int S) {
    __shared__ __align__(16) uint16_t sK[64 * 72];
    __shared__ __align__(16) uint16_t sV[64 * 72];

    const int tid = threadIdx.x;
    const int lane = tid & 31;
    const int wid = tid >> 5;
    const int h = blockIdx.y;
    const int b = blockIdx.z;
    const int q0 = blockIdx.x * 64;
    const int tok0 = b * S;
    const int hoff = h * HEAD_DIM;

    const uint32_t aK = smem_u32(sK), aV = smem_u32(sV);

#pragma unroll
    for (int i = 0; i < 4; i++) {
        int seg = tid + i * 128;
        int row = seg >> 3;
        int cs = seg & 7;
        const void* sh = Qh_ + (size_t)(tok0 + q0 + row) * D_MODEL + hoff + cs * 8;
        CP_ASYNC16(aK + (row * 72 + cs * 8) * 2, sh);
    }
    CP_COMMIT;
    cp_wait<0>();
    __syncthreads();

    uint32_t qh[4][4];
#pragma unroll
    for (int kt = 0; kt < 4; kt++) {
        uint32_t off = ((wid * 16 + (lane & 15)) * 72 + kt * 16 + (lane >> 4) * 8) * 2;
        ldsm_x4(qh[kt], aK + off);
    }
    __syncthreads();

    float acc_o[8][4];
#pragma unroll
    for (int i = 0; i < 8; i++)
#pragma unroll
        for (int j = 0; j < 4; j++) acc_o[i][j] = 0.f;
    float mA = -1e30f, mB = -1e30f, lA = 0.f, lB = 0.f;

    for (int c0 = 0; c0 < S; c0 += 64) {
#pragma unroll
        for (int i = 0; i < 4; i++) {
            int seg = tid + i * 128;
            int row = seg >> 3;
            int cs = seg & 7;
            size_t g = (size_t)(tok0 + c0 + row) * D_MODEL + hoff + cs * 8;
            uint32_t d = (row * 72 + cs * 8) * 2;
            CP_ASYNC16(aK + d, Kh_ + g);
            CP_ASYNC16(aV + d, Vh_ + g);
        }
        CP_COMMIT;
        cp_wait<0>();
        __syncthreads();

        float s[8][4];
#pragma unroll
        for (int i = 0; i < 8; i++)
#pragma unroll
            for (int j = 0; j < 4; j++) s[i][j] = 0.f;

#pragma unroll
        for (int kt = 0; kt < 4; kt++) {
#pragma unroll
            for (int np = 0; np < 4; np++) {
                uint32_t off = ((np * 16 + ((lane >> 4) << 3) + (lane & 7)) * 72
                                + kt * 16 + ((lane >> 3) & 1) * 8) * 2;
                uint32_t bh[4];
                ldsm_x4(bh, aK + off);
                mma_f16(s[2 * np],     qh[kt], bh);
                mma_f16(s[2 * np + 1], qh[kt], bh + 2);
            }
        }

        float mxA = -1e30f, mxB = -1e30f;
#pragma unroll
        for (int nt = 0; nt < 8; nt++) {
            mxA = fmaxf(mxA, fmaxf(s[nt][0], s[nt][1]));
            mxB = fmaxf(mxB, fmaxf(s[nt][2], s[nt][3]));
        }
        mxA = fmaxf(mxA, __shfl_xor_sync(0xffffffffu, mxA, 1));
        mxA = fmaxf(mxA, __shfl_xor_sync(0xffffffffu, mxA, 2));
        mxB = fmaxf(mxB, __shfl_xor_sync(0xffffffffu, mxB, 1));
        mxB = fmaxf(mxB, __shfl_xor_sync(0xffffffffu, mxB, 2));
        float mAn = fmaxf(mA, mxA);
        float mBn = fmaxf(mB, mxB);

        float sumA = 0.f, sumB = 0.f;
#pragma unroll
        for (int nt = 0; nt < 8; nt++) {
            s[nt][0] = exp2_fast(s[nt][0] - mAn);
            s[nt][1] = exp2_fast(s[nt][1] - mAn);
            s[nt][2] = exp2_fast(s[nt][2] - mBn);
            s[nt][3] = exp2_fast(s[nt][3] - mBn);
            sumA += s[nt][0] + s[nt][1];
            sumB += s[nt][2] + s[nt][3];
        }
        sumA += __shfl_xor_sync(0xffffffffu, sumA, 1);
        sumA += __shfl_xor_sync(0xffffffffu, sumA, 2);
        sumB += __shfl_xor_sync(0xffffffffu, sumB, 1);
        sumB += __shfl_xor_sync(0xffffffffu, sumB, 2);

        // rescale only if any lane's max advanced (fac==1 exactly otherwise)
        if (!__all_sync(0xffffffffu, (mAn == mA) && (mBn == mB))) {
            float facA = exp2_fast(mA - mAn);
            float facB = exp2_fast(mB - mBn);
            lA *= facA;
            lB *= facB;
#pragma unroll
            for (int dn = 0; dn < 8; dn++) {
                acc_o[dn][0] *= facA; acc_o[dn][1] *= facA;
                acc_o[dn][2] *= facB; acc_o[dn][3] *= facB;
            }
        }
        lA += sumA;
        lB += sumB;
        mA = mAn; mB = mBn;

#pragma unroll
        for (int kt = 0; kt < 4; kt++) {
            uint32_t Ph[4];
            Ph[0] = pack_f16x2(s[2 * kt][0], s[2 * kt][1]);
            Ph[1] = pack_f16x2(s[2 * kt][2], s[2 * kt][3]);
            Ph[2] = pack_f16x2(s[2 * kt + 1][0], s[2 * kt + 1][1]);
            Ph[3] = pack_f16x2(s[2 * kt + 1][2], s[2 * kt + 1][3]);
#pragma unroll
            for (int dp = 0; dp < 4; dp++) {
                uint32_t off = ((kt * 16 + ((lane >> 3) & 1) * 8 + (lane & 7)) * 72
                                + dp * 16 + (lane >> 4) * 8) * 2;
                uint32_t vh[4];
                ldsm_x4t(vh, aV + off);
                mma_f16(acc_o[2 * dp],     Ph, vh);
                mma_f16(acc_o[2 * dp + 1], Ph, vh + 2);
            }
        }
        __syncthreads();
    }

    float invA = 1.0f / lA, invB = 1.0f / lB;
    float xs = xsa[0];
    int rowA = tok0 + q0 + wid * 16 + (lane >> 2);
    int rowB = rowA + 8;
    float dotA = 0.f, vnA = 0.f, dotB = 0.f, vnB = 0.f;
#pragma unroll
    for (int dn = 0; dn < 8; dn++) {
        int col = hoff + dn * 8 + (lane & 3) * 2;
        float2 va = *(const float2*)&Vf[(size_t)rowA * D_MODEL + col];
        float2 vb = *(const float2*)&Vf[(size_t)rowB * D_MODEL + col];
        float o0 = acc_o[dn][0] * invA, o1 = acc_o[dn][1] * invA;
        float o2 = acc_o[dn][2] * invB, o3 = acc_o[dn][3] * invB;
        acc_o[dn][0] = o0; acc_o[dn][1] = o1;
        acc_o[dn][2] = o2; acc_o[dn][3] = o3;
        dotA += o0 * va.x + o1 * va.y;
        vnA  += va.x * va.x + va.y * va.y;
        dotB += o2 * vb.x + o3 * vb.y;
        vnB  += vb.x * vb.x + vb.y * vb.y;
    }
    dotA += __shfl_xor_sync(0xffffffffu, dotA, 1);
    dotA += __shfl_xor_sync(0xffffffffu, dotA, 2);
    vnA  += __shfl_xor_sync(0xffffffffu, vnA, 1);
    vnA  += __shfl_xor_sync(0xffffffffu, vnA, 2);
    dotB += __shfl_xor_sync(0xffffffffu, dotB, 1);
    dotB += __shfl_xor_sync(0xffffffffu, dotB, 2);
    vnB  += __shfl_xor_sync(0xffffffffu, vnB, 1);
    vnB  += __shfl_xor_sync(0xffffffffu, vnB, 2);
    float scA = xs * dotA / (vnA + 1e-8f);
    float scB = xs * dotB / (vnB + 1e-8f);
#pragma unroll
    for (int dn = 0; dn < 8; dn++) {
        int col = hoff + dn * 8 + (lane & 3) * 2;
        float2 va = *(const float2*)&Vf[(size_t)rowA * D_MODEL + col];
        float2 vb = *(const float2*)&Vf[(size_t)rowB * D_MODEL + col];
        uint32_t pa = pack_f16x2(acc_o[dn][0] - scA * va.x,
                                 acc_o[dn][1] - scA * va.y);
        uint32_t pb = pack_f16x2(acc_o[dn][2] - scB * vb.x,
                                 acc_o[dn][3] - scB * vb.y);
        *(uint32_t*)&Oh[(size_t)rowA * D_MODEL + col] = pa;
        *(uint32_t*)&Oh[(size_t)rowB * D_MODEL + col] = pb;
    }
}

// ---------------------------------------------------------------------------
// Launch
// ---------------------------------------------------------------------------
extern "C" void kernel_launch(void* const* d_in, const int* in_sizes, int n_in,
                              void* d_out, int out_size) {
    const float* x   = (const float*)d_in[0];
    const float* Wq  = (const float*)d_in[1];
    const float* Wk  = (const float*)d_in[2];
    const float* Wv  = (const float*)d_in[3];
    const float* Wo  = (const float*)d_in[4];
    const float* xsa = (const float*)d_in[5];

    const int M = in_sizes[0] / D_MODEL;   // 4096
    const int B = 2;
    const int S = M / B;                   // 2048

    float* v;
    cudaGetSymbolAddress((void**)&v, g_v);

    __half *xh, *qh, *kh, *vh, *oh;
    __half *wqh, *wkh, *wvh, *woh;
    cudaGetSymbolAddress((void**)&xh, g_xh);
    cudaGetSymbolAddress((void**)&qh, g_qh);
    cudaGetSymbolAddress((void**)&kh, g_kh);
    cudaGetSymbolAddress((void**)&vh, g_vh);
    cudaGetSymbolAddress((void**)&oh, g_oh);
    cudaGetSymbolAddress((void**)&wqh, g_wqh);
    cudaGetSymbolAddress((void**)&wkh, g_wkh);
    cudaGetSymbolAddress((void**)&wvh, g_wvh);
    cudaGetSymbolAddress((void**)&woh, g_woh);

    convert_all<<<8192, 256>>>(x, Wq, Wk, Wv, Wo, xh, wqh, wkh, wvh, woh);

    dim3 gqkv(24, M / 64);   // Q, K, V projections in one launch (1536 CTAs)
    gemm_qkv<<<gqkv, 128>>>(xh, wqh, wkh, wvh, qh, kh, vh, v, M, D_MODEL, D_MODEL);

    dim3 gattn(S / 64, NUM_HEADS, B);
    attn_mma<<<gattn, 128>>>(qh, kh, vh, v, xsa, oh, S);

    dim3 gout(D_MODEL / 128, M / 64);
    gemm_out<<<gout, 128>>>(oh, woh, (float*)d_out, M, D_MODEL, D_MODEL);
}

// round 17
// speedup vs baseline: 2.6089x; 1.0775x over previous
#include <cuda_runtime.h>
#include <cuda_fp16.h>
#include <math.h>
#include <stdint.h>

#define D_MODEL   1024
#define NUM_HEADS 16
#define HEAD_DIM  64
#define NTOK      4096
// (1/sqrt(64)) * log2(e)
#define C_SCALE   0.18033688011112042f

// ---------------- static scratch (allocation-free rule) ----------------
__device__ __half g_xh[NTOK * D_MODEL];
__device__ __half g_qh[NTOK * D_MODEL];
__device__ __half g_kh[NTOK * D_MODEL];
__device__ __half g_vh[NTOK * D_MODEL];
__device__ __half g_oh[NTOK * D_MODEL];
__device__ __half g_wqh[D_MODEL * D_MODEL];
__device__ __half g_wkh[D_MODEL * D_MODEL];
__device__ __half g_wvh[D_MODEL * D_MODEL];
__device__ __half g_woh[D_MODEL * D_MODEL];

// ---------------- helpers ----------------
__device__ __forceinline__ uint32_t smem_u32(const void* p) {
    uint32_t a;
    asm("{ .reg .u64 t; cvta.to.shared.u64 t, %1; cvt.u32.u64 %0, t; }"
        : "=r"(a) : "l"(p));
    return a;
}

__device__ __forceinline__ void ldsm_x4(uint32_t* r, uint32_t addr) {
    asm volatile("ldmatrix.sync.aligned.m8n8.x4.shared.b16 {%0,%1,%2,%3}, [%4];"
                 : "=r"(r[0]), "=r"(r[1]), "=r"(r[2]), "=r"(r[3]) : "r"(addr));
}
__device__ __forceinline__ void ldsm_x4t(uint32_t* r, uint32_t addr) {
    asm volatile("ldmatrix.sync.aligned.m8n8.x4.trans.shared.b16 {%0,%1,%2,%3}, [%4];"
                 : "=r"(r[0]), "=r"(r[1]), "=r"(r[2]), "=r"(r[3]) : "r"(addr));
}
__device__ __forceinline__ void mma_f16(float* d, const uint32_t* a, const uint32_t* b) {
    asm volatile(
        "mma.sync.aligned.m16n8k16.row.col.f32.f16.f16.f32 "
        "{%0,%1,%2,%3}, {%4,%5,%6,%7}, {%8,%9}, {%0,%1,%2,%3};"
        : "+f"(d[0]), "+f"(d[1]), "+f"(d[2]), "+f"(d[3])
        : "r"(a[0]), "r"(a[1]), "r"(a[2]), "r"(a[3]), "r"(b[0]), "r"(b[1]));
}

#define CP_ASYNC16(dst, src) \
    asm volatile("cp.async.cg.shared.global [%0], [%1], 16;" :: "r"(dst), "l"(src))
#define CP_COMMIT asm volatile("cp.async.commit_group;" ::: "memory")
template <int N>
__device__ __forceinline__ void cp_wait() {
    asm volatile("cp.async.wait_group %0;" :: "n"(N) : "memory");
}

__device__ __forceinline__ uint32_t pack_f16x2(float lo, float hi) {
    __half2 t = __floats2half2_rn(lo, hi);   // .x = lo (low 16 bits)
    return *(uint32_t*)&t;
}

// fast 2^t (fma/alu pipes only): magic-constant rounding + degree-4 poly on
// [-0.5, 0.5]; rel err < 5e-5. exp2_fast(0) == 1.0 exactly.
__device__ __forceinline__ float exp2_fast(float t) {
    t = fmaxf(t, -126.0f);
    float z = t + 12582912.0f;                 // 2^23 * 1.5: round-to-nearest
    int n = __float_as_int(z);
    float f = t - (z - 12582912.0f);           // f in [-0.5, 0.5]
    float p = fmaf(f, 0.0096181291f, 0.0555041087f);
    p = fmaf(f, p, 0.2402265070f);
    p = fmaf(f, p, 0.6931471806f);
    p = fmaf(f, p, 1.0f);
    return p * __int_as_float((n << 23) + 0x3f800000);
}

// ---------------------------------------------------------------------------
// Fused conversion kernel (all hi-only).
// ---------------------------------------------------------------------------
__global__ void convert_all(const float* __restrict__ x,
                            const float* __restrict__ Wq, const float* __restrict__ Wk,
                            const float* __restrict__ Wv, const float* __restrict__ Wo,
                            __half* __restrict__ xh, __half* __restrict__ wqh,
                            __half* __restrict__ wkh, __half* __restrict__ wvh,
                            __half* __restrict__ woh) {
    int blk = blockIdx.x;
    const float* src;
    __half* dst;
    if (blk < 4096)      { src = x;  dst = xh;  }
    else if (blk < 5120) { src = Wq; dst = wqh; blk -= 4096; }
    else if (blk < 6144) { src = Wk; dst = wkh; blk -= 5120; }
    else if (blk < 7168) { src = Wo; dst = woh; blk -= 6144; }
    else                 { src = Wv; dst = wvh; blk -= 7168; }

    int i = (blk * 256 + threadIdx.x) * 4;
    float4 v = *(const float4*)(src + i);
    __half2* hp = (__half2*)(dst + i);
    hp[0] = __floats2half2_rn(v.x, v.y);
    hp[1] = __floats2half2_rn(v.z, v.w);
}

// ---------------------------------------------------------------------------
// HMMA fp16 GEMM body (1-pass), k-chunk 64 (halved barrier count vs R16).
// 64x128 tile, 128 thr, 4 CTAs/SM. Row stride 72 halves (144 B): ldmatrix
// rows step 4 banks -> conflict-free.
// ---------------------------------------------------------------------------
#define GROWH   72
#define GA_T    (64 * GROWH * 2)     // 9216
#define GB_T    (128 * GROWH * 2)    // 18432

__device__ __forceinline__ void gemm_body(const __half* aP, const __half* bH,
                                          float* C, __half* Ch, float oscale,
                                          int m0, int n0, int N, int K,
                                          uint32_t sb) {
    const int tid = threadIdx.x;
    const int lane = tid & 31;
    const int wid = tid >> 5;

    float acc[4][4][4];
#pragma unroll
    for (int a = 0; a < 4; a++)
#pragma unroll
        for (int b = 0; b < 4; b++)
#pragma unroll
            for (int c = 0; c < 4; c++) acc[a][b][c] = 0.f;

    const int NCH = K / 64;   // 16

    for (int kc = 0; kc < NCH; kc++) {
        int koff = kc * 64;
#pragma unroll
        for (int i = 0; i < 4; i++) {
            int seg = tid + i * 128;          // 0..511
            int row = seg >> 3;               // 0..63
            int cs = seg & 7;
            size_t g = (size_t)row * K + koff + cs * 8;
            uint32_t d = (row * GROWH + cs * 8) * 2;
            CP_ASYNC16(sb + d, aP + g);
        }
#pragma unroll
        for (int i = 0; i < 8; i++) {
            int seg = tid + i * 128;          // 0..1023
            int row = seg >> 3;               // 0..127
            int cs = seg & 7;
            size_t g = (size_t)row * K + koff + cs * 8;
            uint32_t d = GA_T + (row * GROWH + cs * 8) * 2;
            CP_ASYNC16(sb + d, bH + g);
        }
        CP_COMMIT;
        cp_wait<0>();
        __syncthreads();

#pragma unroll
        for (int kk = 0; kk < 64; kk += 16) {
            uint32_t ah[4][4];
#pragma unroll
            for (int mt = 0; mt < 4; mt++) {
                uint32_t ar = sb + ((mt * 16 + (lane & 15)) * GROWH
                                    + kk + (lane >> 4) * 8) * 2;
                ldsm_x4(ah[mt], ar);
            }
#pragma unroll
            for (int npp = 0; npp < 2; npp++) {
                uint32_t br = sb + GA_T
                            + ((wid * 32 + npp * 16 + ((lane >> 4) << 3) + (lane & 7)) * GROWH
                               + kk + ((lane >> 3) & 1) * 8) * 2;
                uint32_t bh[4];
                ldsm_x4(bh, br);
#pragma unroll
                for (int mt = 0; mt < 4; mt++) {
                    mma_f16(acc[mt][2 * npp],     ah[mt], bh);
                    mma_f16(acc[mt][2 * npp + 1], ah[mt], bh + 2);
                }
            }
        }
        __syncthreads();
    }

#pragma unroll
    for (int mt = 0; mt < 4; mt++) {
#pragma unroll
        for (int nt = 0; nt < 4; nt++) {
            int r0 = m0 + mt * 16 + (lane >> 2);
            int col = n0 + wid * 32 + nt * 8 + (lane & 3) * 2;
            float d0 = acc[mt][nt][0], d1 = acc[mt][nt][1];
            float d2 = acc[mt][nt][2], d3 = acc[mt][nt][3];
            if (C) {
                float2 v0 = {d0, d1}, v1 = {d2, d3};
                *(float2*)&C[(size_t)r0 * N + col] = v0;
                *(float2*)&C[(size_t)(r0 + 8) * N + col] = v1;
            }
            if (Ch) {
                *(uint32_t*)&Ch[(size_t)r0 * N + col] =
                    pack_f16x2(d0 * oscale, d1 * oscale);
                *(uint32_t*)&Ch[(size_t)(r0 + 8) * N + col] =
                    pack_f16x2(d2 * oscale, d3 * oscale);
            }
        }
    }
}

// All three projections in one launch. blockIdx.x:
//   [0,8): Q (pre-scaled by C_SCALE), [8,16): K, [16,24): V
__global__ __launch_bounds__(128, 4)
void gemm_qkv(const __half* __restrict__ A,
              const __half* __restrict__ Bq, const __half* __restrict__ Bk,
              const __half* __restrict__ Bv,
              __half* __restrict__ Cq, __half* __restrict__ Ck,
              __half* __restrict__ Cv, int M, int N, int K) {
    __shared__ __align__(16) char smem[GA_T + GB_T];
    const int sel = blockIdx.x >> 3;
    const int nb = blockIdx.x & 7;
    const __half* Bh = (sel == 0) ? Bq : (sel == 1) ? Bk : Bv;
    __half* Ch = (sel == 0) ? Cq : (sel == 1) ? Ck : Cv;
    const float os = (sel == 0) ? C_SCALE : 1.0f;
    gemm_body(A + (size_t)blockIdx.y * 64 * K,
              Bh + (size_t)nb * 128 * K,
              nullptr, Ch, os, blockIdx.y * 64, nb * 128, N, K, smem_u32(smem));
}

// Output projection (fp32 out).
__global__ __launch_bounds__(128, 4)
void gemm_out(const __half* __restrict__ A, const __half* __restrict__ Bh,
              float* __restrict__ C, int M, int N, int K) {
    __shared__ __align__(16) char smem[GA_T + GB_T];
    gemm_body(A + (size_t)blockIdx.y * 64 * K,
              Bh + (size_t)blockIdx.x * 128 * K,
              C, nullptr, 1.0f, blockIdx.y * 64, blockIdx.x * 128, N, K,
              smem_u32(smem));
}

// ---------------------------------------------------------------------------
// HMMA flash attention. Scores pre-scaled via Q; vote-skipped rescale;
// subtract-projection fused in epilogue using fp16 v (projection is
// scale-invariant in v, direction error ~3e-5 measured in R16).
// ---------------------------------------------------------------------------
__global__ __launch_bounds__(128)
void attn_mma(const __half* __restrict__ Qh_,
              const __half* __restrict__ Kh_, const __half* __restrict__ Vh_,
              const float* __restrict__ xsa, __half* __restrict__ Oh, int S) {
    __shared__ __align__(16) uint16_t sK[64 * 72];
    __shared__ __align__(16) uint16_t sV[64 * 72];

    const int tid = threadIdx.x;
    const int lane = tid & 31;
    const int wid = tid >> 5;
    const int h = blockIdx.y;
    const int b = blockIdx.z;
    const int q0 = blockIdx.x * 64;
    const int tok0 = b * S;
    const int hoff = h * HEAD_DIM;

    const uint32_t aK = smem_u32(sK), aV = smem_u32(sV);

#pragma unroll
    for (int i = 0; i < 4; i++) {
        int seg = tid + i * 128;
        int row = seg >> 3;
        int cs = seg & 7;
        const void* sh = Qh_ + (size_t)(tok0 + q0 + row) * D_MODEL + hoff + cs * 8;
        CP_ASYNC16(aK + (row * 72 + cs * 8) * 2, sh);
    }
    CP_COMMIT;
    cp_wait<0>();
    __syncthreads();

    uint32_t qh[4][4];
#pragma unroll
    for (int kt = 0; kt < 4; kt++) {
        uint32_t off = ((wid * 16 + (lane & 15)) * 72 + kt * 16 + (lane >> 4) * 8) * 2;
        ldsm_x4(qh[kt], aK + off);
    }
    __syncthreads();

    float acc_o[8][4];
#pragma unroll
    for (int i = 0; i < 8; i++)
#pragma unroll
        for (int j = 0; j < 4; j++) acc_o[i][j] = 0.f;
    float mA = -1e30f, mB = -1e30f, lA = 0.f, lB = 0.f;

    for (int c0 = 0; c0 < S; c0 += 64) {
#pragma unroll
        for (int i = 0; i < 4; i++) {
            int seg = tid + i * 128;
            int row = seg >> 3;
            int cs = seg & 7;
            size_t g = (size_t)(tok0 + c0 + row) * D_MODEL + hoff + cs * 8;
            uint32_t d = (row * 72 + cs * 8) * 2;
            CP_ASYNC16(aK + d, Kh_ + g);
            CP_ASYNC16(aV + d, Vh_ + g);
        }
        CP_COMMIT;
        cp_wait<0>();
        __syncthreads();

        float s[8][4];
#pragma unroll
        for (int i = 0; i < 8; i++)
#pragma unroll
            for (int j = 0; j < 4; j++) s[i][j] = 0.f;

#pragma unroll
        for (int kt = 0; kt < 4; kt++) {
#pragma unroll
            for (int np = 0; np < 4; np++) {
                uint32_t off = ((np * 16 + ((lane >> 4) << 3) + (lane & 7)) * 72
                                + kt * 16 + ((lane >> 3) & 1) * 8) * 2;
                uint32_t bh[4];
                ldsm_x4(bh, aK + off);
                mma_f16(s[2 * np],     qh[kt], bh);
                mma_f16(s[2 * np + 1], qh[kt], bh + 2);
            }
        }

        float mxA = -1e30f, mxB = -1e30f;
#pragma unroll
        for (int nt = 0; nt < 8; nt++) {
            mxA = fmaxf(mxA, fmaxf(s[nt][0], s[nt][1]));
            mxB = fmaxf(mxB, fmaxf(s[nt][2], s[nt][3]));
        }
        mxA = fmaxf(mxA, __shfl_xor_sync(0xffffffffu, mxA, 1));
        mxA = fmaxf(mxA, __shfl_xor_sync(0xffffffffu, mxA, 2));
        mxB = fmaxf(mxB, __shfl_xor_sync(0xffffffffu, mxB, 1));
        mxB = fmaxf(mxB, __shfl_xor_sync(0xffffffffu, mxB, 2));
        float mAn = fmaxf(mA, mxA);
        float mBn = fmaxf(mB, mxB);

        float sumA = 0.f, sumB = 0.f;
#pragma unroll
        for (int nt = 0; nt < 8; nt++) {
            s[nt][0] = exp2_fast(s[nt][0] - mAn);
            s[nt][1] = exp2_fast(s[nt][1] - mAn);
            s[nt][2] = exp2_fast(s[nt][2] - mBn);
            s[nt][3] = exp2_fast(s[nt][3] - mBn);
            sumA += s[nt][0] + s[nt][1];
            sumB += s[nt][2] + s[nt][3];
        }
        sumA += __shfl_xor_sync(0xffffffffu, sumA, 1);
        sumA += __shfl_xor_sync(0xffffffffu, sumA, 2);
        sumB += __shfl_xor_sync(0xffffffffu, sumB, 1);
        sumB += __shfl_xor_sync(0xffffffffu, sumB, 2);

        if (!__all_sync(0xffffffffu, (mAn == mA) && (mBn == mB))) {
            float facA = exp2_fast(mA - mAn);
            float facB = exp2_fast(mB - mBn);
            lA *= facA;
            lB *= facB;
#pragma unroll
            for (int dn = 0; dn < 8; dn++) {
                acc_o[dn][0] *= facA; acc_o[dn][1] *= facA;
                acc_o[dn][2] *= facB; acc_o[dn][3] *= facB;
            }
        }
        lA += sumA;
        lB += sumB;
        mA = mAn; mB = mBn;

#pragma unroll
        for (int kt = 0; kt < 4; kt++) {
            uint32_t Ph[4];
            Ph[0] = pack_f16x2(s[2 * kt][0], s[2 * kt][1]);
            Ph[1] = pack_f16x2(s[2 * kt][2], s[2 * kt][3]);
            Ph[2] = pack_f16x2(s[2 * kt + 1][0], s[2 * kt + 1][1]);
            Ph[3] = pack_f16x2(s[2 * kt + 1][2], s[2 * kt + 1][3]);
#pragma unroll
            for (int dp = 0; dp < 4; dp++) {
                uint32_t off = ((kt * 16 + ((lane >> 3) & 1) * 8 + (lane & 7)) * 72
                                + dp * 16 + (lane >> 4) * 8) * 2;
                uint32_t vh[4];
                ldsm_x4t(vh, aV + off);
                mma_f16(acc_o[2 * dp],     Ph, vh);
                mma_f16(acc_o[2 * dp + 1], Ph, vh + 2);
            }
        }
        __syncthreads();
    }

    // ---- epilogue: normalize + fused subtract-projection (fp16 v) ----
    float invA = 1.0f / lA, invB = 1.0f / lB;
    float xs = xsa[0];
    int rowA = tok0 + q0 + wid * 16 + (lane >> 2);
    int rowB = rowA + 8;
    float dotA = 0.f, vnA = 0.f, dotB = 0.f, vnB = 0.f;
    float2 vaf[8], vbf[8];
#pragma unroll
    for (int dn = 0; dn < 8; dn++) {
        int col = hoff + dn * 8 + (lane & 3) * 2;
        __half2 va2 = *(const __half2*)&Vh_[(size_t)rowA * D_MODEL + col];
        __half2 vb2 = *(const __half2*)&Vh_[(size_t)rowB * D_MODEL + col];
        float2 va = __half22float2(va2);
        float2 vb = __half22float2(vb2);
        vaf[dn] = va; vbf[dn] = vb;
        float o0 = acc_o[dn][0] * invA, o1 = acc_o[dn][1] * invA;
        float o2 = acc_o[dn][2] * invB, o3 = acc_o[dn][3] * invB;
        acc_o[dn][0] = o0; acc_o[dn][1] = o1;
        acc_o[dn][2] = o2; acc_o[dn][3] = o3;
        dotA += o0 * va.x + o1 * va.y;
        vnA  += va.x * va.x + va.y * va.y;
        dotB += o2 * vb.x + o3 * vb.y;
        vnB  += vb.x * vb.x + vb.y * vb.y;
    }
    dotA += __shfl_xor_sync(0xffffffffu, dotA, 1);
    dotA += __shfl_xor_sync(0xffffffffu, dotA, 2);
    vnA  += __shfl_xor_sync(0xffffffffu, vnA, 1);
    vnA  += __shfl_xor_sync(0xffffffffu, vnA, 2);
    dotB += __shfl_xor_sync(0xffffffffu, dotB, 1);
    dotB += __shfl_xor_sync(0xffffffffu, dotB, 2);
    vnB  += __shfl_xor_sync(0xffffffffu, vnB, 1);
    vnB  += __shfl_xor_sync(0xffffffffu, vnB, 2);
    float scA = xs * dotA / (vnA + 1e-8f);
    float scB = xs * dotB / (vnB + 1e-8f);
#pragma unroll
    for (int dn = 0; dn < 8; dn++) {
        int col = hoff + dn * 8 + (lane & 3) * 2;
        uint32_t pa = pack_f16x2(acc_o[dn][0] - scA * vaf[dn].x,
                                 acc_o[dn][1] - scA * vaf[dn].y);
        uint32_t pb = pack_f16x2(acc_o[dn][2] - scB * vbf[dn].x,
                                 acc_o[dn][3] - scB * vbf[dn].y);
        *(uint32_t*)&Oh[(size_t)rowA * D_MODEL + col] = pa;
        *(uint32_t*)&Oh[(size_t)rowB * D_MODEL + col] = pb;
    }
}

// ---------------------------------------------------------------------------
// Launch
// ---------------------------------------------------------------------------
extern "C" void kernel_launch(void* const* d_in, const int* in_sizes, int n_in,
                              void* d_out, int out_size) {
    const float* x   = (const float*)d_in[0];
    const float* Wq  = (const float*)d_in[1];
    const float* Wk  = (const float*)d_in[2];
    const float* Wv  = (const float*)d_in[3];
    const float* Wo  = (const float*)d_in[4];
    const float* xsa = (const float*)d_in[5];

    const int M = in_sizes[0] / D_MODEL;   // 4096
    const int B = 2;
    const int S = M / B;                   // 2048

    __half *xh, *qh, *kh, *vh, *oh;
    __half *wqh, *wkh, *wvh, *woh;
    cudaGetSymbolAddress((void**)&xh, g_xh);
    cudaGetSymbolAddress((void**)&qh, g_qh);
    cudaGetSymbolAddress((void**)&kh, g_kh);
    cudaGetSymbolAddress((void**)&vh, g_vh);
    cudaGetSymbolAddress((void**)&oh, g_oh);
    cudaGetSymbolAddress((void**)&wqh, g_wqh);
    cudaGetSymbolAddress((void**)&wkh, g_wkh);
    cudaGetSymbolAddress((void**)&wvh, g_wvh);
    cudaGetSymbolAddress((void**)&woh, g_woh);

    convert_all<<<8192, 256>>>(x, Wq, Wk, Wv, Wo, xh, wqh, wkh, wvh, woh);

    dim3 gqkv(24, M / 64);
    gemm_qkv<<<gqkv, 128>>>(xh, wqh, wkh, wvh, qh, kh, vh, M, D_MODEL, D_MODEL);

    dim3 gattn(S / 64, NUM_HEADS, B);
    attn_mma<<<gattn, 128>>>(qh, kh, vh, xsa, oh, S);

    dim3 gout(D_MODEL / 128, M / 64);
    gemm_out<<<gout, 128>>>(oh, woh, (float*)d_out, M, D_MODEL, D_MODEL);
}